// round 2
// baseline (speedup 1.0000x reference)
#include <cuda_runtime.h>
#include <math.h>

// Problem constants
#define BATCH 64
#define SEQ   512
#define DIN   128
#define HID   512
#define OUTN  24
#define K0    (DIN + HID)    // 640
#define K1    (2 * HID)      // 1024
#define COLS  (4 * HID)      // 2048 gate-major columns per layer

#define NCTA  128
#define NT    256
#define KT    64             // k-chunk per smem tile

// ---------------- persistent device state (no cudaMalloc allowed) ----------
__device__ float d_W0r[K0 * COLS];   // [k][unit*4+gate]
__device__ float d_W1r[K1 * COLS];
__device__ float d_b0r[COLS];
__device__ float d_b1r[COLS];
__device__ float d_h0[2][BATCH * HID];
__device__ float d_h1[2][BATCH * HID];
__device__ unsigned g_bar_count = 0;
__device__ unsigned g_bar_gen   = 0;

// ---------------- weight rearrangement ------------------------------------
__global__ void prep_kernel(
    const float* __restrict__ wf0, const float* __restrict__ wi0,
    const float* __restrict__ wo0, const float* __restrict__ wg0,
    const float* __restrict__ bf0, const float* __restrict__ bi0,
    const float* __restrict__ bo0, const float* __restrict__ bg0,
    const float* __restrict__ wf1, const float* __restrict__ wi1,
    const float* __restrict__ wo1, const float* __restrict__ wg1,
    const float* __restrict__ bf1, const float* __restrict__ bi1,
    const float* __restrict__ bo1, const float* __restrict__ bg1)
{
    const int n0 = K0 * COLS;
    const int n1 = K1 * COLS;
    const int ntot = n0 + n1 + 2 * COLS;
    for (int idx = blockIdx.x * blockDim.x + threadIdx.x; idx < ntot;
         idx += gridDim.x * blockDim.x) {
        if (idx < n0) {
            int k = idx / COLS, col = idx % COLS;
            int u = col >> 2, g = col & 3;
            const float* w = (g == 0) ? wf0 : (g == 1) ? wi0 : (g == 2) ? wo0 : wg0;
            d_W0r[idx] = w[u * K0 + k];
        } else if (idx < n0 + n1) {
            int j = idx - n0;
            int k = j / COLS, col = j % COLS;
            int u = col >> 2, g = col & 3;
            const float* w = (g == 0) ? wf1 : (g == 1) ? wi1 : (g == 2) ? wo1 : wg1;
            d_W1r[j] = w[u * K1 + k];
        } else if (idx < n0 + n1 + COLS) {
            int col = idx - n0 - n1;
            int u = col >> 2, g = col & 3;
            const float* bb = (g == 0) ? bf0 : (g == 1) ? bi0 : (g == 2) ? bo0 : bg0;
            d_b0r[col] = bb[u];
        } else {
            int col = idx - n0 - n1 - COLS;
            int u = col >> 2, g = col & 3;
            const float* bb = (g == 0) ? bf1 : (g == 1) ? bi1 : (g == 2) ? bo1 : bg1;
            d_b1r[col] = bb[u];
        }
    }
}

// ---------------- grid barrier (all NCTA blocks resident) ------------------
__device__ __forceinline__ void grid_barrier()
{
    __syncthreads();
    if (threadIdx.x == 0) {
        volatile unsigned* genp = &g_bar_gen;
        unsigned gen = *genp;
        __threadfence();                       // release my writes
        unsigned prev = atomicAdd(&g_bar_count, 1u);
        if (prev == NCTA - 1) {
            atomicExch(&g_bar_count, 0u);
            __threadfence();
            atomicAdd(&g_bar_gen, 1u);
        } else {
            while (*genp == gen) { __nanosleep(64); }
            __threadfence();                   // acquire others' writes
        }
    }
    __syncthreads();
}

__device__ __forceinline__ float sigf(float v) { return 1.0f / (1.0f + expf(-v)); }

// ---------------- persistent scan kernel -----------------------------------
__global__ void __launch_bounds__(NT) scan_kernel(const float* __restrict__ x)
{
    __shared__ float As[BATCH][KT + 4];    // activations tile (stride 68)
    __shared__ float Bs[16][KT + 4];       // weights tile, Bs[col][k]
    __shared__ float pw[BATCH][17];        // preactivation exchange
    __shared__ float cst[2][4][BATCH];     // cell state per layer/unitLocal/batch

    const int tid   = threadIdx.x;
    const int cta   = blockIdx.x;
    const int tx    = tid & 15;            // local output column 0..15
    const int ty    = tid >> 4;            // batch group 0..15
    const int bbase = ty << 2;             // 4 batches per thread
    const int lane5 = tid & 31;
    const int wgrp  = tid >> 5;
    const int colbase = cta * 16;          // this CTA's 16 columns (4 units x 4 gates)

    // ---- init (every launch): zero "t = -1" hidden buffers and cell state
    {
        int gt = cta * NT + tid;           // exactly covers BATCH*HID = 32768
        d_h0[1][gt] = 0.0f;
        d_h1[1][gt] = 0.0f;
        ((float*)cst)[tid]       = 0.0f;
        ((float*)cst)[tid + NT]  = 0.0f;
    }
    grid_barrier();

    for (int k = 0; k <= SEQ; ++k) {
        // ======== layer 0: compute step t = k =========
        if (k < SEQ) {
            const int t = k;
            const float* __restrict__ h0prev = d_h0[(k + 1) & 1];
            float acc0 = 0.f, acc1 = 0.f, acc2 = 0.f, acc3 = 0.f;
            #pragma unroll 1
            for (int kc = 0; kc < K0 / KT; ++kc) {
                const int kb = kc * KT;
                // load A tile: rows=batches, cols=k slice of [x_t, h0prev]
                #pragma unroll
                for (int r = 0; r < 8; ++r) {
                    int row = wgrp * 8 + r;
                    int kg0 = kb + lane5;
                    int kg1 = kg0 + 32;
                    As[row][lane5] = (kg0 < DIN)
                        ? x[row * (SEQ * DIN) + t * DIN + kg0]
                        : h0prev[row * HID + (kg0 - DIN)];
                    As[row][lane5 + 32] = (kg1 < DIN)
                        ? x[row * (SEQ * DIN) + t * DIN + kg1]
                        : h0prev[row * HID + (kg1 - DIN)];
                }
                // load B tile
                #pragma unroll
                for (int e = tid; e < 16 * KT; e += NT) {
                    int kk = e >> 4, col = e & 15;
                    Bs[col][kk] = d_W0r[(kb + kk) * COLS + colbase + col];
                }
                __syncthreads();
                #pragma unroll
                for (int kk = 0; kk < KT; kk += 4) {
                    float4 bv = *(const float4*)(&Bs[tx][kk]);
                    float4 a0 = *(const float4*)(&As[bbase + 0][kk]);
                    float4 a1 = *(const float4*)(&As[bbase + 1][kk]);
                    float4 a2 = *(const float4*)(&As[bbase + 2][kk]);
                    float4 a3 = *(const float4*)(&As[bbase + 3][kk]);
                    acc0 = fmaf(a0.x, bv.x, fmaf(a0.y, bv.y, fmaf(a0.z, bv.z, fmaf(a0.w, bv.w, acc0))));
                    acc1 = fmaf(a1.x, bv.x, fmaf(a1.y, bv.y, fmaf(a1.z, bv.z, fmaf(a1.w, bv.w, acc1))));
                    acc2 = fmaf(a2.x, bv.x, fmaf(a2.y, bv.y, fmaf(a2.z, bv.z, fmaf(a2.w, bv.w, acc2))));
                    acc3 = fmaf(a3.x, bv.x, fmaf(a3.y, bv.y, fmaf(a3.z, bv.z, fmaf(a3.w, bv.w, acc3))));
                }
                __syncthreads();
            }
            float bias = d_b0r[colbase + tx];
            pw[bbase + 0][tx] = acc0 + bias;
            pw[bbase + 1][tx] = acc1 + bias;
            pw[bbase + 2][tx] = acc2 + bias;
            pw[bbase + 3][tx] = acc3 + bias;
            __syncthreads();
            {
                int uL = tid & 3, b = tid >> 2;
                float fg = sigf(pw[b][uL * 4 + 0]);
                float ig = sigf(pw[b][uL * 4 + 1]);
                float og = sigf(pw[b][uL * 4 + 2]);
                float gg = tanhf(pw[b][uL * 4 + 3]);
                float c = fg * cst[0][uL][b] + ig * gg;
                cst[0][uL][b] = c;
                d_h0[k & 1][b * HID + cta * 4 + uL] = og * tanhf(c);
            }
            __syncthreads();
        }

        // ======== layer 1: compute step t = k-1 =========
        if (k >= 1) {
            const float* __restrict__ h0cur  = d_h0[(k - 1) & 1];  // h0 at t=k-1
            const float* __restrict__ h1prev = d_h1[k & 1];        // h1 at t=k-2
            float acc0 = 0.f, acc1 = 0.f, acc2 = 0.f, acc3 = 0.f;
            #pragma unroll 1
            for (int kc = 0; kc < K1 / KT; ++kc) {
                const int kb = kc * KT;
                #pragma unroll
                for (int r = 0; r < 8; ++r) {
                    int row = wgrp * 8 + r;
                    int kg0 = kb + lane5;
                    int kg1 = kg0 + 32;
                    As[row][lane5] = (kg0 < HID)
                        ? h0cur[row * HID + kg0]
                        : h1prev[row * HID + (kg0 - HID)];
                    As[row][lane5 + 32] = (kg1 < HID)
                        ? h0cur[row * HID + kg1]
                        : h1prev[row * HID + (kg1 - HID)];
                }
                #pragma unroll
                for (int e = tid; e < 16 * KT; e += NT) {
                    int kk = e >> 4, col = e & 15;
                    Bs[col][kk] = d_W1r[(kb + kk) * COLS + colbase + col];
                }
                __syncthreads();
                #pragma unroll
                for (int kk = 0; kk < KT; kk += 4) {
                    float4 bv = *(const float4*)(&Bs[tx][kk]);
                    float4 a0 = *(const float4*)(&As[bbase + 0][kk]);
                    float4 a1 = *(const float4*)(&As[bbase + 1][kk]);
                    float4 a2 = *(const float4*)(&As[bbase + 2][kk]);
                    float4 a3 = *(const float4*)(&As[bbase + 3][kk]);
                    acc0 = fmaf(a0.x, bv.x, fmaf(a0.y, bv.y, fmaf(a0.z, bv.z, fmaf(a0.w, bv.w, acc0))));
                    acc1 = fmaf(a1.x, bv.x, fmaf(a1.y, bv.y, fmaf(a1.z, bv.z, fmaf(a1.w, bv.w, acc1))));
                    acc2 = fmaf(a2.x, bv.x, fmaf(a2.y, bv.y, fmaf(a2.z, bv.z, fmaf(a2.w, bv.w, acc2))));
                    acc3 = fmaf(a3.x, bv.x, fmaf(a3.y, bv.y, fmaf(a3.z, bv.z, fmaf(a3.w, bv.w, acc3))));
                }
                __syncthreads();
            }
            float bias = d_b1r[colbase + tx];
            pw[bbase + 0][tx] = acc0 + bias;
            pw[bbase + 1][tx] = acc1 + bias;
            pw[bbase + 2][tx] = acc2 + bias;
            pw[bbase + 3][tx] = acc3 + bias;
            __syncthreads();
            {
                int uL = tid & 3, b = tid >> 2;
                float fg = sigf(pw[b][uL * 4 + 0]);
                float ig = sigf(pw[b][uL * 4 + 1]);
                float og = sigf(pw[b][uL * 4 + 2]);
                float gg = tanhf(pw[b][uL * 4 + 3]);
                float c = fg * cst[1][uL][b] + ig * gg;
                cst[1][uL][b] = c;
                d_h1[(k - 1) & 1][b * HID + cta * 4 + uL] = og * tanhf(c);
            }
            __syncthreads();
        }

        grid_barrier();
    }
}

// ---------------- final FC head ---------------------------------------------
__global__ void fc_kernel(const float* __restrict__ fc1w, const float* __restrict__ fc1b,
                          const float* __restrict__ fc2w, const float* __restrict__ fc2b,
                          float* __restrict__ out)
{
    __shared__ float hs[HID];
    __shared__ float y1[HID];
    const int b = blockIdx.x;
    const int tid = threadIdx.x;
    // final h1 (t = SEQ-1 = 511) lives in slot (SEQ-1)&1 = 1
    const float* __restrict__ h = d_h1[1] + b * HID;
    for (int i = tid; i < HID; i += blockDim.x) hs[i] = h[i];
    __syncthreads();
    for (int j = tid; j < HID; j += blockDim.x) {
        float a = fc1b[j];
        const float* __restrict__ w = fc1w + j * HID;
        #pragma unroll 4
        for (int kk = 0; kk < HID; ++kk) a = fmaf(w[kk], hs[kk], a);
        y1[j] = a;
    }
    __syncthreads();
    if (tid < OUTN) {
        float a = fc2b[tid];
        const float* __restrict__ w = fc2w + tid * HID;
        #pragma unroll 4
        for (int kk = 0; kk < HID; ++kk) a = fmaf(w[kk], y1[kk], a);
        out[b * OUTN + tid] = fmaxf(a, 0.0f);
    }
}

// ---------------- launch ------------------------------------------------------
extern "C" void kernel_launch(void* const* d_in, const int* in_sizes, int n_in,
                              void* d_out, int out_size)
{
    const float* x    = (const float*)d_in[0];
    const float* wf0  = (const float*)d_in[1];
    const float* bf0  = (const float*)d_in[2];
    const float* wi0  = (const float*)d_in[3];
    const float* bi0  = (const float*)d_in[4];
    const float* wo0  = (const float*)d_in[5];
    const float* bo0  = (const float*)d_in[6];
    const float* wg0  = (const float*)d_in[7];
    const float* bg0  = (const float*)d_in[8];
    const float* wf1  = (const float*)d_in[9];
    const float* bf1  = (const float*)d_in[10];
    const float* wi1  = (const float*)d_in[11];
    const float* bi1  = (const float*)d_in[12];
    const float* wo1  = (const float*)d_in[13];
    const float* bo1  = (const float*)d_in[14];
    const float* wg1  = (const float*)d_in[15];
    const float* bg1  = (const float*)d_in[16];
    const float* fc1w = (const float*)d_in[17];
    const float* fc1b = (const float*)d_in[18];
    const float* fc2w = (const float*)d_in[19];
    const float* fc2b = (const float*)d_in[20];
    float* out = (float*)d_out;

    prep_kernel<<<4096, 256>>>(wf0, wi0, wo0, wg0, bf0, bi0, bo0, bg0,
                               wf1, wi1, wo1, wg1, bf1, bi1, bo1, bg1);
    scan_kernel<<<NCTA, NT>>>(x);
    fc_kernel<<<BATCH, 256>>>(fc1w, fc1b, fc2w, fc2b, out);
}

// round 3
// speedup vs baseline: 3.5866x; 3.5866x over previous
#include <cuda_runtime.h>
#include <math.h>

#define BATCH 64
#define SEQ   512
#define DIN   128
#define HID   512
#define OUTN  24
#define K0    640
#define K1    1024
#define COLS  2048

#define NCTA  128
#define NT    256

#define WP_L0 20480                 // 80 k8-blocks * 4 n8-blocks * 64 floats
#define WP_L1 32768                 // 128 * 4 * 64
#define WP_PER_CG (WP_L0 + WP_L1)   // 53248 floats per column-group
#define NWP (64 * WP_PER_CG)

#define AS_FLOATS 4352              // 2 halves * 32 rows * 68 stride
#define SMEM_FLOATS (WP_PER_CG + AS_FLOATS + 64)
#define SMEM_BYTES  (SMEM_FLOATS * 4)

// ---------------- persistent device state ----------------------------------
__device__ __align__(16) float d_Wp[NWP];          // tf32-rounded, fragment-packed
__device__ float d_b0r[COLS];
__device__ float d_b1r[COLS];
__device__ __align__(16) float d_h0[2][BATCH * HID];
__device__ __align__(16) float d_h1[2][BATCH * HID];
__device__ unsigned g_bar_count = 0;
__device__ unsigned g_bar_gen   = 0;

__device__ __forceinline__ float tf32r(float v) {
    float r; asm("cvt.rna.tf32.f32 %0, %1;" : "=f"(r) : "f"(v)); return r;
}
__device__ __forceinline__ void cvt4(float4& v) {
    v.x = tf32r(v.x); v.y = tf32r(v.y); v.z = tf32r(v.z); v.w = tf32r(v.w);
}
__device__ __forceinline__ float sigf(float v) { return 1.0f / (1.0f + expf(-v)); }

__device__ __forceinline__ void mma8(float c[4], unsigned a0, unsigned a1,
                                     unsigned a2, unsigned a3,
                                     unsigned b0, unsigned b1)
{
    asm volatile(
        "mma.sync.aligned.m16n8k8.row.col.f32.tf32.tf32.f32 "
        "{%0,%1,%2,%3},{%4,%5,%6,%7},{%8,%9},{%0,%1,%2,%3};"
        : "+f"(c[0]), "+f"(c[1]), "+f"(c[2]), "+f"(c[3])
        : "r"(a0), "r"(a1), "r"(a2), "r"(a3), "r"(b0), "r"(b1));
}

// ---------------- weight rearrangement + tf32 rounding ----------------------
__global__ void prep_kernel(
    const float* __restrict__ wf0, const float* __restrict__ wi0,
    const float* __restrict__ wo0, const float* __restrict__ wg0,
    const float* __restrict__ bf0, const float* __restrict__ bi0,
    const float* __restrict__ bo0, const float* __restrict__ bg0,
    const float* __restrict__ wf1, const float* __restrict__ wi1,
    const float* __restrict__ wo1, const float* __restrict__ wg1,
    const float* __restrict__ bf1, const float* __restrict__ bi1,
    const float* __restrict__ bo1, const float* __restrict__ bg1)
{
    const int ntot = NWP + 2 * COLS;
    for (int idx = blockIdx.x * blockDim.x + threadIdx.x; idx < ntot;
         idx += gridDim.x * blockDim.x) {
        if (idx < NWP) {
            int cg = idx / WP_PER_CG;
            int r  = idx % WP_PER_CG;
            int layer = (r < WP_L0) ? 0 : 1;
            int rr    = layer ? (r - WP_L0) : r;
            int j   = rr & 1;
            int t   = (rr >> 1) & 31;
            int nbk = rr >> 6;
            int nb  = nbk & 3;
            int kb8 = nbk >> 2;
            int cloc = nb * 8 + (t >> 2);          // 0..31 local column
            int unit = cg * 8 + (cloc >> 2);
            int gate = cloc & 3;
            int kk   = kb8 * 8 + (t & 3) + j * 4;
            const float* w;
            if (layer == 0)
                w = (gate == 0) ? wf0 : (gate == 1) ? wi0 : (gate == 2) ? wo0 : wg0;
            else
                w = (gate == 0) ? wf1 : (gate == 1) ? wi1 : (gate == 2) ? wo1 : wg1;
            int K = layer ? K1 : K0;
            d_Wp[idx] = tf32r(w[unit * K + kk]);
        } else {
            int col = idx - NWP;
            if (col < COLS) {
                int u = col >> 2, g = col & 3;
                const float* bb = (g == 0) ? bf0 : (g == 1) ? bi0 : (g == 2) ? bo0 : bg0;
                d_b0r[col] = bb[u];
            } else {
                col -= COLS;
                int u = col >> 2, g = col & 3;
                const float* bb = (g == 0) ? bf1 : (g == 1) ? bi1 : (g == 2) ? bo1 : bg1;
                d_b1r[col] = bb[u];
            }
        }
    }
}

// ---------------- grid barrier (all NCTA blocks resident) -------------------
__device__ __forceinline__ void grid_barrier()
{
    __syncthreads();
    if (threadIdx.x == 0) {
        volatile unsigned* genp = &g_bar_gen;
        unsigned gen = *genp;
        __threadfence();
        unsigned prev = atomicAdd(&g_bar_count, 1u);
        if (prev == NCTA - 1) {
            atomicExch(&g_bar_count, 0u);
            __threadfence();
            atomicAdd(&g_bar_gen, 1u);
        } else {
            while (*genp == gen) { __nanosleep(64); }
            __threadfence();
        }
    }
    __syncthreads();
}

// ---------------- per-layer reduction + pointwise ----------------------------
__device__ __forceinline__ void finish_layer(
    float acc[2][4], float* red, const float* bias, float& creg,
    float* __restrict__ hdst, int tid, int kh, int wm, int wn, int cg, int bg)
{
    int lane = tid & 31;
    int rb = wm * 16 + (lane >> 2);
    int cb = wn * 16 + 2 * (lane & 3);
    __syncthreads();                       // all mma done (As half1 free -> red)
    if (kh) {
        #pragma unroll
        for (int nn = 0; nn < 2; ++nn) {
            red[rb * 33 + cb + nn * 8]           = acc[nn][0];
            red[rb * 33 + cb + nn * 8 + 1]       = acc[nn][1];
            red[(rb + 8) * 33 + cb + nn * 8]     = acc[nn][2];
            red[(rb + 8) * 33 + cb + nn * 8 + 1] = acc[nn][3];
        }
    }
    __syncthreads();
    if (!kh) {
        #pragma unroll
        for (int nn = 0; nn < 2; ++nn) {
            red[rb * 33 + cb + nn * 8]           += acc[nn][0];
            red[rb * 33 + cb + nn * 8 + 1]       += acc[nn][1];
            red[(rb + 8) * 33 + cb + nn * 8]     += acc[nn][2];
            red[(rb + 8) * 33 + cb + nn * 8 + 1] += acc[nn][3];
        }
    }
    __syncthreads();
    int b = tid >> 3, u = tid & 7;
    float zf = red[b * 33 + u * 4 + 0] + bias[u * 4 + 0];
    float zi = red[b * 33 + u * 4 + 1] + bias[u * 4 + 1];
    float zo = red[b * 33 + u * 4 + 2] + bias[u * 4 + 2];
    float zg = red[b * 33 + u * 4 + 3] + bias[u * 4 + 3];
    float f  = sigf(zf);
    float ii = sigf(zi);
    float o  = sigf(zo);
    float g  = tanhf(zg);
    float c  = f * creg + ii * g;
    creg = c;
    hdst[(bg * 32 + b) * HID + cg * 8 + u] = o * tanhf(c);
}

// ---------------- persistent scan kernel -------------------------------------
__global__ void __launch_bounds__(NT) scan_kernel(const float* __restrict__ x)
{
    extern __shared__ float smem[];
    float* wp    = smem;                    // 53248 floats (weights, tf32)
    float* As    = smem + WP_PER_CG;        // 2 x [32][68]
    float* red   = As + 2176;               // alias over As half 1 (32x33)
    float* bias2 = As + AS_FLOATS;          // 64 floats

    const int tid  = threadIdx.x;
    const int cg   = blockIdx.x & 63;       // column group (8 units, 32 cols)
    const int bg   = blockIdx.x >> 6;       // batch group (32 batches)
    const int w    = tid >> 5, lane = tid & 31;
    const int kh   = w >> 2;                // K-split half
    const int wm   = (w >> 1) & 1;          // M block (16 rows)
    const int wn   = w & 1;                 // N block (16 cols)
    const int r4   = lane >> 2, kq4 = lane & 3;

    // staging role: 128 threads per half, each 1 row x 16 k
    const int half = tid >> 7;
    const int lt   = tid & 127;
    const int srow = lt >> 2;
    const int skq  = (lt & 3) * 16;
    const int gbs  = bg * 32 + srow;

    // one-time weight load into SMEM (fragment-packed, tf32)
    {
        const float4* src = (const float4*)(d_Wp + (size_t)cg * WP_PER_CG);
        float4* dst = (float4*)wp;
        for (int i = tid; i < WP_PER_CG / 4; i += NT) dst[i] = src[i];
        if (tid < 32) {
            bias2[tid]      = d_b0r[cg * 32 + tid];
            bias2[32 + tid] = d_b1r[cg * 32 + tid];
        }
    }
    // zero t=-1 hidden buffers (128*256 = 32768 = BATCH*HID)
    {
        int gt = blockIdx.x * NT + tid;
        d_h0[1][gt] = 0.0f;
        d_h1[1][gt] = 0.0f;
    }
    float c0 = 0.0f, c1 = 0.0f;             // cell state in registers
    grid_barrier();

    for (int k = 0; k <= SEQ; ++k) {
        // ===== layer 0, step t = k =====
        if (k < SEQ) {
            const float* __restrict__ h0prev = d_h0[(k + 1) & 1];
            float acc[2][4] = {};
            float4 pre[4];
            {   // prefetch chunk 0
                int kb = (half ? 320 : 0) + skq;
                const float* s = (kb < DIN)
                    ? x + (size_t)gbs * (SEQ * DIN) + (size_t)k * DIN + kb
                    : h0prev + gbs * HID + (kb - DIN);
                pre[0] = ((const float4*)s)[0]; pre[1] = ((const float4*)s)[1];
                pre[2] = ((const float4*)s)[2]; pre[3] = ((const float4*)s)[3];
            }
            #pragma unroll 1
            for (int i = 0; i < 5; ++i) {
                __syncthreads();            // As free
                cvt4(pre[0]); cvt4(pre[1]); cvt4(pre[2]); cvt4(pre[3]);
                float4* dst = (float4*)(As + half * 2176 + srow * 68 + skq);
                dst[0] = pre[0]; dst[1] = pre[1]; dst[2] = pre[2]; dst[3] = pre[3];
                if (i < 4) {                // prefetch next chunk (hide LDG latency)
                    int kb = (half ? 320 : 0) + (i + 1) * 64 + skq;
                    const float* s = (kb < DIN)
                        ? x + (size_t)gbs * (SEQ * DIN) + (size_t)k * DIN + kb
                        : h0prev + gbs * HID + (kb - DIN);
                    pre[0] = ((const float4*)s)[0]; pre[1] = ((const float4*)s)[1];
                    pre[2] = ((const float4*)s)[2]; pre[3] = ((const float4*)s)[3];
                }
                __syncthreads();            // As ready
                const float* ab = As + kh * 2176 + (wm * 16) * 68;
                int kb8b = (kh ? 40 : 0) + i * 8;
                #pragma unroll
                for (int k8 = 0; k8 < 8; ++k8) {
                    int ko = k8 * 8;
                    unsigned a0 = __float_as_uint(ab[ r4      * 68 + ko + kq4]);
                    unsigned a1 = __float_as_uint(ab[(r4 + 8) * 68 + ko + kq4]);
                    unsigned a2 = __float_as_uint(ab[ r4      * 68 + ko + kq4 + 4]);
                    unsigned a3 = __float_as_uint(ab[(r4 + 8) * 68 + ko + kq4 + 4]);
                    const float2* bp = (const float2*)(wp +
                        (size_t)(((kb8b + k8) * 4 + wn * 2) * 32 + lane) * 2);
                    float2 b0 = bp[0], b1 = bp[32];
                    mma8(acc[0], a0, a1, a2, a3,
                         __float_as_uint(b0.x), __float_as_uint(b0.y));
                    mma8(acc[1], a0, a1, a2, a3,
                         __float_as_uint(b1.x), __float_as_uint(b1.y));
                }
            }
            finish_layer(acc, red, bias2, c0, d_h0[k & 1], tid, kh, wm, wn, cg, bg);
        }

        // ===== layer 1, step t = k-1 =====
        if (k >= 1) {
            const float* __restrict__ h0cur  = d_h0[(k - 1) & 1];
            const float* __restrict__ h1prev = d_h1[k & 1];
            float acc[2][4] = {};
            float4 pre[4];
            {
                int kb = (half ? 512 : 0) + skq;
                const float* s = (kb < HID) ? h0cur + gbs * HID + kb
                                            : h1prev + gbs * HID + (kb - HID);
                pre[0] = ((const float4*)s)[0]; pre[1] = ((const float4*)s)[1];
                pre[2] = ((const float4*)s)[2]; pre[3] = ((const float4*)s)[3];
            }
            #pragma unroll 1
            for (int i = 0; i < 8; ++i) {
                __syncthreads();
                cvt4(pre[0]); cvt4(pre[1]); cvt4(pre[2]); cvt4(pre[3]);
                float4* dst = (float4*)(As + half * 2176 + srow * 68 + skq);
                dst[0] = pre[0]; dst[1] = pre[1]; dst[2] = pre[2]; dst[3] = pre[3];
                if (i < 7) {
                    int kb = (half ? 512 : 0) + (i + 1) * 64 + skq;
                    const float* s = (kb < HID) ? h0cur + gbs * HID + kb
                                                : h1prev + gbs * HID + (kb - HID);
                    pre[0] = ((const float4*)s)[0]; pre[1] = ((const float4*)s)[1];
                    pre[2] = ((const float4*)s)[2]; pre[3] = ((const float4*)s)[3];
                }
                __syncthreads();
                const float* ab = As + kh * 2176 + (wm * 16) * 68;
                int kb8b = (kh ? 64 : 0) + i * 8;
                #pragma unroll
                for (int k8 = 0; k8 < 8; ++k8) {
                    int ko = k8 * 8;
                    unsigned a0 = __float_as_uint(ab[ r4      * 68 + ko + kq4]);
                    unsigned a1 = __float_as_uint(ab[(r4 + 8) * 68 + ko + kq4]);
                    unsigned a2 = __float_as_uint(ab[ r4      * 68 + ko + kq4 + 4]);
                    unsigned a3 = __float_as_uint(ab[(r4 + 8) * 68 + ko + kq4 + 4]);
                    const float2* bp = (const float2*)(wp + WP_L0 +
                        (size_t)(((kb8b + k8) * 4 + wn * 2) * 32 + lane) * 2);
                    float2 b0 = bp[0], b1 = bp[32];
                    mma8(acc[0], a0, a1, a2, a3,
                         __float_as_uint(b0.x), __float_as_uint(b0.y));
                    mma8(acc[1], a0, a1, a2, a3,
                         __float_as_uint(b1.x), __float_as_uint(b1.y));
                }
            }
            finish_layer(acc, red, bias2 + 32, c1, d_h1[(k - 1) & 1],
                         tid, kh, wm, wn, cg, bg);
        }

        grid_barrier();
    }
}

// ---------------- final FC head ----------------------------------------------
__global__ void fc_kernel(const float* __restrict__ fc1w, const float* __restrict__ fc1b,
                          const float* __restrict__ fc2w, const float* __restrict__ fc2b,
                          float* __restrict__ out)
{
    __shared__ float hs[HID];
    __shared__ float y1[HID];
    const int b = blockIdx.x;
    const int tid = threadIdx.x;
    const float* __restrict__ h = d_h1[1] + b * HID;   // h1 at t=511
    for (int i = tid; i < HID; i += blockDim.x) hs[i] = h[i];
    __syncthreads();
    for (int j = tid; j < HID; j += blockDim.x) {
        float a = fc1b[j];
        const float* __restrict__ wr = fc1w + j * HID;
        #pragma unroll 4
        for (int kk = 0; kk < HID; ++kk) a = fmaf(wr[kk], hs[kk], a);
        y1[j] = a;
    }
    __syncthreads();
    if (tid < OUTN) {
        float a = fc2b[tid];
        const float* __restrict__ wr = fc2w + tid * HID;
        #pragma unroll 4
        for (int kk = 0; kk < HID; ++kk) a = fmaf(wr[kk], y1[kk], a);
        out[b * OUTN + tid] = fmaxf(a, 0.0f);
    }
}

// ---------------- launch -------------------------------------------------------
extern "C" void kernel_launch(void* const* d_in, const int* in_sizes, int n_in,
                              void* d_out, int out_size)
{
    const float* x    = (const float*)d_in[0];
    const float* wf0  = (const float*)d_in[1];
    const float* bf0  = (const float*)d_in[2];
    const float* wi0  = (const float*)d_in[3];
    const float* bi0  = (const float*)d_in[4];
    const float* wo0  = (const float*)d_in[5];
    const float* bo0  = (const float*)d_in[6];
    const float* wg0  = (const float*)d_in[7];
    const float* bg0  = (const float*)d_in[8];
    const float* wf1  = (const float*)d_in[9];
    const float* bf1  = (const float*)d_in[10];
    const float* wi1  = (const float*)d_in[11];
    const float* bi1  = (const float*)d_in[12];
    const float* wo1  = (const float*)d_in[13];
    const float* bo1  = (const float*)d_in[14];
    const float* wg1  = (const float*)d_in[15];
    const float* bg1  = (const float*)d_in[16];
    const float* fc1w = (const float*)d_in[17];
    const float* fc1b = (const float*)d_in[18];
    const float* fc2w = (const float*)d_in[19];
    const float* fc2b = (const float*)d_in[20];
    float* out = (float*)d_out;

    cudaFuncSetAttribute(scan_kernel,
                         cudaFuncAttributeMaxDynamicSharedMemorySize, SMEM_BYTES);

    prep_kernel<<<4096, 256>>>(wf0, wi0, wo0, wg0, bf0, bi0, bo0, bg0,
                               wf1, wi1, wo1, wg1, bf1, bi1, bo1, bg1);
    scan_kernel<<<NCTA, NT, SMEM_BYTES>>>(x);
    fc_kernel<<<BATCH, 256>>>(fc1w, fc1b, fc2w, fc2b, out);
}

// round 4
// speedup vs baseline: 5.0417x; 1.4057x over previous
#include <cuda_runtime.h>
#include <cuda_fp16.h>
#include <math.h>

#define BATCH 64
#define SEQ   512
#define DIN   128
#define HID   512
#define OUTN  24
#define K0    640
#define K1    1024
#define COLS  2048

#define NCTA  128
#define NT    256

// fp16 weight words (u32 = half2) per column-group
#define WPW_L0 10240               // 40 k16-blocks * 4 n8-blocks * 64 words
#define WPW_L1 16384               // 64 * 4 * 64
#define WPW    (WPW_L0 + WPW_L1)   // 26624 u32 per cg

// A staging strides (u32 words); stride % 32 == 4 -> conflict-free A LDS
#define AS0_STRIDE 324             // layer0: 320 words (640 fp16) + 4 pad
#define AS1_STRIDE 516             // layer1: 512 words (1024 fp16) + 4 pad
#define AS0_WORDS (32 * AS0_STRIDE)   // 10368
#define AS1_WORDS (32 * AS1_STRIDE)   // 16512

#define SMEM_U32  (WPW + AS0_WORDS + AS1_WORDS + 1056 + 64)
#define SMEM_BYTES (SMEM_U32 * 4)     // 218496 bytes

// ---------------- persistent device state ----------------------------------
__device__ __align__(16) unsigned d_Wp[64 * WPW];       // fp16x2 fragment-packed
__device__ __align__(16) unsigned d_x16[BATCH * SEQ * (DIN / 2)];
__device__ float d_b0r[COLS];
__device__ float d_b1r[COLS];
__device__ __align__(16) unsigned d_h0[2][BATCH * (HID / 2)];  // fp16 h state
__device__ __align__(16) unsigned d_h1[2][BATCH * (HID / 2)];
__device__ unsigned g_bar_count = 0;
__device__ unsigned g_bar_gen   = 0;

__device__ __forceinline__ float sigf(float v) { return 1.0f / (1.0f + __expf(-v)); }
__device__ __forceinline__ float tanhfast(float v) {
    // tanh(x) = 1 - 2/(e^{2x}+1)
    return 1.0f - 2.0f / (__expf(2.0f * v) + 1.0f);
}

__device__ __forceinline__ void mma16(float c[4], unsigned a0, unsigned a1,
                                      unsigned a2, unsigned a3,
                                      unsigned b0, unsigned b1)
{
    asm volatile(
        "mma.sync.aligned.m16n8k16.row.col.f32.f16.f16.f32 "
        "{%0,%1,%2,%3},{%4,%5,%6,%7},{%8,%9},{%0,%1,%2,%3};"
        : "+f"(c[0]), "+f"(c[1]), "+f"(c[2]), "+f"(c[3])
        : "r"(a0), "r"(a1), "r"(a2), "r"(a3), "r"(b0), "r"(b1));
}

// ---------------- prep: weight packing (fp16), x conversion, biases ---------
__global__ void prep_kernel(
    const float* __restrict__ x,
    const float* __restrict__ wf0, const float* __restrict__ wi0,
    const float* __restrict__ wo0, const float* __restrict__ wg0,
    const float* __restrict__ bf0, const float* __restrict__ bi0,
    const float* __restrict__ bo0, const float* __restrict__ bg0,
    const float* __restrict__ wf1, const float* __restrict__ wi1,
    const float* __restrict__ wo1, const float* __restrict__ wg1,
    const float* __restrict__ bf1, const float* __restrict__ bi1,
    const float* __restrict__ bo1, const float* __restrict__ bg1)
{
    const int nW = 64 * WPW;
    const int nX = BATCH * SEQ * (DIN / 2);
    const int ntot = nW + nX + 2 * COLS;
    for (int idx = blockIdx.x * blockDim.x + threadIdx.x; idx < ntot;
         idx += gridDim.x * blockDim.x) {
        if (idx < nW) {
            int cg = idx / WPW;
            int r  = idx % WPW;
            int layer = (r < WPW_L0) ? 0 : 1;
            int rr    = layer ? (r - WPW_L0) : r;
            int kb   = rr >> 8;          // 256 words per k16 block
            int rem  = rr & 255;
            int nb   = rem >> 6;
            int t    = rem & 63;
            int lane = t >> 1;
            int reg  = t & 1;
            int colloc = nb * 8 + (lane >> 2);
            int unit = cg * 8 + (colloc >> 2);
            int gate = colloc & 3;
            int k    = kb * 16 + (lane & 3) * 2 + reg * 8;
            const float* w;
            int K;
            if (layer == 0) {
                w = (gate == 0) ? wf0 : (gate == 1) ? wi0 : (gate == 2) ? wo0 : wg0;
                K = K0;
            } else {
                w = (gate == 0) ? wf1 : (gate == 1) ? wi1 : (gate == 2) ? wo1 : wg1;
                K = K1;
            }
            __half2 h2 = __floats2half2_rn(w[unit * K + k], w[unit * K + k + 1]);
            d_Wp[idx] = *(unsigned*)&h2;
        } else if (idx < nW + nX) {
            int i = idx - nW;
            __half2 h2 = __floats2half2_rn(x[2 * i], x[2 * i + 1]);
            d_x16[i] = *(unsigned*)&h2;
        } else {
            int col = idx - nW - nX;
            if (col < COLS) {
                int u = col >> 2, g = col & 3;
                const float* bb = (g == 0) ? bf0 : (g == 1) ? bi0 : (g == 2) ? bo0 : bg0;
                d_b0r[col] = bb[u];
            } else {
                col -= COLS;
                int u = col >> 2, g = col & 3;
                const float* bb = (g == 0) ? bf1 : (g == 1) ? bi1 : (g == 2) ? bo1 : bg1;
                d_b1r[col] = bb[u];
            }
        }
    }
}

// ---------------- grid barrier (spin, no nanosleep) --------------------------
__device__ __forceinline__ void grid_barrier()
{
    __syncthreads();
    if (threadIdx.x == 0) {
        volatile unsigned* genp = &g_bar_gen;
        unsigned gen = *genp;
        __threadfence();
        unsigned prev = atomicAdd(&g_bar_count, 1u);
        if (prev == NCTA - 1) {
            atomicExch(&g_bar_count, 0u);
            __threadfence();
            atomicAdd(&g_bar_gen, 1u);
        } else {
            while (*genp == gen) {}
            __threadfence();
        }
    }
    __syncthreads();
}

// ---------------- per-layer reduction + pointwise -----------------------------
__device__ __forceinline__ void finish_layer(
    float acc[2][4], float* red, const float* bias, float& creg,
    unsigned* __restrict__ hdst, int tid, int kh, int wm, int wn, int cg, int bg)
{
    int lane = tid & 31;
    int rb = wm * 16 + (lane >> 2);
    int cb = wn * 16 + 2 * (lane & 3);
    __syncthreads();
    if (kh) {
        #pragma unroll
        for (int nn = 0; nn < 2; ++nn) {
            red[rb * 33 + cb + nn * 8]           = acc[nn][0];
            red[rb * 33 + cb + nn * 8 + 1]       = acc[nn][1];
            red[(rb + 8) * 33 + cb + nn * 8]     = acc[nn][2];
            red[(rb + 8) * 33 + cb + nn * 8 + 1] = acc[nn][3];
        }
    }
    __syncthreads();
    if (!kh) {
        #pragma unroll
        for (int nn = 0; nn < 2; ++nn) {
            red[rb * 33 + cb + nn * 8]           += acc[nn][0];
            red[rb * 33 + cb + nn * 8 + 1]       += acc[nn][1];
            red[(rb + 8) * 33 + cb + nn * 8]     += acc[nn][2];
            red[(rb + 8) * 33 + cb + nn * 8 + 1] += acc[nn][3];
        }
    }
    __syncthreads();
    int b = tid >> 3, u = tid & 7;
    float zf = red[b * 33 + u * 4 + 0] + bias[u * 4 + 0];
    float zi = red[b * 33 + u * 4 + 1] + bias[u * 4 + 1];
    float zo = red[b * 33 + u * 4 + 2] + bias[u * 4 + 2];
    float zg = red[b * 33 + u * 4 + 3] + bias[u * 4 + 3];
    float f  = sigf(zf);
    float ii = sigf(zi);
    float o  = sigf(zo);
    float g  = tanhfast(zg);
    float c  = f * creg + ii * g;
    creg = c;
    float hv = o * tanhfast(c);
    ((__half*)hdst)[(bg * 32 + b) * HID + cg * 8 + u] = __float2half_rn(hv);
}

// ---------------- persistent scan kernel --------------------------------------
__global__ void __launch_bounds__(NT) scan_kernel()
{
    extern __shared__ unsigned smem_u[];
    unsigned* wp0   = smem_u;                 // layer0 weights  [WPW_L0]
    unsigned* wp1   = smem_u + WPW_L0;        // layer1 weights  [WPW_L1]
    unsigned* As0   = smem_u + WPW;           // [32][324]
    unsigned* As1   = As0 + AS0_WORDS;        // [32][516]
    float*    red   = (float*)(As1 + AS1_WORDS);   // [32][33]
    float*    bias2 = red + 1056;             // [64]

    const int tid  = threadIdx.x;
    const int cg   = blockIdx.x & 63;
    const int bg   = blockIdx.x >> 6;
    const int w    = tid >> 5, lane = tid & 31;
    const int kh   = w >> 2;
    const int wm   = (w >> 1) & 1;
    const int wn   = w & 1;
    const int r4   = lane >> 2, kq4 = lane & 3;

    // one-time weight load into SMEM
    {
        const uint4* src = (const uint4*)(d_Wp + (size_t)cg * WPW);
        uint4* dst = (uint4*)wp0;
        for (int i = tid; i < WPW / 4; i += NT) dst[i] = src[i];
        if (tid < 32) {
            bias2[tid]      = d_b0r[cg * 32 + tid];
            bias2[32 + tid] = d_b1r[cg * 32 + tid];
        }
    }
    // zero t=-1 hidden buffers: 16384 u32 words per buffer, 32768 grid threads
    {
        int gt = blockIdx.x * NT + tid;
        if (gt < BATCH * (HID / 2)) d_h0[1][gt] = 0u;
        else                        d_h1[1][gt - BATCH * (HID / 2)] = 0u;
    }
    float c0 = 0.0f, c1 = 0.0f;
    grid_barrier();

    for (int k = 0; k <= SEQ; ++k) {
        const int doL0 = (k < SEQ);
        const int doL1 = (k >= 1);

        // ===== stage both layers' A tiles (all sources ready post-barrier) ====
        if (doL0) {
            const unsigned* __restrict__ h0prev = d_h0[(k + 1) & 1];
            // 32 rows x 320 words = 2560 uint4
            #pragma unroll 2
            for (int i = tid; i < 2560; i += NT) {
                int row = i / 80;
                int w4  = i % 80;
                int wd  = w4 * 4;
                int gb  = bg * 32 + row;
                const uint4* s = (w4 < 16)
                    ? (const uint4*)(d_x16 + (size_t)gb * (SEQ * 64) + (size_t)k * 64 + wd)
                    : (const uint4*)(h0prev + gb * 256 + (wd - 64));
                *(uint4*)(As0 + row * AS0_STRIDE + wd) = *s;
            }
        }
        if (doL1) {
            const unsigned* __restrict__ h0cur  = d_h0[(k - 1) & 1];
            const unsigned* __restrict__ h1prev = d_h1[k & 1];
            // 32 rows x 512 words = 4096 uint4
            #pragma unroll 2
            for (int i = tid; i < 4096; i += NT) {
                int row = i >> 7;
                int w4  = i & 127;
                int wd  = w4 * 4;
                int gb  = bg * 32 + row;
                const uint4* s = (w4 < 64)
                    ? (const uint4*)(h0cur + gb * 256 + wd)
                    : (const uint4*)(h1prev + gb * 256 + (wd - 256));
                *(uint4*)(As1 + row * AS1_STRIDE + wd) = *s;
            }
        }
        __syncthreads();

        // ===== layer 0 MMAs: t = k =====
        if (doL0) {
            float acc[2][4] = {};
            const unsigned* abase = As0 + (wm * 16 + r4) * AS0_STRIDE + kq4;
            const unsigned* bbase = wp0 + (wn * 2) * 64 + lane * 2;
            #pragma unroll 4
            for (int kb = kh * 20; kb < kh * 20 + 20; ++kb) {
                const unsigned* aw = abase + kb * 8;
                unsigned a0 = aw[0];
                unsigned a1 = aw[8 * AS0_STRIDE];
                unsigned a2 = aw[4];
                unsigned a3 = aw[8 * AS0_STRIDE + 4];
                const unsigned* bp = bbase + kb * 256;
                uint2 b0 = *(const uint2*)bp;
                uint2 b1 = *(const uint2*)(bp + 64);
                mma16(acc[0], a0, a1, a2, a3, b0.x, b0.y);
                mma16(acc[1], a0, a1, a2, a3, b1.x, b1.y);
            }
            finish_layer(acc, red, bias2, c0, d_h0[k & 1], tid, kh, wm, wn, cg, bg);
        }

        // ===== layer 1 MMAs: t = k-1 =====
        if (doL1) {
            float acc[2][4] = {};
            const unsigned* abase = As1 + (wm * 16 + r4) * AS1_STRIDE + kq4;
            const unsigned* bbase = wp1 + (wn * 2) * 64 + lane * 2;
            #pragma unroll 4
            for (int kb = kh * 32; kb < kh * 32 + 32; ++kb) {
                const unsigned* aw = abase + kb * 8;
                unsigned a0 = aw[0];
                unsigned a1 = aw[8 * AS1_STRIDE];
                unsigned a2 = aw[4];
                unsigned a3 = aw[8 * AS1_STRIDE + 4];
                const unsigned* bp = bbase + kb * 256;
                uint2 b0 = *(const uint2*)bp;
                uint2 b1 = *(const uint2*)(bp + 64);
                mma16(acc[0], a0, a1, a2, a3, b0.x, b0.y);
                mma16(acc[1], a0, a1, a2, a3, b1.x, b1.y);
            }
            finish_layer(acc, red, bias2 + 32, c1, d_h1[(k - 1) & 1],
                         tid, kh, wm, wn, cg, bg);
        }

        grid_barrier();
    }
}

// ---------------- final FC head -------------------------------------------------
__global__ void fc_kernel(const float* __restrict__ fc1w, const float* __restrict__ fc1b,
                          const float* __restrict__ fc2w, const float* __restrict__ fc2b,
                          float* __restrict__ out)
{
    __shared__ float hs[HID];
    __shared__ float y1[HID];
    const int b = blockIdx.x;
    const int tid = threadIdx.x;
    const __half* __restrict__ h = (const __half*)d_h1[1] + b * HID;  // t=511
    for (int i = tid; i < HID; i += blockDim.x) hs[i] = __half2float(h[i]);
    __syncthreads();
    for (int j = tid; j < HID; j += blockDim.x) {
        float a = fc1b[j];
        const float* __restrict__ wr = fc1w + j * HID;
        #pragma unroll 4
        for (int kk = 0; kk < HID; ++kk) a = fmaf(wr[kk], hs[kk], a);
        y1[j] = a;
    }
    __syncthreads();
    if (tid < OUTN) {
        float a = fc2b[tid];
        const float* __restrict__ wr = fc2w + tid * HID;
        #pragma unroll 4
        for (int kk = 0; kk < HID; ++kk) a = fmaf(wr[kk], y1[kk], a);
        out[b * OUTN + tid] = fmaxf(a, 0.0f);
    }
}

// ---------------- launch ---------------------------------------------------------
extern "C" void kernel_launch(void* const* d_in, const int* in_sizes, int n_in,
                              void* d_out, int out_size)
{
    const float* x    = (const float*)d_in[0];
    const float* wf0  = (const float*)d_in[1];
    const float* bf0  = (const float*)d_in[2];
    const float* wi0  = (const float*)d_in[3];
    const float* bi0  = (const float*)d_in[4];
    const float* wo0  = (const float*)d_in[5];
    const float* bo0  = (const float*)d_in[6];
    const float* wg0  = (const float*)d_in[7];
    const float* bg0  = (const float*)d_in[8];
    const float* wf1  = (const float*)d_in[9];
    const float* bf1  = (const float*)d_in[10];
    const float* wi1  = (const float*)d_in[11];
    const float* bi1  = (const float*)d_in[12];
    const float* wo1  = (const float*)d_in[13];
    const float* bo1  = (const float*)d_in[14];
    const float* wg1  = (const float*)d_in[15];
    const float* bg1  = (const float*)d_in[16];
    const float* fc1w = (const float*)d_in[17];
    const float* fc1b = (const float*)d_in[18];
    const float* fc2w = (const float*)d_in[19];
    const float* fc2b = (const float*)d_in[20];
    float* out = (float*)d_out;

    cudaFuncSetAttribute(scan_kernel,
                         cudaFuncAttributeMaxDynamicSharedMemorySize, SMEM_BYTES);

    prep_kernel<<<4096, 256>>>(x, wf0, wi0, wo0, wg0, bf0, bi0, bo0, bg0,
                               wf1, wi1, wo1, wg1, bf1, bi1, bo1, bg1);
    scan_kernel<<<NCTA, NT, SMEM_BYTES>>>();
    fc_kernel<<<BATCH, 256>>>(fc1w, fc1b, fc2w, fc2b, out);
}

// round 6
// speedup vs baseline: 6.5509x; 1.2993x over previous
#include <cuda_runtime.h>
#include <cuda_fp16.h>
#include <math.h>

#define BATCH 64
#define SEQ   512
#define DIN   128
#define HID   512
#define OUTN  24
#define K0    640
#define K1    1024
#define COLS  2048

#define NCTA   128
#define NCTABG 64
#define NT     256

// fp16 weight words (u32 = half2) per column-group (full K packing in d_Wp)
#define WPW_L0 10240               // 40 k16-blocks * 4 n8-blocks * 64 words
#define WPW_L1 16384               // 64 * 4 * 64
#define WPW    (WPW_L0 + WPW_L1)   // 26624 u32 per cg

// scan smem: L0 keeps only recurrent part (kb 8..39 -> 32 k16 blocks)
#define WS0_WORDS 8192             // 32 * 256
#define WS1_WORDS 16384            // 64 * 256

#define AS0_STRIDE 260             // 256 words (512 fp16) + 4 pad
#define AS1_STRIDE 516             // 512 words + 4 pad
#define AS0_WORDS (32 * AS0_STRIDE)   // 8320
#define AS1_WORDS (32 * AS1_STRIDE)   // 16512

#define SMEM_U32  (WS0_WORDS + WS1_WORDS + AS0_WORDS + AS1_WORDS + 1056 + 64)
#define SMEM_BYTES (SMEM_U32 * 4)

// xz gemm smem
#define XG_SMEM_U32 (128 * 68 + 16384)
#define XG_SMEM_BYTES (XG_SMEM_U32 * 4)

// ---------------- persistent device state ----------------------------------
__device__ __align__(16) unsigned d_Wp[64 * WPW];
__device__ __align__(16) unsigned d_x16[BATCH * SEQ * (DIN / 2)];
__device__ __align__(16) unsigned d_xz[BATCH * SEQ * (COLS / 2)];  // fp16 x-proj + bias
__device__ float d_b0r[COLS];
__device__ float d_b1r[COLS];
__device__ __align__(16) unsigned d_h0[2][BATCH * (HID / 2)];
__device__ __align__(16) unsigned d_h1[2][BATCH * (HID / 2)];
__device__ unsigned g_bar_count[2] = {0, 0};
__device__ unsigned g_bar_gen[2]   = {0, 0};

__device__ __forceinline__ float sigf(float v) { return 1.0f / (1.0f + __expf(-v)); }
__device__ __forceinline__ float tanhfast(float v) {
    return 1.0f - 2.0f / (__expf(2.0f * v) + 1.0f);
}

__device__ __forceinline__ void mma16(float c[4], unsigned a0, unsigned a1,
                                      unsigned a2, unsigned a3,
                                      unsigned b0, unsigned b1)
{
    asm volatile(
        "mma.sync.aligned.m16n8k16.row.col.f32.f16.f16.f32 "
        "{%0,%1,%2,%3},{%4,%5,%6,%7},{%8,%9},{%0,%1,%2,%3};"
        : "+f"(c[0]), "+f"(c[1]), "+f"(c[2]), "+f"(c[3])
        : "r"(a0), "r"(a1), "r"(a2), "r"(a3), "r"(b0), "r"(b1));
}

__device__ __forceinline__ void cpa16(void* dst, const void* src)
{
    unsigned d = (unsigned)__cvta_generic_to_shared(dst);
    asm volatile("cp.async.cg.shared.global [%0], [%1], 16;" :: "r"(d), "l"(src));
}
__device__ __forceinline__ void cpa_commit_wait()
{
    asm volatile("cp.async.commit_group;");
    asm volatile("cp.async.wait_group 0;");
}

// ---------------- prep: weight packing (fp16), x conversion, biases ---------
__global__ void prep_kernel(
    const float* __restrict__ x,
    const float* __restrict__ wf0, const float* __restrict__ wi0,
    const float* __restrict__ wo0, const float* __restrict__ wg0,
    const float* __restrict__ bf0, const float* __restrict__ bi0,
    const float* __restrict__ bo0, const float* __restrict__ bg0,
    const float* __restrict__ wf1, const float* __restrict__ wi1,
    const float* __restrict__ wo1, const float* __restrict__ wg1,
    const float* __restrict__ bf1, const float* __restrict__ bi1,
    const float* __restrict__ bo1, const float* __restrict__ bg1)
{
    const int nW = 64 * WPW;
    const int nX = BATCH * SEQ * (DIN / 2);
    const int ntot = nW + nX + 2 * COLS;
    for (int idx = blockIdx.x * blockDim.x + threadIdx.x; idx < ntot;
         idx += gridDim.x * blockDim.x) {
        if (idx < nW) {
            int cg = idx / WPW;
            int r  = idx % WPW;
            int layer = (r < WPW_L0) ? 0 : 1;
            int rr    = layer ? (r - WPW_L0) : r;
            int kb   = rr >> 8;
            int rem  = rr & 255;
            int nb   = rem >> 6;
            int t    = rem & 63;
            int lane = t >> 1;
            int reg  = t & 1;
            int colloc = nb * 8 + (lane >> 2);
            int unit = cg * 8 + (colloc >> 2);
            int gate = colloc & 3;
            int k    = kb * 16 + (lane & 3) * 2 + reg * 8;
            const float* w;
            int K;
            if (layer == 0) {
                w = (gate == 0) ? wf0 : (gate == 1) ? wi0 : (gate == 2) ? wo0 : wg0;
                K = K0;
            } else {
                w = (gate == 0) ? wf1 : (gate == 1) ? wi1 : (gate == 2) ? wo1 : wg1;
                K = K1;
            }
            __half2 h2 = __floats2half2_rn(w[unit * K + k], w[unit * K + k + 1]);
            d_Wp[idx] = *(unsigned*)&h2;
        } else if (idx < nW + nX) {
            int i = idx - nW;
            __half2 h2 = __floats2half2_rn(x[2 * i], x[2 * i + 1]);
            d_x16[i] = *(unsigned*)&h2;
        } else {
            int col = idx - nW - nX;
            if (col < COLS) {
                int u = col >> 2, g = col & 3;
                const float* bb = (g == 0) ? bf0 : (g == 1) ? bi0 : (g == 2) ? bo0 : bg0;
                d_b0r[col] = bb[u];
            } else {
                col -= COLS;
                int u = col >> 2, g = col & 3;
                const float* bb = (g == 0) ? bf1 : (g == 1) ? bi1 : (g == 2) ? bo1 : bg1;
                d_b1r[col] = bb[u];
            }
        }
    }
}

// ---------------- xz GEMM: xz[b,t,:] = x_t @ Wx0^T + b0 (fp16 out) ----------
__global__ void __launch_bounds__(NT) xz_gemm_kernel()
{
    extern __shared__ unsigned smem_u[];
    unsigned* As = smem_u;                 // [128][68]
    unsigned* Ws = smem_u + 128 * 68;      // 8 cgs * 2048 words

    const int tid  = threadIdx.x;
    const int w    = tid >> 5, lane = tid & 31;
    const int r4   = lane >> 2, kq4 = lane & 3;
    const int row0 = blockIdx.x * 128;
    const int cg0  = blockIdx.y * 8;

    #pragma unroll
    for (int i = tid; i < 2048; i += NT) {
        int row = i >> 4, w4 = (i & 15) * 4;
        cpa16(As + row * 68 + w4, d_x16 + (size_t)(row0 + row) * 64 + w4);
    }
    #pragma unroll
    for (int i = tid; i < 4096; i += NT) {
        int cgL = i >> 9, r = (i & 511) * 4;
        cpa16(Ws + cgL * 2048 + r, d_Wp + (size_t)(cg0 + cgL) * WPW + r);
    }
    cpa_commit_wait();
    __syncthreads();

    float acc[32][4];
    #pragma unroll
    for (int i = 0; i < 32; ++i)
        { acc[i][0] = 0.f; acc[i][1] = 0.f; acc[i][2] = 0.f; acc[i][3] = 0.f; }

    #pragma unroll
    for (int kb = 0; kb < 8; ++kb) {
        const unsigned* ab = As + (w * 16 + r4) * 68 + kb * 8 + kq4;
        unsigned a0 = ab[0];
        unsigned a1 = ab[8 * 68];
        unsigned a2 = ab[4];
        unsigned a3 = ab[8 * 68 + 4];
        #pragma unroll
        for (int j = 0; j < 32; ++j) {          // j = cgL*4 + nb
            const unsigned* bp = Ws + (j >> 2) * 2048 + kb * 256 + (j & 3) * 64 + lane * 2;
            uint2 b = *(const uint2*)bp;
            mma16(acc[j], a0, a1, a2, a3, b.x, b.y);
        }
    }

    #pragma unroll
    for (int j = 0; j < 32; ++j) {
        int col = (cg0 + (j >> 2)) * 32 + (j & 3) * 8 + 2 * (lane & 3);
        float bs0 = d_b0r[col], bs1 = d_b0r[col + 1];
        int mrow = row0 + w * 16 + r4;
        __half2 p0 = __floats2half2_rn(acc[j][0] + bs0, acc[j][1] + bs1);
        __half2 p1 = __floats2half2_rn(acc[j][2] + bs0, acc[j][3] + bs1);
        d_xz[(size_t)mrow * 1024 + (col >> 1)]        = *(unsigned*)&p0;
        d_xz[(size_t)(mrow + 8) * 1024 + (col >> 1)]  = *(unsigned*)&p1;
    }
}

// ---------------- per-bg grid barrier (split, replay-safe relative gen) ------
__device__ __forceinline__ void bar_arrive(int bg)
{
    __syncthreads();
    if (threadIdx.x == 0) {
        __threadfence();
        unsigned prev = atomicAdd(&g_bar_count[bg], 1u);
        if (prev == NCTABG - 1) {
            atomicExch(&g_bar_count[bg], 0u);
            __threadfence();
            atomicAdd(&g_bar_gen[bg], 1u);
        }
    }
}
// base = snapshot of g_bar_gen[bg] taken at kernel entry (before first arrive).
// Wait until (gen - base) >= mygen; unsigned arithmetic is wraparound-safe and
// replay-safe because only the delta within this launch matters.
__device__ __forceinline__ void bar_wait(int bg, unsigned base, unsigned mygen)
{
    if (threadIdx.x == 0) {
        volatile unsigned* genp = &g_bar_gen[bg];
        while ((unsigned)(*genp - base) < mygen) {}
        __threadfence();
    }
    __syncthreads();
}

// ---------------- persistent scan kernel --------------------------------------
__global__ void __launch_bounds__(NT) scan_kernel()
{
    extern __shared__ unsigned smem_u[];
    unsigned* wp0   = smem_u;                    // [WS0_WORDS] recurrent L0
    unsigned* wp1   = smem_u + WS0_WORDS;        // [WS1_WORDS]
    unsigned* As0   = wp1 + WS1_WORDS;           // [32][260]
    unsigned* As1   = As0 + AS0_WORDS;           // [32][516]
    float*    red   = (float*)(As1 + AS1_WORDS); // [32][33]
    float*    bias1 = red + 1056;                // [32]

    const int tid  = threadIdx.x;
    const int cg   = blockIdx.x & 63;
    const int bg   = blockIdx.x >> 6;
    const int w    = tid >> 5, lane = tid & 31;
    const int kh   = w >> 2;
    const int wm   = (w >> 1) & 1;
    const int wn   = w & 1;
    const int r4   = lane >> 2, kq4 = lane & 3;

    // finish-phase role
    const int fb = tid >> 3, fu = tid & 7;

    // Snapshot barrier generation BEFORE first arrive (replay-safe).
    unsigned bar_base = 0;
    if (tid == 0) bar_base = *(volatile unsigned*)&g_bar_gen[bg];

    // one-time weight load into SMEM (L0 recurrent part: kb 8..39)
    {
        const uint4* s0 = (const uint4*)(d_Wp + (size_t)cg * WPW + 2048);
        const uint4* s1 = (const uint4*)(d_Wp + (size_t)cg * WPW + WPW_L0);
        uint4* t0 = (uint4*)wp0;
        uint4* t1 = (uint4*)wp1;
        for (int i = tid; i < WS0_WORDS / 4; i += NT) t0[i] = s0[i];
        for (int i = tid; i < WS1_WORDS / 4; i += NT) t1[i] = s1[i];
        if (tid < 32) bias1[tid] = d_b1r[cg * 32 + tid];
    }
    // zero this bg's t=-1 hidden rows: 64 CTAs x 256 threads = 16384 slots
    {
        int idx = cg * NT + tid;    // 0..16383
        if (idx < 8192) d_h0[1][bg * 8192 + idx] = 0u;
        else            d_h1[1][bg * 8192 + (idx - 8192)] = 0u;
    }
    float c0 = 0.0f, c1 = 0.0f;
    bar_arrive(bg);
    unsigned mygen = 1;

    for (int k = 0; k <= SEQ; ++k) {
        const int doL0 = (k < SEQ);
        const int doL1 = (k >= 1);

        // xz prefetch (no dependency on h) — overlap with barrier propagation
        uint2 zraw;
        if (doL0)
            zraw = *(const uint2*)(d_xz +
                    (size_t)((bg * 32 + fb) * SEQ + k) * 1024 + cg * 16 + fu * 2);

        bar_wait(bg, bar_base, mygen); ++mygen;

        // ===== stage A tiles via cp.async =====
        if (doL0) {
            const unsigned* __restrict__ h0prev = d_h0[(k + 1) & 1];
            #pragma unroll
            for (int i = tid; i < 2048; i += NT) {
                int row = i >> 6, wd = (i & 63) * 4;
                cpa16(As0 + row * AS0_STRIDE + wd,
                      h0prev + (bg * 32 + row) * 256 + wd);
            }
        }
        if (doL1) {
            const unsigned* __restrict__ h0cur  = d_h0[(k - 1) & 1];
            const unsigned* __restrict__ h1prev = d_h1[k & 1];
            #pragma unroll
            for (int i = tid; i < 4096; i += NT) {
                int row = i >> 7, w4 = i & 127;
                int wd = w4 * 4;
                const unsigned* s = (w4 < 64)
                    ? h0cur + (bg * 32 + row) * 256 + wd
                    : h1prev + (bg * 32 + row) * 256 + (wd - 256);
                cpa16(As1 + row * AS1_STRIDE + wd, s);
            }
        }
        cpa_commit_wait();
        __syncthreads();

        // ===== layer 0 MMAs: t = k (recurrent K=512) =====
        if (doL0) {
            float acc[2][4] = {};
            const unsigned* abase = As0 + (wm * 16 + r4) * AS0_STRIDE + kq4;
            const unsigned* bbase = wp0 + (wn * 2) * 64 + lane * 2;
            #pragma unroll 8
            for (int kb = kh * 16; kb < kh * 16 + 16; ++kb) {
                const unsigned* aw = abase + kb * 8;
                unsigned a0 = aw[0];
                unsigned a1 = aw[8 * AS0_STRIDE];
                unsigned a2 = aw[4];
                unsigned a3 = aw[8 * AS0_STRIDE + 4];
                const unsigned* bp = bbase + kb * 256;
                uint2 b0 = *(const uint2*)bp;
                uint2 b1 = *(const uint2*)(bp + 64);
                mma16(acc[0], a0, a1, a2, a3, b0.x, b0.y);
                mma16(acc[1], a0, a1, a2, a3, b1.x, b1.y);
            }
            // reduce kh halves through smem
            int rb = wm * 16 + r4;
            int cb = wn * 16 + 2 * (lane & 3);
            __syncthreads();
            if (kh) {
                #pragma unroll
                for (int nn = 0; nn < 2; ++nn) {
                    red[rb * 33 + cb + nn * 8]           = acc[nn][0];
                    red[rb * 33 + cb + nn * 8 + 1]       = acc[nn][1];
                    red[(rb + 8) * 33 + cb + nn * 8]     = acc[nn][2];
                    red[(rb + 8) * 33 + cb + nn * 8 + 1] = acc[nn][3];
                }
            }
            __syncthreads();
            if (!kh) {
                #pragma unroll
                for (int nn = 0; nn < 2; ++nn) {
                    red[rb * 33 + cb + nn * 8]           += acc[nn][0];
                    red[rb * 33 + cb + nn * 8 + 1]       += acc[nn][1];
                    red[(rb + 8) * 33 + cb + nn * 8]     += acc[nn][2];
                    red[(rb + 8) * 33 + cb + nn * 8 + 1] += acc[nn][3];
                }
            }
            __syncthreads();
            {
                __half2 zl = *(__half2*)&zraw.x;
                __half2 zh = *(__half2*)&zraw.y;
                float zf = red[fb * 33 + fu * 4 + 0] + __low2float(zl);
                float zi = red[fb * 33 + fu * 4 + 1] + __high2float(zl);
                float zo = red[fb * 33 + fu * 4 + 2] + __low2float(zh);
                float zg = red[fb * 33 + fu * 4 + 3] + __high2float(zh);
                float f  = sigf(zf);
                float ii = sigf(zi);
                float o  = sigf(zo);
                float g  = tanhfast(zg);
                float c  = f * c0 + ii * g;
                c0 = c;
                float hv = o * tanhfast(c);
                ((__half*)d_h0[k & 1])[(bg * 32 + fb) * HID + cg * 8 + fu] =
                    __float2half_rn(hv);
            }
            __syncthreads();
        }

        // ===== layer 1 MMAs: t = k-1 =====
        if (doL1) {
            float acc[2][4] = {};
            const unsigned* abase = As1 + (wm * 16 + r4) * AS1_STRIDE + kq4;
            const unsigned* bbase = wp1 + (wn * 2) * 64 + lane * 2;
            #pragma unroll 8
            for (int kb = kh * 32; kb < kh * 32 + 32; ++kb) {
                const unsigned* aw = abase + kb * 8;
                unsigned a0 = aw[0];
                unsigned a1 = aw[8 * AS1_STRIDE];
                unsigned a2 = aw[4];
                unsigned a3 = aw[8 * AS1_STRIDE + 4];
                const unsigned* bp = bbase + kb * 256;
                uint2 b0 = *(const uint2*)bp;
                uint2 b1 = *(const uint2*)(bp + 64);
                mma16(acc[0], a0, a1, a2, a3, b0.x, b0.y);
                mma16(acc[1], a0, a1, a2, a3, b1.x, b1.y);
            }
            int rb = wm * 16 + r4;
            int cb = wn * 16 + 2 * (lane & 3);
            __syncthreads();
            if (kh) {
                #pragma unroll
                for (int nn = 0; nn < 2; ++nn) {
                    red[rb * 33 + cb + nn * 8]           = acc[nn][0];
                    red[rb * 33 + cb + nn * 8 + 1]       = acc[nn][1];
                    red[(rb + 8) * 33 + cb + nn * 8]     = acc[nn][2];
                    red[(rb + 8) * 33 + cb + nn * 8 + 1] = acc[nn][3];
                }
            }
            __syncthreads();
            if (!kh) {
                #pragma unroll
                for (int nn = 0; nn < 2; ++nn) {
                    red[rb * 33 + cb + nn * 8]           += acc[nn][0];
                    red[rb * 33 + cb + nn * 8 + 1]       += acc[nn][1];
                    red[(rb + 8) * 33 + cb + nn * 8]     += acc[nn][2];
                    red[(rb + 8) * 33 + cb + nn * 8 + 1] += acc[nn][3];
                }
            }
            __syncthreads();
            {
                float zf = red[fb * 33 + fu * 4 + 0] + bias1[fu * 4 + 0];
                float zi = red[fb * 33 + fu * 4 + 1] + bias1[fu * 4 + 1];
                float zo = red[fb * 33 + fu * 4 + 2] + bias1[fu * 4 + 2];
                float zg = red[fb * 33 + fu * 4 + 3] + bias1[fu * 4 + 3];
                float f  = sigf(zf);
                float ii = sigf(zi);
                float o  = sigf(zo);
                float g  = tanhfast(zg);
                float c  = f * c1 + ii * g;
                c1 = c;
                float hv = o * tanhfast(c);
                ((__half*)d_h1[(k - 1) & 1])[(bg * 32 + fb) * HID + cg * 8 + fu] =
                    __float2half_rn(hv);
            }
        }

        bar_arrive(bg);
    }
}

// ---------------- final FC head -------------------------------------------------
__global__ void fc_kernel(const float* __restrict__ fc1w, const float* __restrict__ fc1b,
                          const float* __restrict__ fc2w, const float* __restrict__ fc2b,
                          float* __restrict__ out)
{
    __shared__ float hs[HID];
    __shared__ float y1[HID];
    const int b = blockIdx.x;
    const int tid = threadIdx.x;
    const __half* __restrict__ h = (const __half*)d_h1[1] + b * HID;  // t=511
    for (int i = tid; i < HID; i += blockDim.x) hs[i] = __half2float(h[i]);
    __syncthreads();
    for (int j = tid; j < HID; j += blockDim.x) {
        float a = fc1b[j];
        const float* __restrict__ wr = fc1w + j * HID;
        #pragma unroll 4
        for (int kk = 0; kk < HID; ++kk) a = fmaf(wr[kk], hs[kk], a);
        y1[j] = a;
    }
    __syncthreads();
    if (tid < OUTN) {
        float a = fc2b[tid];
        const float* __restrict__ wr = fc2w + tid * HID;
        #pragma unroll 4
        for (int kk = 0; kk < HID; ++kk) a = fmaf(wr[kk], y1[kk], a);
        out[b * OUTN + tid] = fmaxf(a, 0.0f);
    }
}

// ---------------- launch ---------------------------------------------------------
extern "C" void kernel_launch(void* const* d_in, const int* in_sizes, int n_in,
                              void* d_out, int out_size)
{
    const float* x    = (const float*)d_in[0];
    const float* wf0  = (const float*)d_in[1];
    const float* bf0  = (const float*)d_in[2];
    const float* wi0  = (const float*)d_in[3];
    const float* bi0  = (const float*)d_in[4];
    const float* wo0  = (const float*)d_in[5];
    const float* bo0  = (const float*)d_in[6];
    const float* wg0  = (const float*)d_in[7];
    const float* bg0  = (const float*)d_in[8];
    const float* wf1  = (const float*)d_in[9];
    const float* bf1  = (const float*)d_in[10];
    const float* wi1  = (const float*)d_in[11];
    const float* bi1  = (const float*)d_in[12];
    const float* wo1  = (const float*)d_in[13];
    const float* bo1  = (const float*)d_in[14];
    const float* wg1  = (const float*)d_in[15];
    const float* bg1  = (const float*)d_in[16];
    const float* fc1w = (const float*)d_in[17];
    const float* fc1b = (const float*)d_in[18];
    const float* fc2w = (const float*)d_in[19];
    const float* fc2b = (const float*)d_in[20];
    float* out = (float*)d_out;

    cudaFuncSetAttribute(scan_kernel,
                         cudaFuncAttributeMaxDynamicSharedMemorySize, SMEM_BYTES);
    cudaFuncSetAttribute(xz_gemm_kernel,
                         cudaFuncAttributeMaxDynamicSharedMemorySize, XG_SMEM_BYTES);

    prep_kernel<<<4096, 256>>>(x, wf0, wi0, wo0, wg0, bf0, bi0, bo0, bg0,
                               wf1, wi1, wo1, wg1, bf1, bi1, bo1, bg1);
    dim3 xzgrid(256, 8);
    xz_gemm_kernel<<<xzgrid, NT, XG_SMEM_BYTES>>>();
    scan_kernel<<<NCTA, NT, SMEM_BYTES>>>();
    fc_kernel<<<BATCH, 256>>>(fc1w, fc1b, fc2w, fc2b, out);
}

// round 7
// speedup vs baseline: 7.3959x; 1.1290x over previous
#include <cuda_runtime.h>
#include <cuda_fp16.h>
#include <math.h>

#define BATCH 64
#define SEQ   512
#define DIN   128
#define HID   512
#define OUTN  24
#define K0    640
#define K1    1024
#define COLS  2048

#define NCTA   128
#define NCTABG 64
#define NT     256

// fp16 weight words (u32 = half2) per column-group (full K packing in d_Wp)
#define WPW_L0 10240               // 40 k16-blocks * 4 n8-blocks * 64 words
#define WPW_L1 16384               // 64 * 4 * 64
#define WPW    (WPW_L0 + WPW_L1)   // 26624 u32 per cg

// scan smem: L0 keeps only recurrent part (kb 8..39 -> 32 k16 blocks)
#define WS0_WORDS 8192             // 32 * 256
#define WS1_WORDS 16384            // 64 * 256

#define AS_STRIDE 260              // 256 words (512 fp16) + 4 pad
#define AS_WORDS (32 * AS_STRIDE)  // 8320

// red: 2 layers x 2 kh-halves x 32 x 33 floats
#define RED_FLOATS (2 * 2 * 1056)

#define SMEM_U32  (WS0_WORDS + WS1_WORDS + 2 * AS_WORDS + RED_FLOATS + 64)
#define SMEM_BYTES (SMEM_U32 * 4)

// xz gemm smem
#define XG_SMEM_U32 (128 * 68 + 16384)
#define XG_SMEM_BYTES (XG_SMEM_U32 * 4)

// ---------------- persistent device state ----------------------------------
__device__ __align__(16) unsigned d_Wp[64 * WPW];
__device__ __align__(16) unsigned d_x16[BATCH * SEQ * (DIN / 2)];
__device__ __align__(16) unsigned d_xz[BATCH * SEQ * (COLS / 2)];  // fp16 x-proj + bias
__device__ float d_b0r[COLS];
__device__ float d_b1r[COLS];
__device__ __align__(16) unsigned d_h0[2][BATCH * (HID / 2)];
__device__ __align__(16) unsigned d_h1[2][BATCH * (HID / 2)];
__device__ unsigned g_bar_count[2] = {0, 0};
__device__ unsigned g_bar_gen[2]   = {0, 0};

__device__ __forceinline__ float sigf(float v) { return 1.0f / (1.0f + __expf(-v)); }
__device__ __forceinline__ float tanhfast(float v) {
    return 1.0f - 2.0f / (__expf(2.0f * v) + 1.0f);
}

__device__ __forceinline__ void mma16(float c[4], unsigned a0, unsigned a1,
                                      unsigned a2, unsigned a3,
                                      unsigned b0, unsigned b1)
{
    asm volatile(
        "mma.sync.aligned.m16n8k16.row.col.f32.f16.f16.f32 "
        "{%0,%1,%2,%3},{%4,%5,%6,%7},{%8,%9},{%0,%1,%2,%3};"
        : "+f"(c[0]), "+f"(c[1]), "+f"(c[2]), "+f"(c[3])
        : "r"(a0), "r"(a1), "r"(a2), "r"(a3), "r"(b0), "r"(b1));
}

__device__ __forceinline__ void cpa16(void* dst, const void* src)
{
    unsigned d = (unsigned)__cvta_generic_to_shared(dst);
    asm volatile("cp.async.cg.shared.global [%0], [%1], 16;" :: "r"(d), "l"(src));
}
__device__ __forceinline__ void cpa_commit_wait()
{
    asm volatile("cp.async.commit_group;");
    asm volatile("cp.async.wait_group 0;");
}

// ---------------- prep: weight packing (fp16), x conversion, biases ---------
__global__ void prep_kernel(
    const float* __restrict__ x,
    const float* __restrict__ wf0, const float* __restrict__ wi0,
    const float* __restrict__ wo0, const float* __restrict__ wg0,
    const float* __restrict__ bf0, const float* __restrict__ bi0,
    const float* __restrict__ bo0, const float* __restrict__ bg0,
    const float* __restrict__ wf1, const float* __restrict__ wi1,
    const float* __restrict__ wo1, const float* __restrict__ wg1,
    const float* __restrict__ bf1, const float* __restrict__ bi1,
    const float* __restrict__ bo1, const float* __restrict__ bg1)
{
    const int nW = 64 * WPW;
    const int nX = BATCH * SEQ * (DIN / 2);
    const int ntot = nW + nX + 2 * COLS;
    for (int idx = blockIdx.x * blockDim.x + threadIdx.x; idx < ntot;
         idx += gridDim.x * blockDim.x) {
        if (idx < nW) {
            int cg = idx / WPW;
            int r  = idx % WPW;
            int layer = (r < WPW_L0) ? 0 : 1;
            int rr    = layer ? (r - WPW_L0) : r;
            int kb   = rr >> 8;
            int rem  = rr & 255;
            int nb   = rem >> 6;
            int t    = rem & 63;
            int lane = t >> 1;
            int reg  = t & 1;
            int colloc = nb * 8 + (lane >> 2);
            int unit = cg * 8 + (colloc >> 2);
            int gate = colloc & 3;
            int k    = kb * 16 + (lane & 3) * 2 + reg * 8;
            const float* w;
            int K;
            if (layer == 0) {
                w = (gate == 0) ? wf0 : (gate == 1) ? wi0 : (gate == 2) ? wo0 : wg0;
                K = K0;
            } else {
                w = (gate == 0) ? wf1 : (gate == 1) ? wi1 : (gate == 2) ? wo1 : wg1;
                K = K1;
            }
            __half2 h2 = __floats2half2_rn(w[unit * K + k], w[unit * K + k + 1]);
            d_Wp[idx] = *(unsigned*)&h2;
        } else if (idx < nW + nX) {
            int i = idx - nW;
            __half2 h2 = __floats2half2_rn(x[2 * i], x[2 * i + 1]);
            d_x16[i] = *(unsigned*)&h2;
        } else {
            int col = idx - nW - nX;
            if (col < COLS) {
                int u = col >> 2, g = col & 3;
                const float* bb = (g == 0) ? bf0 : (g == 1) ? bi0 : (g == 2) ? bo0 : bg0;
                d_b0r[col] = bb[u];
            } else {
                col -= COLS;
                int u = col >> 2, g = col & 3;
                const float* bb = (g == 0) ? bf1 : (g == 1) ? bi1 : (g == 2) ? bo1 : bg1;
                d_b1r[col] = bb[u];
            }
        }
    }
}

// ---------------- xz GEMM: xz[b,t,:] = x_t @ Wx0^T + b0 (fp16 out) ----------
__global__ void __launch_bounds__(NT) xz_gemm_kernel()
{
    extern __shared__ unsigned smem_u[];
    unsigned* As = smem_u;                 // [128][68]
    unsigned* Ws = smem_u + 128 * 68;      // 8 cgs * 2048 words

    const int tid  = threadIdx.x;
    const int w    = tid >> 5, lane = tid & 31;
    const int r4   = lane >> 2, kq4 = lane & 3;
    const int row0 = blockIdx.x * 128;
    const int cg0  = blockIdx.y * 8;

    #pragma unroll
    for (int i = tid; i < 2048; i += NT) {
        int row = i >> 4, w4 = (i & 15) * 4;
        cpa16(As + row * 68 + w4, d_x16 + (size_t)(row0 + row) * 64 + w4);
    }
    #pragma unroll
    for (int i = tid; i < 4096; i += NT) {
        int cgL = i >> 9, r = (i & 511) * 4;
        cpa16(Ws + cgL * 2048 + r, d_Wp + (size_t)(cg0 + cgL) * WPW + r);
    }
    cpa_commit_wait();
    __syncthreads();

    float acc[32][4];
    #pragma unroll
    for (int i = 0; i < 32; ++i)
        { acc[i][0] = 0.f; acc[i][1] = 0.f; acc[i][2] = 0.f; acc[i][3] = 0.f; }

    #pragma unroll
    for (int kb = 0; kb < 8; ++kb) {
        const unsigned* ab = As + (w * 16 + r4) * 68 + kb * 8 + kq4;
        unsigned a0 = ab[0];
        unsigned a1 = ab[8 * 68];
        unsigned a2 = ab[4];
        unsigned a3 = ab[8 * 68 + 4];
        #pragma unroll
        for (int j = 0; j < 32; ++j) {          // j = cgL*4 + nb
            const unsigned* bp = Ws + (j >> 2) * 2048 + kb * 256 + (j & 3) * 64 + lane * 2;
            uint2 b = *(const uint2*)bp;
            mma16(acc[j], a0, a1, a2, a3, b.x, b.y);
        }
    }

    #pragma unroll
    for (int j = 0; j < 32; ++j) {
        int col = (cg0 + (j >> 2)) * 32 + (j & 3) * 8 + 2 * (lane & 3);
        float bs0 = d_b0r[col], bs1 = d_b0r[col + 1];
        int mrow = row0 + w * 16 + r4;
        __half2 p0 = __floats2half2_rn(acc[j][0] + bs0, acc[j][1] + bs1);
        __half2 p1 = __floats2half2_rn(acc[j][2] + bs0, acc[j][3] + bs1);
        d_xz[(size_t)mrow * 1024 + (col >> 1)]        = *(unsigned*)&p0;
        d_xz[(size_t)(mrow + 8) * 1024 + (col >> 1)]  = *(unsigned*)&p1;
    }
}

// ---------------- per-bg grid barrier (split, replay-safe relative gen) ------
__device__ __forceinline__ void bar_arrive(int bg)
{
    __syncthreads();
    if (threadIdx.x == 0) {
        __threadfence();
        unsigned prev = atomicAdd(&g_bar_count[bg], 1u);
        if (prev == NCTABG - 1) {
            atomicExch(&g_bar_count[bg], 0u);
            __threadfence();
            atomicAdd(&g_bar_gen[bg], 1u);
        }
    }
}
__device__ __forceinline__ void bar_wait(int bg, unsigned base, unsigned mygen)
{
    if (threadIdx.x == 0) {
        volatile unsigned* genp = &g_bar_gen[bg];
        while ((unsigned)(*genp - base) < mygen) {}
        __threadfence();
    }
    __syncthreads();
}

// ---------------- persistent scan kernel --------------------------------------
__global__ void __launch_bounds__(NT) scan_kernel()
{
    extern __shared__ unsigned smem_u[];
    unsigned* wp0   = smem_u;                    // [WS0_WORDS] recurrent L0
    unsigned* wp1   = smem_u + WS0_WORDS;        // [WS1_WORDS]
    unsigned* As0   = wp1 + WS1_WORDS;           // [32][260]  h0[t] (shared L0/L1)
    unsigned* As1   = As0 + AS_WORDS;            // [32][260]  h1[t-1]
    float*    red   = (float*)(As1 + AS_WORDS);  // [2 layers][2 kh][32][33]
    float*    bias1 = red + RED_FLOATS;          // [32]

    const int tid  = threadIdx.x;
    const int cg   = blockIdx.x & 63;
    const int bg   = blockIdx.x >> 6;
    const int w    = tid >> 5, lane = tid & 31;
    const int kh   = w >> 2;
    const int wm   = (w >> 1) & 1;
    const int wn   = w & 1;
    const int r4   = lane >> 2, kq4 = lane & 3;

    // finish-phase role
    const int fb = tid >> 3, fu = tid & 7;

    // Snapshot barrier generation BEFORE first arrive (replay-safe).
    unsigned bar_base = 0;
    if (tid == 0) bar_base = *(volatile unsigned*)&g_bar_gen[bg];

    // one-time weight load into SMEM (L0 recurrent part: kb 8..39)
    {
        const uint4* s0 = (const uint4*)(d_Wp + (size_t)cg * WPW + 2048);
        const uint4* s1 = (const uint4*)(d_Wp + (size_t)cg * WPW + WPW_L0);
        uint4* t0 = (uint4*)wp0;
        uint4* t1 = (uint4*)wp1;
        for (int i = tid; i < WS0_WORDS / 4; i += NT) t0[i] = s0[i];
        for (int i = tid; i < WS1_WORDS / 4; i += NT) t1[i] = s1[i];
        if (tid < 32) bias1[tid] = d_b1r[cg * 32 + tid];
    }
    // zero this bg's t=-1 hidden rows
    {
        int idx = cg * NT + tid;    // 0..16383
        if (idx < 8192) d_h0[1][bg * 8192 + idx] = 0u;
        else            d_h1[1][bg * 8192 + (idx - 8192)] = 0u;
    }
    float c0 = 0.0f, c1 = 0.0f;
    bar_arrive(bg);
    unsigned mygen = 1;

    // warp-constant pointers for MMA phases
    const unsigned* a0base = As0 + (wm * 16 + r4) * AS_STRIDE + kq4;
    const unsigned* a1base = (kh ? As1 : As0) + (wm * 16 + r4) * AS_STRIDE + kq4;
    float* red0 = red + kh * 1056;          // L0 write target
    float* red1 = red + 2112 + kh * 1056;   // L1 write target

    for (int k = 0; k <= SEQ; ++k) {
        const int doL0 = (k < SEQ);
        const int doL1 = (k >= 1);

        // xz prefetch (no dependency on h) — overlap with barrier propagation
        uint2 zraw;
        if (doL0)
            zraw = *(const uint2*)(d_xz +
                    (size_t)((bg * 32 + fb) * SEQ + k) * 1024 + cg * 16 + fu * 2);

        bar_wait(bg, bar_base, mygen); ++mygen;

        // ===== stage A tiles via cp.async =====
        {   // h0[t = k-1], slot (k+1)&1 — needed by L0 (input) and L1 (kh=0 half)
            const unsigned* __restrict__ h0prev = d_h0[(k + 1) & 1];
            #pragma unroll
            for (int i = tid; i < 2048; i += NT) {
                int row = i >> 6, wd = (i & 63) * 4;
                cpa16(As0 + row * AS_STRIDE + wd,
                      h0prev + (bg * 32 + row) * 256 + wd);
            }
        }
        if (doL1) {   // h1[t = k-2], slot k&1
            const unsigned* __restrict__ h1prev = d_h1[k & 1];
            #pragma unroll
            for (int i = tid; i < 2048; i += NT) {
                int row = i >> 6, wd = (i & 63) * 4;
                cpa16(As1 + row * AS_STRIDE + wd,
                      h1prev + (bg * 32 + row) * 256 + wd);
            }
        }
        cpa_commit_wait();
        __syncthreads();

        const int rb = wm * 16 + r4;
        const int cb = wn * 16 + 2 * (lane & 3);

        // ===== layer 0 MMAs: t = k (recurrent K=512) =====
        if (doL0) {
            float acc[2][4] = {};
            const unsigned* bbase = wp0 + (wn * 2) * 64 + lane * 2;
            #pragma unroll 8
            for (int kb = kh * 16; kb < kh * 16 + 16; ++kb) {
                const unsigned* aw = a0base + kb * 8;
                unsigned a0 = aw[0];
                unsigned a1 = aw[8 * AS_STRIDE];
                unsigned a2 = aw[4];
                unsigned a3 = aw[8 * AS_STRIDE + 4];
                const unsigned* bp = bbase + kb * 256;
                uint2 b0 = *(const uint2*)bp;
                uint2 b1 = *(const uint2*)(bp + 64);
                mma16(acc[0], a0, a1, a2, a3, b0.x, b0.y);
                mma16(acc[1], a0, a1, a2, a3, b1.x, b1.y);
            }
            #pragma unroll
            for (int nn = 0; nn < 2; ++nn) {
                red0[rb * 33 + cb + nn * 8]           = acc[nn][0];
                red0[rb * 33 + cb + nn * 8 + 1]       = acc[nn][1];
                red0[(rb + 8) * 33 + cb + nn * 8]     = acc[nn][2];
                red0[(rb + 8) * 33 + cb + nn * 8 + 1] = acc[nn][3];
            }
        }

        // ===== layer 1 MMAs: t = k-1 (kh=0 reads As0=h0[t], kh=1 reads As1=h1[t-1])
        if (doL1) {
            float acc[2][4] = {};
            const unsigned* bbase = wp1 + (wn * 2) * 64 + lane * 2;
            #pragma unroll 8
            for (int kbl = 0; kbl < 32; ++kbl) {
                const unsigned* aw = a1base + kbl * 8;
                unsigned a0 = aw[0];
                unsigned a1 = aw[8 * AS_STRIDE];
                unsigned a2 = aw[4];
                unsigned a3 = aw[8 * AS_STRIDE + 4];
                const unsigned* bp = bbase + (kh * 32 + kbl) * 256;
                uint2 b0 = *(const uint2*)bp;
                uint2 b1 = *(const uint2*)(bp + 64);
                mma16(acc[0], a0, a1, a2, a3, b0.x, b0.y);
                mma16(acc[1], a0, a1, a2, a3, b1.x, b1.y);
            }
            #pragma unroll
            for (int nn = 0; nn < 2; ++nn) {
                red1[rb * 33 + cb + nn * 8]           = acc[nn][0];
                red1[rb * 33 + cb + nn * 8 + 1]       = acc[nn][1];
                red1[(rb + 8) * 33 + cb + nn * 8]     = acc[nn][2];
                red1[(rb + 8) * 33 + cb + nn * 8 + 1] = acc[nn][3];
            }
        }

        __syncthreads();

        // ===== pointwise finishes (both layers, independent) =====
        if (doL0) {
            __half2 zl = *(__half2*)&zraw.x;
            __half2 zh = *(__half2*)&zraw.y;
            int o0 = fb * 33 + fu * 4;
            float zf = red[o0 + 0] + red[1056 + o0 + 0] + __low2float(zl);
            float zi = red[o0 + 1] + red[1056 + o0 + 1] + __high2float(zl);
            float zo = red[o0 + 2] + red[1056 + o0 + 2] + __low2float(zh);
            float zg = red[o0 + 3] + red[1056 + o0 + 3] + __high2float(zh);
            float f  = sigf(zf);
            float ii = sigf(zi);
            float o  = sigf(zo);
            float g  = tanhfast(zg);
            float c  = f * c0 + ii * g;
            c0 = c;
            float hv = o * tanhfast(c);
            ((__half*)d_h0[k & 1])[(bg * 32 + fb) * HID + cg * 8 + fu] =
                __float2half_rn(hv);
        }
        if (doL1) {
            int o1 = 2112 + fb * 33 + fu * 4;
            float zf = red[o1 + 0] + red[1056 + o1 + 0] + bias1[fu * 4 + 0];
            float zi = red[o1 + 1] + red[1056 + o1 + 1] + bias1[fu * 4 + 1];
            float zo = red[o1 + 2] + red[1056 + o1 + 2] + bias1[fu * 4 + 2];
            float zg = red[o1 + 3] + red[1056 + o1 + 3] + bias1[fu * 4 + 3];
            float f  = sigf(zf);
            float ii = sigf(zi);
            float o  = sigf(zo);
            float g  = tanhfast(zg);
            float c  = f * c1 + ii * g;
            c1 = c;
            float hv = o * tanhfast(c);
            ((__half*)d_h1[(k - 1) & 1])[(bg * 32 + fb) * HID + cg * 8 + fu] =
                __float2half_rn(hv);
        }

        bar_arrive(bg);
    }
}

// ---------------- final FC head: 1 block per batch, 512 threads ----------------
__global__ void __launch_bounds__(512) fc_kernel(
    const float* __restrict__ fc1w, const float* __restrict__ fc1b,
    const float* __restrict__ fc2w, const float* __restrict__ fc2b,
    float* __restrict__ out)
{
    __shared__ float hs[HID];
    __shared__ float y1[HID];
    const int b = blockIdx.x;
    const int tid = threadIdx.x;
    const __half* __restrict__ h = (const __half*)d_h1[1] + b * HID;  // t=511
    if (tid < HID) hs[tid] = __half2float(h[tid]);
    __syncthreads();

    // fc1: one thread per output, float4 loads (128 iterations)
    {
        float a = fc1b[tid];
        const float4* wr = (const float4*)(fc1w + tid * HID);
        const float4* hv = (const float4*)hs;
        #pragma unroll 8
        for (int kk = 0; kk < HID / 4; ++kk) {
            float4 wv = wr[kk];
            float4 xv = hv[kk];
            a = fmaf(wv.x, xv.x, a);
            a = fmaf(wv.y, xv.y, a);
            a = fmaf(wv.z, xv.z, a);
            a = fmaf(wv.w, xv.w, a);
        }
        y1[tid] = a;
    }
    __syncthreads();

    // fc2: 8 threads per output (24 outputs -> 192 threads), tree reduce
    if (tid < OUTN * 8) {
        int j = tid >> 3, part = tid & 7;
        const float4* wr = (const float4*)(fc2w + j * HID + part * 64);
        const float4* yv = (const float4*)(y1 + part * 64);
        float a = 0.0f;
        #pragma unroll
        for (int kk = 0; kk < 16; ++kk) {
            float4 wv = wr[kk];
            float4 xv = yv[kk];
            a = fmaf(wv.x, xv.x, a);
            a = fmaf(wv.y, xv.y, a);
            a = fmaf(wv.z, xv.z, a);
            a = fmaf(wv.w, xv.w, a);
        }
        a += __shfl_down_sync(0xffffffffu, a, 4, 8);
        a += __shfl_down_sync(0xffffffffu, a, 2, 8);
        a += __shfl_down_sync(0xffffffffu, a, 1, 8);
        if (part == 0)
            out[b * OUTN + j] = fmaxf(a + fc2b[j], 0.0f);
    }
}

// ---------------- launch ---------------------------------------------------------
extern "C" void kernel_launch(void* const* d_in, const int* in_sizes, int n_in,
                              void* d_out, int out_size)
{
    const float* x    = (const float*)d_in[0];
    const float* wf0  = (const float*)d_in[1];
    const float* bf0  = (const float*)d_in[2];
    const float* wi0  = (const float*)d_in[3];
    const float* bi0  = (const float*)d_in[4];
    const float* wo0  = (const float*)d_in[5];
    const float* bo0  = (const float*)d_in[6];
    const float* wg0  = (const float*)d_in[7];
    const float* bg0  = (const float*)d_in[8];
    const float* wf1  = (const float*)d_in[9];
    const float* bf1  = (const float*)d_in[10];
    const float* wi1  = (const float*)d_in[11];
    const float* bi1  = (const float*)d_in[12];
    const float* wo1  = (const float*)d_in[13];
    const float* bo1  = (const float*)d_in[14];
    const float* wg1  = (const float*)d_in[15];
    const float* bg1  = (const float*)d_in[16];
    const float* fc1w = (const float*)d_in[17];
    const float* fc1b = (const float*)d_in[18];
    const float* fc2w = (const float*)d_in[19];
    const float* fc2b = (const float*)d_in[20];
    float* out = (float*)d_out;

    cudaFuncSetAttribute(scan_kernel,
                         cudaFuncAttributeMaxDynamicSharedMemorySize, SMEM_BYTES);
    cudaFuncSetAttribute(xz_gemm_kernel,
                         cudaFuncAttributeMaxDynamicSharedMemorySize, XG_SMEM_BYTES);

    prep_kernel<<<4096, 256>>>(x, wf0, wi0, wo0, wg0, bf0, bi0, bo0, bg0,
                               wf1, wi1, wo1, wg1, bf1, bi1, bo1, bg1);
    dim3 xzgrid(256, 8);
    xz_gemm_kernel<<<xzgrid, NT, XG_SMEM_BYTES>>>();
    scan_kernel<<<NCTA, NT, SMEM_BYTES>>>();
    fc_kernel<<<BATCH, 512>>>(fc1w, fc1b, fc2w, fc2b, out);
}

// round 8
// speedup vs baseline: 8.1600x; 1.1033x over previous
#include <cuda_runtime.h>
#include <cuda_fp16.h>
#include <math.h>

#define BATCH 64
#define SEQ   512
#define DIN   128
#define HID   512
#define OUTN  24
#define K0    640
#define K1    1024
#define COLS  2048

#define NCTA   128
#define NCTABG 64
#define NT     256

// fp16 weight words (u32 = half2) per column-group (full K packing in d_Wp)
#define WPW_L0 10240               // 40 k16-blocks * 4 n8-blocks * 64 words
#define WPW_L1 16384               // 64 * 4 * 64
#define WPW    (WPW_L0 + WPW_L1)   // 26624 u32 per cg

#define AS_STRIDE 260              // 256 words (512 fp16) + 4 pad
#define AS_WORDS (32 * AS_STRIDE)  // 8320

// red: 2 layers x 2 kh-halves x 32 x 33 floats
#define RED_FLOATS (2 * 2 * 1056)

#define SMEM_U32  (2 * AS_WORDS + RED_FLOATS + 64)
#define SMEM_BYTES (SMEM_U32 * 4)

// xz gemm smem
#define XG_SMEM_U32 (128 * 68 + 16384)
#define XG_SMEM_BYTES (XG_SMEM_U32 * 4)

// ---------------- persistent device state ----------------------------------
__device__ __align__(16) unsigned d_Wp[64 * WPW];
__device__ __align__(16) unsigned d_x16[BATCH * SEQ * (DIN / 2)];
__device__ __align__(16) unsigned d_xz[BATCH * SEQ * (COLS / 2)];  // fp16 x-proj + bias
__device__ float d_b0r[COLS];
__device__ float d_b1r[COLS];
__device__ __align__(16) unsigned d_h0[2][BATCH * (HID / 2)];
__device__ __align__(16) unsigned d_h1[2][BATCH * (HID / 2)];
__device__ unsigned g_bar_count[2] = {0, 0};
__device__ unsigned g_bar_gen[2]   = {0, 0};

__device__ __forceinline__ float sigf(float v) { return 1.0f / (1.0f + __expf(-v)); }
__device__ __forceinline__ float tanhfast(float v) {
    return 1.0f - 2.0f / (__expf(2.0f * v) + 1.0f);
}

__device__ __forceinline__ void mma16(float c[4], unsigned a0, unsigned a1,
                                      unsigned a2, unsigned a3,
                                      unsigned b0, unsigned b1)
{
    asm volatile(
        "mma.sync.aligned.m16n8k16.row.col.f32.f16.f16.f32 "
        "{%0,%1,%2,%3},{%4,%5,%6,%7},{%8,%9},{%0,%1,%2,%3};"
        : "+f"(c[0]), "+f"(c[1]), "+f"(c[2]), "+f"(c[3])
        : "r"(a0), "r"(a1), "r"(a2), "r"(a3), "r"(b0), "r"(b1));
}

__device__ __forceinline__ void ldsm4(unsigned& a0, unsigned& a1,
                                      unsigned& a2, unsigned& a3, unsigned addr)
{
    asm volatile(
        "ldmatrix.sync.aligned.m8n8.x4.shared.b16 {%0,%1,%2,%3}, [%4];"
        : "=r"(a0), "=r"(a1), "=r"(a2), "=r"(a3) : "r"(addr));
}

__device__ __forceinline__ void cpa16(void* dst, const void* src)
{
    unsigned d = (unsigned)__cvta_generic_to_shared(dst);
    asm volatile("cp.async.cg.shared.global [%0], [%1], 16;" :: "r"(d), "l"(src));
}
__device__ __forceinline__ void cpa_commit_wait()
{
    asm volatile("cp.async.commit_group;");
    asm volatile("cp.async.wait_group 0;");
}

// ---------------- prep: weight packing (fp16), x conversion, biases ---------
__global__ void prep_kernel(
    const float* __restrict__ x,
    const float* __restrict__ wf0, const float* __restrict__ wi0,
    const float* __restrict__ wo0, const float* __restrict__ wg0,
    const float* __restrict__ bf0, const float* __restrict__ bi0,
    const float* __restrict__ bo0, const float* __restrict__ bg0,
    const float* __restrict__ wf1, const float* __restrict__ wi1,
    const float* __restrict__ wo1, const float* __restrict__ wg1,
    const float* __restrict__ bf1, const float* __restrict__ bi1,
    const float* __restrict__ bo1, const float* __restrict__ bg1)
{
    const int nW = 64 * WPW;
    const int nX = BATCH * SEQ * (DIN / 2);
    const int ntot = nW + nX + 2 * COLS;
    for (int idx = blockIdx.x * blockDim.x + threadIdx.x; idx < ntot;
         idx += gridDim.x * blockDim.x) {
        if (idx < nW) {
            int cg = idx / WPW;
            int r  = idx % WPW;
            int layer = (r < WPW_L0) ? 0 : 1;
            int rr    = layer ? (r - WPW_L0) : r;
            int kb   = rr >> 8;
            int rem  = rr & 255;
            int nb   = rem >> 6;
            int t    = rem & 63;
            int lane = t >> 1;
            int reg  = t & 1;
            int colloc = nb * 8 + (lane >> 2);
            int unit = cg * 8 + (colloc >> 2);
            int gate = colloc & 3;
            int k    = kb * 16 + (lane & 3) * 2 + reg * 8;
            const float* w;
            int K;
            if (layer == 0) {
                w = (gate == 0) ? wf0 : (gate == 1) ? wi0 : (gate == 2) ? wo0 : wg0;
                K = K0;
            } else {
                w = (gate == 0) ? wf1 : (gate == 1) ? wi1 : (gate == 2) ? wo1 : wg1;
                K = K1;
            }
            __half2 h2 = __floats2half2_rn(w[unit * K + k], w[unit * K + k + 1]);
            d_Wp[idx] = *(unsigned*)&h2;
        } else if (idx < nW + nX) {
            int i = idx - nW;
            __half2 h2 = __floats2half2_rn(x[2 * i], x[2 * i + 1]);
            d_x16[i] = *(unsigned*)&h2;
        } else {
            int col = idx - nW - nX;
            if (col < COLS) {
                int u = col >> 2, g = col & 3;
                const float* bb = (g == 0) ? bf0 : (g == 1) ? bi0 : (g == 2) ? bo0 : bg0;
                d_b0r[col] = bb[u];
            } else {
                col -= COLS;
                int u = col >> 2, g = col & 3;
                const float* bb = (g == 0) ? bf1 : (g == 1) ? bi1 : (g == 2) ? bo1 : bg1;
                d_b1r[col] = bb[u];
            }
        }
    }
}

// ---------------- xz GEMM: xz[b,t,:] = x_t @ Wx0^T + b0 (fp16 out) ----------
__global__ void __launch_bounds__(NT) xz_gemm_kernel()
{
    extern __shared__ unsigned smem_u[];
    unsigned* As = smem_u;                 // [128][68]
    unsigned* Ws = smem_u + 128 * 68;      // 8 cgs * 2048 words

    const int tid  = threadIdx.x;
    const int w    = tid >> 5, lane = tid & 31;
    const int r4   = lane >> 2, kq4 = lane & 3;
    const int row0 = blockIdx.x * 128;
    const int cg0  = blockIdx.y * 8;

    #pragma unroll
    for (int i = tid; i < 2048; i += NT) {
        int row = i >> 4, w4 = (i & 15) * 4;
        cpa16(As + row * 68 + w4, d_x16 + (size_t)(row0 + row) * 64 + w4);
    }
    #pragma unroll
    for (int i = tid; i < 4096; i += NT) {
        int cgL = i >> 9, r = (i & 511) * 4;
        cpa16(Ws + cgL * 2048 + r, d_Wp + (size_t)(cg0 + cgL) * WPW + r);
    }
    cpa_commit_wait();
    __syncthreads();

    float acc[32][4];
    #pragma unroll
    for (int i = 0; i < 32; ++i)
        { acc[i][0] = 0.f; acc[i][1] = 0.f; acc[i][2] = 0.f; acc[i][3] = 0.f; }

    #pragma unroll
    for (int kb = 0; kb < 8; ++kb) {
        const unsigned* ab = As + (w * 16 + r4) * 68 + kb * 8 + kq4;
        unsigned a0 = ab[0];
        unsigned a1 = ab[8 * 68];
        unsigned a2 = ab[4];
        unsigned a3 = ab[8 * 68 + 4];
        #pragma unroll
        for (int j = 0; j < 32; ++j) {          // j = cgL*4 + nb
            const unsigned* bp = Ws + (j >> 2) * 2048 + kb * 256 + (j & 3) * 64 + lane * 2;
            uint2 b = *(const uint2*)bp;
            mma16(acc[j], a0, a1, a2, a3, b.x, b.y);
        }
    }

    #pragma unroll
    for (int j = 0; j < 32; ++j) {
        int col = (cg0 + (j >> 2)) * 32 + (j & 3) * 8 + 2 * (lane & 3);
        float bs0 = d_b0r[col], bs1 = d_b0r[col + 1];
        int mrow = row0 + w * 16 + r4;
        __half2 p0 = __floats2half2_rn(acc[j][0] + bs0, acc[j][1] + bs1);
        __half2 p1 = __floats2half2_rn(acc[j][2] + bs0, acc[j][3] + bs1);
        d_xz[(size_t)mrow * 1024 + (col >> 1)]        = *(unsigned*)&p0;
        d_xz[(size_t)(mrow + 8) * 1024 + (col >> 1)]  = *(unsigned*)&p1;
    }
}

// ---------------- per-bg grid barrier (split, replay-safe relative gen) ------
__device__ __forceinline__ void bar_arrive(int bg)
{
    __syncthreads();
    if (threadIdx.x == 0) {
        __threadfence();
        unsigned prev = atomicAdd(&g_bar_count[bg], 1u);
        if (prev == NCTABG - 1) {
            atomicExch(&g_bar_count[bg], 0u);
            __threadfence();
            atomicAdd(&g_bar_gen[bg], 1u);
        }
    }
}
__device__ __forceinline__ void bar_wait(int bg, unsigned base, unsigned mygen)
{
    if (threadIdx.x == 0) {
        volatile unsigned* genp = &g_bar_gen[bg];
        while ((unsigned)(*genp - base) < mygen) {}
        __threadfence();
    }
    __syncthreads();
}

// ---------------- persistent scan kernel --------------------------------------
__global__ void __launch_bounds__(NT, 1) scan_kernel()
{
    extern __shared__ unsigned smem_u[];
    unsigned* As0   = smem_u;                    // [32][260]  h0[t] (shared L0/L1)
    unsigned* As1   = As0 + AS_WORDS;            // [32][260]  h1[t-1]
    float*    red   = (float*)(As1 + AS_WORDS);  // [2 layers][2 kh][32][33]
    float*    bias1 = red + RED_FLOATS;          // [32]

    const int tid  = threadIdx.x;
    const int cg   = blockIdx.x & 63;
    const int bg   = blockIdx.x >> 6;
    const int w    = tid >> 5, lane = tid & 31;
    const int kh   = w >> 2;
    const int wm   = (w >> 1) & 1;
    const int wn   = w & 1;
    const int r4   = lane >> 2;

    // finish-phase role
    const int fb = tid >> 3, fu = tid & 7;

    // Snapshot barrier generation BEFORE first arrive (replay-safe).
    unsigned bar_base = 0;
    if (tid == 0) bar_base = *(volatile unsigned*)&g_bar_gen[bg];

    // ---- one-time: B fragments -> registers (persistent across the scan) ----
    uint2 B0a[16], B0b[16];     // L0 recurrent: 16 k16 blocks (this kh half)
    uint2 B1a[32], B1b[32];     // L1: 32 k16 blocks (this kh half)
    {
        const unsigned* w0 = d_Wp + (size_t)cg * WPW + 2048
                           + (kh * 16) * 256 + wn * 128 + lane * 2;
        #pragma unroll
        for (int j = 0; j < 16; ++j) {
            B0a[j] = *(const uint2*)(w0 + j * 256);
            B0b[j] = *(const uint2*)(w0 + j * 256 + 64);
        }
        const unsigned* w1 = d_Wp + (size_t)cg * WPW + WPW_L0
                           + (kh * 32) * 256 + wn * 128 + lane * 2;
        #pragma unroll
        for (int j = 0; j < 32; ++j) {
            B1a[j] = *(const uint2*)(w1 + j * 256);
            B1b[j] = *(const uint2*)(w1 + j * 256 + 64);
        }
    }
    if (tid < 32) bias1[tid] = d_b1r[cg * 32 + tid];

    // zero this bg's t=-1 hidden rows
    {
        int idx = cg * NT + tid;    // 0..16383
        if (idx < 8192) d_h0[1][bg * 8192 + idx] = 0u;
        else            d_h1[1][bg * 8192 + (idx - 8192)] = 0u;
    }
    float c0 = 0.0f, c1 = 0.0f;
    bar_arrive(bg);
    unsigned mygen = 1;

    // ldmatrix per-lane addresses (shared space, bytes)
    unsigned smem_base = (unsigned)__cvta_generic_to_shared(smem_u);
    const int lrow = wm * 16 + (lane & 15);
    const int lcol = (lane >> 4) * 4;                 // word offset (k+8 halves)
    const unsigned la0 = smem_base + (unsigned)(lrow * AS_STRIDE + lcol) * 4;
    const unsigned la1 = la0 + (kh ? AS_WORDS * 4 : 0);  // L1 kh=0: As0, kh=1: As1

    float* red0 = red + kh * 1056;          // L0 write target
    float* red1 = red + 2112 + kh * 1056;   // L1 write target

    for (int k = 0; k <= SEQ; ++k) {
        const int doL0 = (k < SEQ);
        const int doL1 = (k >= 1);

        // xz prefetch (no dependency on h) — overlap with barrier propagation
        uint2 zraw;
        if (doL0)
            zraw = *(const uint2*)(d_xz +
                    (size_t)((bg * 32 + fb) * SEQ + k) * 1024 + cg * 16 + fu * 2);

        bar_wait(bg, bar_base, mygen); ++mygen;

        // ===== stage A tiles via cp.async =====
        {   // h0[t = k-1], slot (k+1)&1 — needed by L0 (input) and L1 (kh=0 half)
            const unsigned* __restrict__ h0prev = d_h0[(k + 1) & 1];
            #pragma unroll
            for (int i = tid; i < 2048; i += NT) {
                int row = i >> 6, wd = (i & 63) * 4;
                cpa16(As0 + row * AS_STRIDE + wd,
                      h0prev + (bg * 32 + row) * 256 + wd);
            }
        }
        if (doL1) {   // h1[t = k-2], slot k&1
            const unsigned* __restrict__ h1prev = d_h1[k & 1];
            #pragma unroll
            for (int i = tid; i < 2048; i += NT) {
                int row = i >> 6, wd = (i & 63) * 4;
                cpa16(As1 + row * AS_STRIDE + wd,
                      h1prev + (bg * 32 + row) * 256 + wd);
            }
        }
        cpa_commit_wait();
        __syncthreads();

        const int rb = wm * 16 + r4;
        const int cb = wn * 16 + 2 * (lane & 3);

        // ===== layer 0 MMAs: t = k (recurrent K=512, this kh half) =====
        if (doL0) {
            float acc[2][4] = {};
            #pragma unroll
            for (int j = 0; j < 16; ++j) {
                unsigned a0, a1, a2, a3;
                ldsm4(a0, a1, a2, a3, la0 + (unsigned)(kh * 16 + j) * 32);
                mma16(acc[0], a0, a1, a2, a3, B0a[j].x, B0a[j].y);
                mma16(acc[1], a0, a1, a2, a3, B0b[j].x, B0b[j].y);
            }
            #pragma unroll
            for (int nn = 0; nn < 2; ++nn) {
                red0[rb * 33 + cb + nn * 8]           = acc[nn][0];
                red0[rb * 33 + cb + nn * 8 + 1]       = acc[nn][1];
                red0[(rb + 8) * 33 + cb + nn * 8]     = acc[nn][2];
                red0[(rb + 8) * 33 + cb + nn * 8 + 1] = acc[nn][3];
            }
        }

        // ===== layer 1 MMAs: t = k-1 (kh=0 reads As0=h0[t], kh=1 reads As1) ===
        if (doL1) {
            float acc[2][4] = {};
            #pragma unroll
            for (int j = 0; j < 32; ++j) {
                unsigned a0, a1, a2, a3;
                ldsm4(a0, a1, a2, a3, la1 + (unsigned)j * 32);
                mma16(acc[0], a0, a1, a2, a3, B1a[j].x, B1a[j].y);
                mma16(acc[1], a0, a1, a2, a3, B1b[j].x, B1b[j].y);
            }
            #pragma unroll
            for (int nn = 0; nn < 2; ++nn) {
                red1[rb * 33 + cb + nn * 8]           = acc[nn][0];
                red1[rb * 33 + cb + nn * 8 + 1]       = acc[nn][1];
                red1[(rb + 8) * 33 + cb + nn * 8]     = acc[nn][2];
                red1[(rb + 8) * 33 + cb + nn * 8 + 1] = acc[nn][3];
            }
        }

        __syncthreads();

        // ===== pointwise finishes (both layers, independent) =====
        if (doL0) {
            __half2 zl = *(__half2*)&zraw.x;
            __half2 zh = *(__half2*)&zraw.y;
            int o0 = fb * 33 + fu * 4;
            float zf = red[o0 + 0] + red[1056 + o0 + 0] + __low2float(zl);
            float zi = red[o0 + 1] + red[1056 + o0 + 1] + __high2float(zl);
            float zo = red[o0 + 2] + red[1056 + o0 + 2] + __low2float(zh);
            float zg = red[o0 + 3] + red[1056 + o0 + 3] + __high2float(zh);
            float f  = sigf(zf);
            float ii = sigf(zi);
            float o  = sigf(zo);
            float g  = tanhfast(zg);
            float c  = f * c0 + ii * g;
            c0 = c;
            float hv = o * tanhfast(c);
            ((__half*)d_h0[k & 1])[(bg * 32 + fb) * HID + cg * 8 + fu] =
                __float2half_rn(hv);
        }
        if (doL1) {
            int o1 = 2112 + fb * 33 + fu * 4;
            float zf = red[o1 + 0] + red[1056 + o1 + 0] + bias1[fu * 4 + 0];
            float zi = red[o1 + 1] + red[1056 + o1 + 1] + bias1[fu * 4 + 1];
            float zo = red[o1 + 2] + red[1056 + o1 + 2] + bias1[fu * 4 + 2];
            float zg = red[o1 + 3] + red[1056 + o1 + 3] + bias1[fu * 4 + 3];
            float f  = sigf(zf);
            float ii = sigf(zi);
            float o  = sigf(zo);
            float g  = tanhfast(zg);
            float c  = f * c1 + ii * g;
            c1 = c;
            float hv = o * tanhfast(c);
            ((__half*)d_h1[(k - 1) & 1])[(bg * 32 + fb) * HID + cg * 8 + fu] =
                __float2half_rn(hv);
        }

        bar_arrive(bg);
    }
}

// ---------------- final FC head: 1 block per batch, 512 threads ----------------
__global__ void __launch_bounds__(512) fc_kernel(
    const float* __restrict__ fc1w, const float* __restrict__ fc1b,
    const float* __restrict__ fc2w, const float* __restrict__ fc2b,
    float* __restrict__ out)
{
    __shared__ float hs[HID];
    __shared__ float y1[HID];
    const int b = blockIdx.x;
    const int tid = threadIdx.x;
    const __half* __restrict__ h = (const __half*)d_h1[1] + b * HID;  // t=511
    if (tid < HID) hs[tid] = __half2float(h[tid]);
    __syncthreads();

    // fc1: one thread per output, float4 loads (128 iterations)
    {
        float a = fc1b[tid];
        const float4* wr = (const float4*)(fc1w + tid * HID);
        const float4* hv = (const float4*)hs;
        #pragma unroll 8
        for (int kk = 0; kk < HID / 4; ++kk) {
            float4 wv = wr[kk];
            float4 xv = hv[kk];
            a = fmaf(wv.x, xv.x, a);
            a = fmaf(wv.y, xv.y, a);
            a = fmaf(wv.z, xv.z, a);
            a = fmaf(wv.w, xv.w, a);
        }
        y1[tid] = a;
    }
    __syncthreads();

    // fc2: 8 threads per output (24 outputs -> 192 threads), tree reduce
    if (tid < OUTN * 8) {
        int j = tid >> 3, part = tid & 7;
        const float4* wr = (const float4*)(fc2w + j * HID + part * 64);
        const float4* yv = (const float4*)(y1 + part * 64);
        float a = 0.0f;
        #pragma unroll
        for (int kk = 0; kk < 16; ++kk) {
            float4 wv = wr[kk];
            float4 xv = yv[kk];
            a = fmaf(wv.x, xv.x, a);
            a = fmaf(wv.y, xv.y, a);
            a = fmaf(wv.z, xv.z, a);
            a = fmaf(wv.w, xv.w, a);
        }
        a += __shfl_down_sync(0xffffffffu, a, 4, 8);
        a += __shfl_down_sync(0xffffffffu, a, 2, 8);
        a += __shfl_down_sync(0xffffffffu, a, 1, 8);
        if (part == 0)
            out[b * OUTN + j] = fmaxf(a + fc2b[j], 0.0f);
    }
}

// ---------------- launch ---------------------------------------------------------
extern "C" void kernel_launch(void* const* d_in, const int* in_sizes, int n_in,
                              void* d_out, int out_size)
{
    const float* x    = (const float*)d_in[0];
    const float* wf0  = (const float*)d_in[1];
    const float* bf0  = (const float*)d_in[2];
    const float* wi0  = (const float*)d_in[3];
    const float* bi0  = (const float*)d_in[4];
    const float* wo0  = (const float*)d_in[5];
    const float* bo0  = (const float*)d_in[6];
    const float* wg0  = (const float*)d_in[7];
    const float* bg0  = (const float*)d_in[8];
    const float* wf1  = (const float*)d_in[9];
    const float* bf1  = (const float*)d_in[10];
    const float* wi1  = (const float*)d_in[11];
    const float* bi1  = (const float*)d_in[12];
    const float* wo1  = (const float*)d_in[13];
    const float* bo1  = (const float*)d_in[14];
    const float* wg1  = (const float*)d_in[15];
    const float* bg1  = (const float*)d_in[16];
    const float* fc1w = (const float*)d_in[17];
    const float* fc1b = (const float*)d_in[18];
    const float* fc2w = (const float*)d_in[19];
    const float* fc2b = (const float*)d_in[20];
    float* out = (float*)d_out;

    cudaFuncSetAttribute(scan_kernel,
                         cudaFuncAttributeMaxDynamicSharedMemorySize, SMEM_BYTES);
    cudaFuncSetAttribute(xz_gemm_kernel,
                         cudaFuncAttributeMaxDynamicSharedMemorySize, XG_SMEM_BYTES);

    prep_kernel<<<4096, 256>>>(x, wf0, wi0, wo0, wg0, bf0, bi0, bo0, bg0,
                               wf1, wi1, wo1, wg1, bf1, bi1, bo1, bg1);
    dim3 xzgrid(256, 8);
    xz_gemm_kernel<<<xzgrid, NT, XG_SMEM_BYTES>>>();
    scan_kernel<<<NCTA, NT, SMEM_BYTES>>>();
    fc_kernel<<<BATCH, 512>>>(fc1w, fc1b, fc2w, fc2b, out);
}

// round 9
// speedup vs baseline: 9.9637x; 1.2210x over previous
#include <cuda_runtime.h>
#include <cuda_fp16.h>
#include <math.h>

#define BATCH 64
#define SEQ   512
#define DIN   128
#define HID   512
#define OUTN  24
#define K0    640
#define K1    1024
#define COLS  2048

#define NCTA   128
#define NBG    4
#define NCTABG 32
#define NT     256

// fp16 weight words (u32 = half2) per old-style column-group of 8 units
#define WPW_L0 10240               // 40 k16-blocks * 4 n8-blocks * 64 words
#define WPW_L1 16384               // 64 * 4 * 64
#define WPW    (WPW_L0 + WPW_L1)   // 26624 u32 per cg

#define AS_STRIDE 260              // 256 words (512 fp16) + 4 pad
#define AS_WORDS (16 * AS_STRIDE)  // 4160 (16 rows now)

// red: 2 layers x 2 kh x [16][68] floats
#define RED_PER   1088
#define RED_FLOATS (4 * RED_PER)

#define SMEM_U32  (2 * AS_WORDS + RED_FLOATS + 64 + 16)
#define SMEM_BYTES (SMEM_U32 * 4)

#define XG_SMEM_U32 (128 * 68 + 16384)
#define XG_SMEM_BYTES (XG_SMEM_U32 * 4)

#define FC1_SMEM_BYTES (16384 * 4)   // h as u32 half2 words

// ---------------- persistent device state ----------------------------------
__device__ __align__(16) unsigned d_Wp[64 * WPW];
__device__ __align__(16) unsigned d_x16[BATCH * SEQ * (DIN / 2)];
__device__ __align__(16) unsigned d_xz[BATCH * SEQ * (COLS / 2)];
__device__ float d_b0r[COLS];
__device__ float d_b1r[COLS];
__device__ __align__(16) unsigned d_h0[2][BATCH * (HID / 2)];
__device__ __align__(16) unsigned d_h1[2][BATCH * (HID / 2)];
__device__ float d_y1[BATCH * HID];
__device__ unsigned g_bar_count[NBG * 32];   // padded: one counter per 128B
__device__ unsigned g_bar_gen[NBG * 32];

__device__ __forceinline__ float sigf(float v) { return 1.0f / (1.0f + __expf(-v)); }
__device__ __forceinline__ float tanhfast(float v) {
    return 1.0f - 2.0f / (__expf(2.0f * v) + 1.0f);
}

__device__ __forceinline__ void mma16(float c[4], unsigned a0, unsigned a1,
                                      unsigned a2, unsigned a3,
                                      unsigned b0, unsigned b1)
{
    asm volatile(
        "mma.sync.aligned.m16n8k16.row.col.f32.f16.f16.f32 "
        "{%0,%1,%2,%3},{%4,%5,%6,%7},{%8,%9},{%0,%1,%2,%3};"
        : "+f"(c[0]), "+f"(c[1]), "+f"(c[2]), "+f"(c[3])
        : "r"(a0), "r"(a1), "r"(a2), "r"(a3), "r"(b0), "r"(b1));
}

__device__ __forceinline__ void ldsm4(unsigned& a0, unsigned& a1,
                                      unsigned& a2, unsigned& a3, unsigned addr)
{
    asm volatile(
        "ldmatrix.sync.aligned.m8n8.x4.shared.b16 {%0,%1,%2,%3}, [%4];"
        : "=r"(a0), "=r"(a1), "=r"(a2), "=r"(a3) : "r"(addr));
}

__device__ __forceinline__ void cpa16(void* dst, const void* src)
{
    unsigned d = (unsigned)__cvta_generic_to_shared(dst);
    asm volatile("cp.async.cg.shared.global [%0], [%1], 16;" :: "r"(d), "l"(src));
}
__device__ __forceinline__ void cpa_commit()
{
    asm volatile("cp.async.commit_group;");
}
template<int N>
__device__ __forceinline__ void cpa_wait()
{
    asm volatile("cp.async.wait_group %0;" :: "n"(N));
}

// ---------------- prep: weight packing (fp16), x conversion, biases ---------
__global__ void prep_kernel(
    const float* __restrict__ x,
    const float* __restrict__ wf0, const float* __restrict__ wi0,
    const float* __restrict__ wo0, const float* __restrict__ wg0,
    const float* __restrict__ bf0, const float* __restrict__ bi0,
    const float* __restrict__ bo0, const float* __restrict__ bg0,
    const float* __restrict__ wf1, const float* __restrict__ wi1,
    const float* __restrict__ wo1, const float* __restrict__ wg1,
    const float* __restrict__ bf1, const float* __restrict__ bi1,
    const float* __restrict__ bo1, const float* __restrict__ bg1)
{
    const int nW = 64 * WPW;
    const int nX = BATCH * SEQ * (DIN / 2);
    const int ntot = nW + nX + 2 * COLS;
    for (int idx = blockIdx.x * blockDim.x + threadIdx.x; idx < ntot;
         idx += gridDim.x * blockDim.x) {
        if (idx < nW) {
            int cg = idx / WPW;
            int r  = idx % WPW;
            int layer = (r < WPW_L0) ? 0 : 1;
            int rr    = layer ? (r - WPW_L0) : r;
            int kb   = rr >> 8;
            int rem  = rr & 255;
            int nb   = rem >> 6;
            int t    = rem & 63;
            int lane = t >> 1;
            int reg  = t & 1;
            int colloc = nb * 8 + (lane >> 2);
            int unit = cg * 8 + (colloc >> 2);
            int gate = colloc & 3;
            int k    = kb * 16 + (lane & 3) * 2 + reg * 8;
            const float* w;
            int K;
            if (layer == 0) {
                w = (gate == 0) ? wf0 : (gate == 1) ? wi0 : (gate == 2) ? wo0 : wg0;
                K = K0;
            } else {
                w = (gate == 0) ? wf1 : (gate == 1) ? wi1 : (gate == 2) ? wo1 : wg1;
                K = K1;
            }
            __half2 h2 = __floats2half2_rn(w[unit * K + k], w[unit * K + k + 1]);
            d_Wp[idx] = *(unsigned*)&h2;
        } else if (idx < nW + nX) {
            int i = idx - nW;
            __half2 h2 = __floats2half2_rn(x[2 * i], x[2 * i + 1]);
            d_x16[i] = *(unsigned*)&h2;
        } else {
            int col = idx - nW - nX;
            if (col < COLS) {
                int u = col >> 2, g = col & 3;
                const float* bb = (g == 0) ? bf0 : (g == 1) ? bi0 : (g == 2) ? bo0 : bg0;
                d_b0r[col] = bb[u];
            } else {
                col -= COLS;
                int u = col >> 2, g = col & 3;
                const float* bb = (g == 0) ? bf1 : (g == 1) ? bi1 : (g == 2) ? bo1 : bg1;
                d_b1r[col] = bb[u];
            }
        }
    }
}

// ---------------- xz GEMM: xz[b,t,:] = x_t @ Wx0^T + b0 (fp16 out) ----------
__global__ void __launch_bounds__(NT) xz_gemm_kernel()
{
    extern __shared__ unsigned smem_u[];
    unsigned* As = smem_u;                 // [128][68]
    unsigned* Ws = smem_u + 128 * 68;      // 8 cgs * 2048 words

    const int tid  = threadIdx.x;
    const int w    = tid >> 5, lane = tid & 31;
    const int r4   = lane >> 2, kq4 = lane & 3;
    const int row0 = blockIdx.x * 128;
    const int cg0  = blockIdx.y * 8;

    #pragma unroll
    for (int i = tid; i < 2048; i += NT) {
        int row = i >> 4, w4 = (i & 15) * 4;
        cpa16(As + row * 68 + w4, d_x16 + (size_t)(row0 + row) * 64 + w4);
    }
    #pragma unroll
    for (int i = tid; i < 4096; i += NT) {
        int cgL = i >> 9, r = (i & 511) * 4;
        cpa16(Ws + cgL * 2048 + r, d_Wp + (size_t)(cg0 + cgL) * WPW + r);
    }
    cpa_commit();
    cpa_wait<0>();
    __syncthreads();

    float acc[32][4];
    #pragma unroll
    for (int i = 0; i < 32; ++i)
        { acc[i][0] = 0.f; acc[i][1] = 0.f; acc[i][2] = 0.f; acc[i][3] = 0.f; }

    #pragma unroll
    for (int kb = 0; kb < 8; ++kb) {
        const unsigned* ab = As + (w * 16 + r4) * 68 + kb * 8 + kq4;
        unsigned a0 = ab[0];
        unsigned a1 = ab[8 * 68];
        unsigned a2 = ab[4];
        unsigned a3 = ab[8 * 68 + 4];
        #pragma unroll
        for (int j = 0; j < 32; ++j) {
            const unsigned* bp = Ws + (j >> 2) * 2048 + kb * 256 + (j & 3) * 64 + lane * 2;
            uint2 b = *(const uint2*)bp;
            mma16(acc[j], a0, a1, a2, a3, b.x, b.y);
        }
    }

    #pragma unroll
    for (int j = 0; j < 32; ++j) {
        int col = (cg0 + (j >> 2)) * 32 + (j & 3) * 8 + 2 * (lane & 3);
        float bs0 = d_b0r[col], bs1 = d_b0r[col + 1];
        int mrow = row0 + w * 16 + r4;
        __half2 p0 = __floats2half2_rn(acc[j][0] + bs0, acc[j][1] + bs1);
        __half2 p1 = __floats2half2_rn(acc[j][2] + bs0, acc[j][3] + bs1);
        d_xz[(size_t)mrow * 1024 + (col >> 1)]        = *(unsigned*)&p0;
        d_xz[(size_t)(mrow + 8) * 1024 + (col >> 1)]  = *(unsigned*)&p1;
    }
}

// ---------------- per-bg grid barrier (32 CTAs, padded counters) -------------
__device__ __forceinline__ void bar_arrive(int bg)
{
    __syncthreads();
    if (threadIdx.x == 0) {
        __threadfence();
        unsigned prev = atomicAdd(&g_bar_count[bg * 32], 1u);
        if (prev == NCTABG - 1) {
            atomicExch(&g_bar_count[bg * 32], 0u);
            __threadfence();
            atomicAdd(&g_bar_gen[bg * 32], 1u);
        }
    }
}
__device__ __forceinline__ void bar_wait(int bg, unsigned base, unsigned mygen)
{
    if (threadIdx.x == 0) {
        volatile unsigned* genp = &g_bar_gen[bg * 32];
        while ((unsigned)(*genp - base) < mygen) {}
        __threadfence();
    }
    __syncthreads();
}

// ---------------- persistent scan kernel --------------------------------------
// 128 CTAs = 4 batch-groups (16 batches) x 32 unit-groups (16 units = 64 cols)
__global__ void __launch_bounds__(NT, 1) scan_kernel()
{
    extern __shared__ unsigned smem_u[];
    unsigned* As0   = smem_u;                    // [16][260]  h0[t]
    unsigned* As1   = As0 + AS_WORDS;            // [16][260]  h1[t-1]
    float*    red   = (float*)(As1 + AS_WORDS);  // [2 layers][2 kh][16][68]
    float*    bias1 = red + RED_FLOATS;          // [64]

    const int tid  = threadIdx.x;
    const int cg   = blockIdx.x & 31;            // unit group (16 units)
    const int bg   = blockIdx.x >> 5;            // batch group (16 batches)
    const int w    = tid >> 5, lane = tid & 31;
    const int kh   = w >> 2;                     // K half
    const int wn   = w & 3;                      // n16 block (cols wn*16..)
    const int r4   = lane >> 2;

    // finish-phase role: (row fb, unit fu)
    const int fb = tid >> 4, fu = tid & 15;

    unsigned bar_base = 0;
    if (tid == 0) bar_base = *(volatile unsigned*)&g_bar_gen[bg * 32];

    // ---- one-time: B fragments -> registers ----
    // this warp covers old-cg cgA, n8 blocks nbA and nbA+1
    const int cgA = cg * 2 + (wn >> 1);
    const int nbA = (wn & 1) * 2;
    uint2 B0a[16], B0b[16];
    uint2 B1a[32], B1b[32];
    {
        const unsigned* w0 = d_Wp + (size_t)cgA * WPW + 2048
                           + (kh * 16) * 256 + nbA * 64 + lane * 2;
        #pragma unroll
        for (int j = 0; j < 16; ++j) {
            B0a[j] = *(const uint2*)(w0 + j * 256);
            B0b[j] = *(const uint2*)(w0 + j * 256 + 64);
        }
        const unsigned* w1 = d_Wp + (size_t)cgA * WPW + WPW_L0
                           + (kh * 32) * 256 + nbA * 64 + lane * 2;
        #pragma unroll
        for (int j = 0; j < 32; ++j) {
            B1a[j] = *(const uint2*)(w1 + j * 256);
            B1b[j] = *(const uint2*)(w1 + j * 256 + 64);
        }
    }
    if (tid < 64) bias1[tid] = d_b1r[cg * 64 + tid];

    // zero this bg's t=-1 hidden rows: 32 CTAs x 256 = 8192 slots = 2 x 4096
    {
        int idx = cg * NT + tid;
        if (idx < 4096) d_h0[1][bg * 4096 + idx] = 0u;
        else            d_h1[1][bg * 4096 + (idx - 4096)] = 0u;
    }
    float c0 = 0.0f, c1 = 0.0f;
    bar_arrive(bg);
    unsigned mygen = 1;

    // ldmatrix per-lane addresses
    unsigned smem_base = (unsigned)__cvta_generic_to_shared(smem_u);
    const int lrow = lane & 15;
    const int lcol = (lane >> 4) * 4;
    const unsigned la0 = smem_base + (unsigned)(lrow * AS_STRIDE + lcol) * 4;
    const unsigned la1 = la0 + (kh ? AS_WORDS * 4 : 0);

    float* red0 = red + kh * RED_PER;
    float* red1 = red + 2 * RED_PER + kh * RED_PER;

    for (int k = 0; k <= SEQ; ++k) {
        const int doL0 = (k < SEQ);
        const int doL1 = (k >= 1);

        // xz prefetch (no dependency on h) — overlap with barrier propagation
        uint2 zraw;
        if (doL0)
            zraw = *(const uint2*)(d_xz +
                    (size_t)((bg * 16 + fb) * SEQ + k) * 1024 + cg * 32 + fu * 2);

        bar_wait(bg, bar_base, mygen); ++mygen;

        // ===== stage h0[t=k-1] (group 1), then h1[t=k-2] (group 0) ============
        {
            const unsigned* __restrict__ h0prev = d_h0[(k + 1) & 1];
            #pragma unroll
            for (int i = tid; i < 1024; i += NT) {
                int row = i >> 6, wd = (i & 63) * 4;
                cpa16(As0 + row * AS_STRIDE + wd,
                      h0prev + (bg * 16 + row) * 256 + wd);
            }
        }
        cpa_commit();
        if (doL1) {
            const unsigned* __restrict__ h1prev = d_h1[k & 1];
            #pragma unroll
            for (int i = tid; i < 1024; i += NT) {
                int row = i >> 6, wd = (i & 63) * 4;
                cpa16(As1 + row * AS_STRIDE + wd,
                      h1prev + (bg * 16 + row) * 256 + wd);
            }
        }
        cpa_commit();

        cpa_wait<1>();         // h0 tile ready
        __syncthreads();

        const int rb = r4;
        const int cb = wn * 16 + 2 * (lane & 3);

        // ===== layer 0 MMAs (overlaps in-flight h1 staging) =====
        if (doL0) {
            float acc[2][4] = {};
            #pragma unroll
            for (int j = 0; j < 16; ++j) {
                unsigned a0, a1, a2, a3;
                ldsm4(a0, a1, a2, a3, la0 + (unsigned)(kh * 16 + j) * 32);
                mma16(acc[0], a0, a1, a2, a3, B0a[j].x, B0a[j].y);
                mma16(acc[1], a0, a1, a2, a3, B0b[j].x, B0b[j].y);
            }
            #pragma unroll
            for (int nn = 0; nn < 2; ++nn) {
                red0[rb * 68 + cb + nn * 8]           = acc[nn][0];
                red0[rb * 68 + cb + nn * 8 + 1]       = acc[nn][1];
                red0[(rb + 8) * 68 + cb + nn * 8]     = acc[nn][2];
                red0[(rb + 8) * 68 + cb + nn * 8 + 1] = acc[nn][3];
            }
        }

        cpa_wait<0>();         // h1 tile ready
        __syncthreads();

        // ===== layer 1 MMAs (kh=0 reads As0=h0[t], kh=1 reads As1=h1[t-1]) ===
        if (doL1) {
            float acc[2][4] = {};
            #pragma unroll
            for (int j = 0; j < 32; ++j) {
                unsigned a0, a1, a2, a3;
                ldsm4(a0, a1, a2, a3, la1 + (unsigned)j * 32);
                mma16(acc[0], a0, a1, a2, a3, B1a[j].x, B1a[j].y);
                mma16(acc[1], a0, a1, a2, a3, B1b[j].x, B1b[j].y);
            }
            #pragma unroll
            for (int nn = 0; nn < 2; ++nn) {
                red1[rb * 68 + cb + nn * 8]           = acc[nn][0];
                red1[rb * 68 + cb + nn * 8 + 1]       = acc[nn][1];
                red1[(rb + 8) * 68 + cb + nn * 8]     = acc[nn][2];
                red1[(rb + 8) * 68 + cb + nn * 8 + 1] = acc[nn][3];
            }
        }

        __syncthreads();

        // ===== pointwise finishes =====
        if (doL0) {
            __half2 zl = *(__half2*)&zraw.x;
            __half2 zh = *(__half2*)&zraw.y;
            int o0 = fb * 68 + fu * 4;
            float zf = red[o0 + 0] + red[RED_PER + o0 + 0] + __low2float(zl);
            float zi = red[o0 + 1] + red[RED_PER + o0 + 1] + __high2float(zl);
            float zo = red[o0 + 2] + red[RED_PER + o0 + 2] + __low2float(zh);
            float zg = red[o0 + 3] + red[RED_PER + o0 + 3] + __high2float(zh);
            float f  = sigf(zf);
            float ii = sigf(zi);
            float o  = sigf(zo);
            float g  = tanhfast(zg);
            float c  = f * c0 + ii * g;
            c0 = c;
            float hv = o * tanhfast(c);
            ((__half*)d_h0[k & 1])[(bg * 16 + fb) * HID + cg * 16 + fu] =
                __float2half_rn(hv);
        }
        if (doL1) {
            int o1 = 2 * RED_PER + fb * 68 + fu * 4;
            float zf = red[o1 + 0] + red[RED_PER + o1 + 0] + bias1[fu * 4 + 0];
            float zi = red[o1 + 1] + red[RED_PER + o1 + 1] + bias1[fu * 4 + 1];
            float zo = red[o1 + 2] + red[RED_PER + o1 + 2] + bias1[fu * 4 + 2];
            float zg = red[o1 + 3] + red[RED_PER + o1 + 3] + bias1[fu * 4 + 3];
            float f  = sigf(zf);
            float ii = sigf(zi);
            float o  = sigf(zo);
            float g  = tanhfast(zg);
            float c  = f * c1 + ii * g;
            c1 = c;
            float hv = o * tanhfast(c);
            ((__half*)d_h1[(k - 1) & 1])[(bg * 16 + fb) * HID + cg * 16 + fu] =
                __float2half_rn(hv);
        }

        bar_arrive(bg);
    }
}

// ---------------- fc1 as tiled GEMM: y1[64,512] = h @ fc1w^T + b ---------------
// grid 16 (32 cols each), block 256: warp = 8 batches, lane = col.
__global__ void __launch_bounds__(256) fc1_kernel(
    const float* __restrict__ fc1w, const float* __restrict__ fc1b)
{
    extern __shared__ unsigned hsm[];   // [64][256] h as half2 words
    const int tid = threadIdx.x;
    #pragma unroll
    for (int i = tid; i < 16384; i += 256) hsm[i] = d_h1[1][i];
    __syncthreads();

    const int j  = blockIdx.x * 32 + (tid & 31);
    const int b0 = (tid >> 5) * 8;
    float acc[8] = {0.f, 0.f, 0.f, 0.f, 0.f, 0.f, 0.f, 0.f};
    const float4* wr = (const float4*)(fc1w + (size_t)j * HID);
    #pragma unroll 4
    for (int k4 = 0; k4 < 128; ++k4) {
        float4 wv = wr[k4];
        #pragma unroll
        for (int b = 0; b < 8; ++b) {
            uint2 hp = *(const uint2*)(hsm + (b0 + b) * 256 + k4 * 2);
            float2 f0 = __half22float2(*(__half2*)&hp.x);
            float2 f1 = __half22float2(*(__half2*)&hp.y);
            acc[b] = fmaf(wv.x, f0.x, acc[b]);
            acc[b] = fmaf(wv.y, f0.y, acc[b]);
            acc[b] = fmaf(wv.z, f1.x, acc[b]);
            acc[b] = fmaf(wv.w, f1.y, acc[b]);
        }
    }
    float bj = fc1b[j];
    #pragma unroll
    for (int b = 0; b < 8; ++b)
        d_y1[(size_t)(b0 + b) * HID + j] = acc[b] + bj;
}

// ---------------- fc2 + relu: out[64,24] -----------------------------------------
__global__ void __launch_bounds__(192) fc2_kernel(
    const float* __restrict__ fc2w, const float* __restrict__ fc2b,
    float* __restrict__ out)
{
    __shared__ float ys[HID];
    const int b = blockIdx.x;
    const int tid = threadIdx.x;
    for (int i = tid; i < HID; i += 192) ys[i] = d_y1[(size_t)b * HID + i];
    __syncthreads();
    int j = tid >> 3, part = tid & 7;
    const float4* wr = (const float4*)(fc2w + (size_t)j * HID + part * 64);
    const float4* yv = (const float4*)(ys + part * 64);
    float a = 0.0f;
    #pragma unroll
    for (int kk = 0; kk < 16; ++kk) {
        float4 wv = wr[kk];
        float4 xv = yv[kk];
        a = fmaf(wv.x, xv.x, a);
        a = fmaf(wv.y, xv.y, a);
        a = fmaf(wv.z, xv.z, a);
        a = fmaf(wv.w, xv.w, a);
    }
    a += __shfl_down_sync(0xffffffffu, a, 4, 8);
    a += __shfl_down_sync(0xffffffffu, a, 2, 8);
    a += __shfl_down_sync(0xffffffffu, a, 1, 8);
    if (part == 0)
        out[b * OUTN + j] = fmaxf(a + fc2b[j], 0.0f);
}

// ---------------- launch ---------------------------------------------------------
extern "C" void kernel_launch(void* const* d_in, const int* in_sizes, int n_in,
                              void* d_out, int out_size)
{
    const float* x    = (const float*)d_in[0];
    const float* wf0  = (const float*)d_in[1];
    const float* bf0  = (const float*)d_in[2];
    const float* wi0  = (const float*)d_in[3];
    const float* bi0  = (const float*)d_in[4];
    const float* wo0  = (const float*)d_in[5];
    const float* bo0  = (const float*)d_in[6];
    const float* wg0  = (const float*)d_in[7];
    const float* bg0  = (const float*)d_in[8];
    const float* wf1  = (const float*)d_in[9];
    const float* bf1  = (const float*)d_in[10];
    const float* wi1  = (const float*)d_in[11];
    const float* bi1  = (const float*)d_in[12];
    const float* wo1  = (const float*)d_in[13];
    const float* bo1  = (const float*)d_in[14];
    const float* wg1  = (const float*)d_in[15];
    const float* bg1  = (const float*)d_in[16];
    const float* fc1w = (const float*)d_in[17];
    const float* fc1b = (const float*)d_in[18];
    const float* fc2w = (const float*)d_in[19];
    const float* fc2b = (const float*)d_in[20];
    float* out = (float*)d_out;

    cudaFuncSetAttribute(scan_kernel,
                         cudaFuncAttributeMaxDynamicSharedMemorySize, SMEM_BYTES);
    cudaFuncSetAttribute(xz_gemm_kernel,
                         cudaFuncAttributeMaxDynamicSharedMemorySize, XG_SMEM_BYTES);
    cudaFuncSetAttribute(fc1_kernel,
                         cudaFuncAttributeMaxDynamicSharedMemorySize, FC1_SMEM_BYTES);

    prep_kernel<<<4096, 256>>>(x, wf0, wi0, wo0, wg0, bf0, bi0, bo0, bg0,
                               wf1, wi1, wo1, wg1, bf1, bi1, bo1, bg1);
    dim3 xzgrid(256, 8);
    xz_gemm_kernel<<<xzgrid, NT, XG_SMEM_BYTES>>>();
    scan_kernel<<<NCTA, NT, SMEM_BYTES>>>();
    fc1_kernel<<<16, 256, FC1_SMEM_BYTES>>>(fc1w, fc1b);
    fc2_kernel<<<BATCH, 192>>>(fc2w, fc2b, out);
}

// round 10
// speedup vs baseline: 10.1719x; 1.0209x over previous
#include <cuda_runtime.h>
#include <cuda_fp16.h>
#include <math.h>

#define BATCH 64
#define SEQ   512
#define DIN   128
#define HID   512
#define OUTN  24
#define K0    640
#define K1    1024
#define COLS  2048

#define NCTA   128
#define NBG    4
#define NCTABG 32
#define NT     256

// fp16 weight words (u32 = half2) per old-style column-group of 8 units
#define WPW_L0 10240               // 40 k16-blocks * 4 n8-blocks * 64 words
#define WPW_L1 16384               // 64 * 4 * 64
#define WPW    (WPW_L0 + WPW_L1)   // 26624 u32 per cg

#define AS_STRIDE 260              // 256 words (512 fp16) + 4 pad
#define AS_WORDS (16 * AS_STRIDE)  // 4160

// red: 2 layers x 4 kq x [16][68] floats
#define RED_PER   1088
#define RED_FLOATS (8 * RED_PER)

#define SMEM_U32  (2 * AS_WORDS + RED_FLOATS + 64 + 16)
#define SMEM_BYTES (SMEM_U32 * 4)

#define XG_SMEM_U32 (128 * 68 + 16384)
#define XG_SMEM_BYTES (XG_SMEM_U32 * 4)

#define FC1_SMEM_BYTES (4096 * 4)    // 16 batches of h as half2 words

// ---------------- persistent device state ----------------------------------
__device__ __align__(16) unsigned d_Wp[64 * WPW];
__device__ __align__(16) unsigned d_x16[BATCH * SEQ * (DIN / 2)];
__device__ __align__(16) unsigned d_xz[BATCH * SEQ * (COLS / 2)];
__device__ float d_b0r[COLS];
__device__ float d_b1r[COLS];
__device__ __align__(16) unsigned d_h0[2][BATCH * (HID / 2)];
__device__ __align__(16) unsigned d_h1[2][BATCH * (HID / 2)];
__device__ float d_y1[BATCH * HID];
__device__ unsigned g_bar_count[NBG * 32];
__device__ unsigned g_bar_gen[NBG * 32];

__device__ __forceinline__ float sigf(float v) { return 1.0f / (1.0f + __expf(-v)); }
__device__ __forceinline__ float tanha(float v) {
    float r; asm("tanh.approx.f32 %0, %1;" : "=f"(r) : "f"(v)); return r;
}

__device__ __forceinline__ void mma16(float c[4], unsigned a0, unsigned a1,
                                      unsigned a2, unsigned a3,
                                      unsigned b0, unsigned b1)
{
    asm volatile(
        "mma.sync.aligned.m16n8k16.row.col.f32.f16.f16.f32 "
        "{%0,%1,%2,%3},{%4,%5,%6,%7},{%8,%9},{%0,%1,%2,%3};"
        : "+f"(c[0]), "+f"(c[1]), "+f"(c[2]), "+f"(c[3])
        : "r"(a0), "r"(a1), "r"(a2), "r"(a3), "r"(b0), "r"(b1));
}

__device__ __forceinline__ void ldsm4(unsigned& a0, unsigned& a1,
                                      unsigned& a2, unsigned& a3, unsigned addr)
{
    asm volatile(
        "ldmatrix.sync.aligned.m8n8.x4.shared.b16 {%0,%1,%2,%3}, [%4];"
        : "=r"(a0), "=r"(a1), "=r"(a2), "=r"(a3) : "r"(addr));
}

__device__ __forceinline__ void cpa16(void* dst, const void* src)
{
    unsigned d = (unsigned)__cvta_generic_to_shared(dst);
    asm volatile("cp.async.cg.shared.global [%0], [%1], 16;" :: "r"(d), "l"(src));
}
__device__ __forceinline__ void cpa_commit()
{
    asm volatile("cp.async.commit_group;");
}
template<int N>
__device__ __forceinline__ void cpa_wait()
{
    asm volatile("cp.async.wait_group %0;" :: "n"(N));
}

// ---------------- prep: weight packing (fp16), x conversion, biases ---------
__global__ void prep_kernel(
    const float* __restrict__ x,
    const float* __restrict__ wf0, const float* __restrict__ wi0,
    const float* __restrict__ wo0, const float* __restrict__ wg0,
    const float* __restrict__ bf0, const float* __restrict__ bi0,
    const float* __restrict__ bo0, const float* __restrict__ bg0,
    const float* __restrict__ wf1, const float* __restrict__ wi1,
    const float* __restrict__ wo1, const float* __restrict__ wg1,
    const float* __restrict__ bf1, const float* __restrict__ bi1,
    const float* __restrict__ bo1, const float* __restrict__ bg1)
{
    const int nW = 64 * WPW;
    const int nX = BATCH * SEQ * (DIN / 2);
    const int ntot = nW + nX + 2 * COLS;
    for (int idx = blockIdx.x * blockDim.x + threadIdx.x; idx < ntot;
         idx += gridDim.x * blockDim.x) {
        if (idx < nW) {
            int cg = idx / WPW;
            int r  = idx % WPW;
            int layer = (r < WPW_L0) ? 0 : 1;
            int rr    = layer ? (r - WPW_L0) : r;
            int kb   = rr >> 8;
            int rem  = rr & 255;
            int nb   = rem >> 6;
            int t    = rem & 63;
            int lane = t >> 1;
            int reg  = t & 1;
            int colloc = nb * 8 + (lane >> 2);
            int unit = cg * 8 + (colloc >> 2);
            int gate = colloc & 3;
            int k    = kb * 16 + (lane & 3) * 2 + reg * 8;
            const float* w;
            int K;
            if (layer == 0) {
                w = (gate == 0) ? wf0 : (gate == 1) ? wi0 : (gate == 2) ? wo0 : wg0;
                K = K0;
            } else {
                w = (gate == 0) ? wf1 : (gate == 1) ? wi1 : (gate == 2) ? wo1 : wg1;
                K = K1;
            }
            __half2 h2 = __floats2half2_rn(w[unit * K + k], w[unit * K + k + 1]);
            d_Wp[idx] = *(unsigned*)&h2;
        } else if (idx < nW + nX) {
            int i = idx - nW;
            __half2 h2 = __floats2half2_rn(x[2 * i], x[2 * i + 1]);
            d_x16[i] = *(unsigned*)&h2;
        } else {
            int col = idx - nW - nX;
            if (col < COLS) {
                int u = col >> 2, g = col & 3;
                const float* bb = (g == 0) ? bf0 : (g == 1) ? bi0 : (g == 2) ? bo0 : bg0;
                d_b0r[col] = bb[u];
            } else {
                col -= COLS;
                int u = col >> 2, g = col & 3;
                const float* bb = (g == 0) ? bf1 : (g == 1) ? bi1 : (g == 2) ? bo1 : bg1;
                d_b1r[col] = bb[u];
            }
        }
    }
}

// ---------------- xz GEMM: xz[b,t,:] = x_t @ Wx0^T + b0 (fp16 out) ----------
__global__ void __launch_bounds__(NT) xz_gemm_kernel()
{
    extern __shared__ unsigned smem_u[];
    unsigned* As = smem_u;                 // [128][68]
    unsigned* Ws = smem_u + 128 * 68;      // 8 cgs * 2048 words

    const int tid  = threadIdx.x;
    const int w    = tid >> 5, lane = tid & 31;
    const int r4   = lane >> 2, kq4 = lane & 3;
    const int row0 = blockIdx.x * 128;
    const int cg0  = blockIdx.y * 8;

    #pragma unroll
    for (int i = tid; i < 2048; i += NT) {
        int row = i >> 4, w4 = (i & 15) * 4;
        cpa16(As + row * 68 + w4, d_x16 + (size_t)(row0 + row) * 64 + w4);
    }
    #pragma unroll
    for (int i = tid; i < 4096; i += NT) {
        int cgL = i >> 9, r = (i & 511) * 4;
        cpa16(Ws + cgL * 2048 + r, d_Wp + (size_t)(cg0 + cgL) * WPW + r);
    }
    cpa_commit();
    cpa_wait<0>();
    __syncthreads();

    float acc[32][4];
    #pragma unroll
    for (int i = 0; i < 32; ++i)
        { acc[i][0] = 0.f; acc[i][1] = 0.f; acc[i][2] = 0.f; acc[i][3] = 0.f; }

    #pragma unroll
    for (int kb = 0; kb < 8; ++kb) {
        const unsigned* ab = As + (w * 16 + r4) * 68 + kb * 8 + kq4;
        unsigned a0 = ab[0];
        unsigned a1 = ab[8 * 68];
        unsigned a2 = ab[4];
        unsigned a3 = ab[8 * 68 + 4];
        #pragma unroll
        for (int j = 0; j < 32; ++j) {
            const unsigned* bp = Ws + (j >> 2) * 2048 + kb * 256 + (j & 3) * 64 + lane * 2;
            uint2 b = *(const uint2*)bp;
            mma16(acc[j], a0, a1, a2, a3, b.x, b.y);
        }
    }

    #pragma unroll
    for (int j = 0; j < 32; ++j) {
        int col = (cg0 + (j >> 2)) * 32 + (j & 3) * 8 + 2 * (lane & 3);
        float bs0 = d_b0r[col], bs1 = d_b0r[col + 1];
        int mrow = row0 + w * 16 + r4;
        __half2 p0 = __floats2half2_rn(acc[j][0] + bs0, acc[j][1] + bs1);
        __half2 p1 = __floats2half2_rn(acc[j][2] + bs0, acc[j][3] + bs1);
        d_xz[(size_t)mrow * 1024 + (col >> 1)]        = *(unsigned*)&p0;
        d_xz[(size_t)(mrow + 8) * 1024 + (col >> 1)]  = *(unsigned*)&p1;
    }
}

// ---------------- per-bg grid barrier (32 CTAs, padded counters) -------------
__device__ __forceinline__ void bar_arrive(int bg)
{
    __syncthreads();
    if (threadIdx.x == 0) {
        __threadfence();
        unsigned prev = atomicAdd(&g_bar_count[bg * 32], 1u);
        if (prev == NCTABG - 1) {
            atomicExch(&g_bar_count[bg * 32], 0u);
            __threadfence();
            atomicAdd(&g_bar_gen[bg * 32], 1u);
        }
    }
}
__device__ __forceinline__ void bar_wait(int bg, unsigned base, unsigned mygen)
{
    if (threadIdx.x == 0) {
        volatile unsigned* genp = &g_bar_gen[bg * 32];
        while ((unsigned)(*genp - base) < mygen) {}
        __threadfence();
    }
    __syncthreads();
}

// ---------------- persistent scan kernel --------------------------------------
// 128 CTAs = 4 batch-groups (16 batches) x 32 unit-groups (16 units = 64 cols)
// warps: 4 K-quarters (kq) x 2 col-halves (wn, 32 cols = 4 n8 blocks)
__global__ void __launch_bounds__(NT, 1) scan_kernel()
{
    extern __shared__ unsigned smem_u[];
    unsigned* As0   = smem_u;                    // [16][260]  h0[t]
    unsigned* As1   = As0 + AS_WORDS;            // [16][260]  h1[t-1]
    float*    red   = (float*)(As1 + AS_WORDS);  // [2 layers][4 kq][16][68]
    float*    bias1 = red + RED_FLOATS;          // [64]

    const int tid  = threadIdx.x;
    const int cg   = blockIdx.x & 31;
    const int bg   = blockIdx.x >> 5;
    const int w    = tid >> 5, lane = tid & 31;
    const int wn   = w & 1;                      // col half (32 cols)
    const int kq   = w >> 1;                     // K quarter
    const int r4   = lane >> 2;

    const int fb = tid >> 4, fu = tid & 15;

    unsigned bar_base = 0;
    if (tid == 0) bar_base = *(volatile unsigned*)&g_bar_gen[bg * 32];

    // ---- one-time: B fragments -> registers ----
    // warp covers old-cg cgA = cg*2 + wn, all 4 n8 blocks, K-quarter kq
    const int cgA = cg * 2 + wn;
    uint2 B0[8][4];      // L0 recurrent: 8 k16 blocks x 4 n8
    uint2 B1[16][4];     // L1: 16 k16 blocks x 4 n8
    {
        const unsigned* w0 = d_Wp + (size_t)cgA * WPW + 2048
                           + (kq * 8) * 256 + lane * 2;
        #pragma unroll
        for (int j = 0; j < 8; ++j)
            #pragma unroll
            for (int n = 0; n < 4; ++n)
                B0[j][n] = *(const uint2*)(w0 + j * 256 + n * 64);
        const unsigned* w1 = d_Wp + (size_t)cgA * WPW + WPW_L0
                           + (kq * 16) * 256 + lane * 2;
        #pragma unroll
        for (int j = 0; j < 16; ++j)
            #pragma unroll
            for (int n = 0; n < 4; ++n)
                B1[j][n] = *(const uint2*)(w1 + j * 256 + n * 64);
    }
    if (tid < 64) bias1[tid] = d_b1r[cg * 64 + tid];

    // zero this bg's t=-1 hidden rows
    {
        int idx = cg * NT + tid;
        if (idx < 4096) d_h0[1][bg * 4096 + idx] = 0u;
        else            d_h1[1][bg * 4096 + (idx - 4096)] = 0u;
    }
    float c0 = 0.0f, c1 = 0.0f;
    bar_arrive(bg);
    unsigned mygen = 1;

    // ldmatrix per-lane addresses
    unsigned smem_base = (unsigned)__cvta_generic_to_shared(smem_u);
    const int lrow = lane & 15;
    const int lcol = (lane >> 4) * 4;
    const unsigned la0 = smem_base + (unsigned)(lrow * AS_STRIDE + lcol) * 4;
    // L1: quarters 0,1 -> As0 blocks [16kq,16kq+16); quarters 2,3 -> As1
    const unsigned la1 = (kq < 2 ? la0 : la0 + AS_WORDS * 4)
                       + (unsigned)((kq & 1) * 16) * 32;

    float* red0 = red + kq * RED_PER;
    float* red1 = red + 4 * RED_PER + kq * RED_PER;

    for (int k = 0; k <= SEQ; ++k) {
        const int doL0 = (k < SEQ);
        const int doL1 = (k >= 1);

        // xz prefetch (no dependency on h) — overlap with barrier propagation
        uint2 zraw;
        if (doL0)
            zraw = *(const uint2*)(d_xz +
                    (size_t)((bg * 16 + fb) * SEQ + k) * 1024 + cg * 32 + fu * 2);

        bar_wait(bg, bar_base, mygen); ++mygen;

        // ===== stage h0[t=k-1] (group 1), then h1[t=k-2] (group 0) ============
        {
            const unsigned* __restrict__ h0prev = d_h0[(k + 1) & 1];
            #pragma unroll
            for (int i = tid; i < 1024; i += NT) {
                int row = i >> 6, wd = (i & 63) * 4;
                cpa16(As0 + row * AS_STRIDE + wd,
                      h0prev + (bg * 16 + row) * 256 + wd);
            }
        }
        cpa_commit();
        if (doL1) {
            const unsigned* __restrict__ h1prev = d_h1[k & 1];
            #pragma unroll
            for (int i = tid; i < 1024; i += NT) {
                int row = i >> 6, wd = (i & 63) * 4;
                cpa16(As1 + row * AS_STRIDE + wd,
                      h1prev + (bg * 16 + row) * 256 + wd);
            }
        }
        cpa_commit();

        cpa_wait<1>();         // h0 tile ready
        __syncthreads();

        const int cbb = 2 * (lane & 3);

        // ===== layer 0 MMAs (overlaps in-flight h1 staging) =====
        if (doL0) {
            float acc[4][4] = {};
            #pragma unroll
            for (int j = 0; j < 8; ++j) {
                unsigned a0, a1, a2, a3;
                ldsm4(a0, a1, a2, a3, la0 + (unsigned)(kq * 8 + j) * 32);
                #pragma unroll
                for (int n = 0; n < 4; ++n)
                    mma16(acc[n], a0, a1, a2, a3, B0[j][n].x, B0[j][n].y);
            }
            #pragma unroll
            for (int n = 0; n < 4; ++n) {
                int cb = wn * 32 + n * 8 + cbb;
                *(float2*)&red0[r4 * 68 + cb]       = make_float2(acc[n][0], acc[n][1]);
                *(float2*)&red0[(r4 + 8) * 68 + cb] = make_float2(acc[n][2], acc[n][3]);
            }
        }

        cpa_wait<0>();         // h1 tile ready
        __syncthreads();

        // ===== layer 1 MMAs =====
        if (doL1) {
            float acc[4][4] = {};
            #pragma unroll
            for (int j = 0; j < 16; ++j) {
                unsigned a0, a1, a2, a3;
                ldsm4(a0, a1, a2, a3, la1 + (unsigned)j * 32);
                #pragma unroll
                for (int n = 0; n < 4; ++n)
                    mma16(acc[n], a0, a1, a2, a3, B1[j][n].x, B1[j][n].y);
            }
            #pragma unroll
            for (int n = 0; n < 4; ++n) {
                int cb = wn * 32 + n * 8 + cbb;
                *(float2*)&red1[r4 * 68 + cb]       = make_float2(acc[n][0], acc[n][1]);
                *(float2*)&red1[(r4 + 8) * 68 + cb] = make_float2(acc[n][2], acc[n][3]);
            }
        }

        __syncthreads();

        // ===== pointwise finishes =====
        const int o = fb * 68 + fu * 4;
        if (doL0) {
            float4 q0 = *(const float4*)&red[0 * RED_PER + o];
            float4 q1 = *(const float4*)&red[1 * RED_PER + o];
            float4 q2 = *(const float4*)&red[2 * RED_PER + o];
            float4 q3 = *(const float4*)&red[3 * RED_PER + o];
            __half2 zl = *(__half2*)&zraw.x;
            __half2 zh = *(__half2*)&zraw.y;
            float zf = q0.x + q1.x + q2.x + q3.x + __low2float(zl);
            float zi = q0.y + q1.y + q2.y + q3.y + __high2float(zl);
            float zo = q0.z + q1.z + q2.z + q3.z + __low2float(zh);
            float zg = q0.w + q1.w + q2.w + q3.w + __high2float(zh);
            float f  = sigf(zf);
            float ii = sigf(zi);
            float oo = sigf(zo);
            float g  = tanha(zg);
            float c  = f * c0 + ii * g;
            c0 = c;
            float hv = oo * tanha(c);
            ((__half*)d_h0[k & 1])[(bg * 16 + fb) * HID + cg * 16 + fu] =
                __float2half_rn(hv);
        }
        if (doL1) {
            float4 q0 = *(const float4*)&red[4 * RED_PER + o];
            float4 q1 = *(const float4*)&red[5 * RED_PER + o];
            float4 q2 = *(const float4*)&red[6 * RED_PER + o];
            float4 q3 = *(const float4*)&red[7 * RED_PER + o];
            float zf = q0.x + q1.x + q2.x + q3.x + bias1[fu * 4 + 0];
            float zi = q0.y + q1.y + q2.y + q3.y + bias1[fu * 4 + 1];
            float zo = q0.z + q1.z + q2.z + q3.z + bias1[fu * 4 + 2];
            float zg = q0.w + q1.w + q2.w + q3.w + bias1[fu * 4 + 3];
            float f  = sigf(zf);
            float ii = sigf(zi);
            float oo = sigf(zo);
            float g  = tanha(zg);
            float c  = f * c1 + ii * g;
            c1 = c;
            float hv = oo * tanha(c);
            ((__half*)d_h1[(k - 1) & 1])[(bg * 16 + fb) * HID + cg * 16 + fu] =
                __float2half_rn(hv);
        }

        bar_arrive(bg);
    }
}

// ---------------- fc1: grid (16 colblocks, 4 batchgroups), block 256 -----------
__global__ void __launch_bounds__(256) fc1_kernel(
    const float* __restrict__ fc1w, const float* __restrict__ fc1b)
{
    extern __shared__ unsigned hsm[];   // [16][256] h as half2 words
    const int tid = threadIdx.x;
    const int bgrp = blockIdx.y;
    #pragma unroll
    for (int i = tid; i < 4096; i += 256)
        hsm[i] = d_h1[1][(bgrp * 16) * 256 + i];
    __syncthreads();

    const int j  = blockIdx.x * 32 + (tid & 31);
    const int wid = tid >> 5;            // 0..7 -> 2 batches each
    float acc0 = 0.f, acc1 = 0.f;
    const float4* wr = (const float4*)(fc1w + (size_t)j * HID);
    const unsigned* h0p = hsm + (wid * 2) * 256;
    const unsigned* h1p = hsm + (wid * 2 + 1) * 256;
    #pragma unroll 4
    for (int k4 = 0; k4 < 128; ++k4) {
        float4 wv = wr[k4];
        uint2 hpa = *(const uint2*)(h0p + k4 * 2);
        uint2 hpb = *(const uint2*)(h1p + k4 * 2);
        float2 a0 = __half22float2(*(__half2*)&hpa.x);
        float2 a1 = __half22float2(*(__half2*)&hpa.y);
        float2 b0 = __half22float2(*(__half2*)&hpb.x);
        float2 b1 = __half22float2(*(__half2*)&hpb.y);
        acc0 = fmaf(wv.x, a0.x, acc0); acc0 = fmaf(wv.y, a0.y, acc0);
        acc0 = fmaf(wv.z, a1.x, acc0); acc0 = fmaf(wv.w, a1.y, acc0);
        acc1 = fmaf(wv.x, b0.x, acc1); acc1 = fmaf(wv.y, b0.y, acc1);
        acc1 = fmaf(wv.z, b1.x, acc1); acc1 = fmaf(wv.w, b1.y, acc1);
    }
    float bj = fc1b[j];
    d_y1[(size_t)(bgrp * 16 + wid * 2)     * HID + j] = acc0 + bj;
    d_y1[(size_t)(bgrp * 16 + wid * 2 + 1) * HID + j] = acc1 + bj;
}

// ---------------- fc2 + relu: out[64,24] -----------------------------------------
__global__ void __launch_bounds__(192) fc2_kernel(
    const float* __restrict__ fc2w, const float* __restrict__ fc2b,
    float* __restrict__ out)
{
    __shared__ float ys[HID];
    const int b = blockIdx.x;
    const int tid = threadIdx.x;
    for (int i = tid; i < HID; i += 192) ys[i] = d_y1[(size_t)b * HID + i];
    __syncthreads();
    int j = tid >> 3, part = tid & 7;
    const float4* wr = (const float4*)(fc2w + (size_t)j * HID + part * 64);
    const float4* yv = (const float4*)(ys + part * 64);
    float a = 0.0f;
    #pragma unroll
    for (int kk = 0; kk < 16; ++kk) {
        float4 wv = wr[kk];
        float4 xv = yv[kk];
        a = fmaf(wv.x, xv.x, a);
        a = fmaf(wv.y, xv.y, a);
        a = fmaf(wv.z, xv.z, a);
        a = fmaf(wv.w, xv.w, a);
    }
    a += __shfl_down_sync(0xffffffffu, a, 4, 8);
    a += __shfl_down_sync(0xffffffffu, a, 2, 8);
    a += __shfl_down_sync(0xffffffffu, a, 1, 8);
    if (part == 0)
        out[b * OUTN + j] = fmaxf(a + fc2b[j], 0.0f);
}

// ---------------- launch ---------------------------------------------------------
extern "C" void kernel_launch(void* const* d_in, const int* in_sizes, int n_in,
                              void* d_out, int out_size)
{
    const float* x    = (const float*)d_in[0];
    const float* wf0  = (const float*)d_in[1];
    const float* bf0  = (const float*)d_in[2];
    const float* wi0  = (const float*)d_in[3];
    const float* bi0  = (const float*)d_in[4];
    const float* wo0  = (const float*)d_in[5];
    const float* bo0  = (const float*)d_in[6];
    const float* wg0  = (const float*)d_in[7];
    const float* bg0  = (const float*)d_in[8];
    const float* wf1  = (const float*)d_in[9];
    const float* bf1  = (const float*)d_in[10];
    const float* wi1  = (const float*)d_in[11];
    const float* bi1  = (const float*)d_in[12];
    const float* wo1  = (const float*)d_in[13];
    const float* bo1  = (const float*)d_in[14];
    const float* wg1  = (const float*)d_in[15];
    const float* bg1  = (const float*)d_in[16];
    const float* fc1w = (const float*)d_in[17];
    const float* fc1b = (const float*)d_in[18];
    const float* fc2w = (const float*)d_in[19];
    const float* fc2b = (const float*)d_in[20];
    float* out = (float*)d_out;

    cudaFuncSetAttribute(scan_kernel,
                         cudaFuncAttributeMaxDynamicSharedMemorySize, SMEM_BYTES);
    cudaFuncSetAttribute(xz_gemm_kernel,
                         cudaFuncAttributeMaxDynamicSharedMemorySize, XG_SMEM_BYTES);
    cudaFuncSetAttribute(fc1_kernel,
                         cudaFuncAttributeMaxDynamicSharedMemorySize, FC1_SMEM_BYTES);

    prep_kernel<<<4096, 256>>>(x, wf0, wi0, wo0, wg0, bf0, bi0, bo0, bg0,
                               wf1, wi1, wo1, wg1, bf1, bi1, bo1, bg1);
    dim3 xzgrid(256, 8);
    xz_gemm_kernel<<<xzgrid, NT, XG_SMEM_BYTES>>>();
    scan_kernel<<<NCTA, NT, SMEM_BYTES>>>();
    dim3 fc1grid(16, 4);
    fc1_kernel<<<fc1grid, 256, FC1_SMEM_BYTES>>>(fc1w, fc1b);
    fc2_kernel<<<BATCH, 192>>>(fc2w, fc2b, out);
}

// round 11
// speedup vs baseline: 10.8548x; 1.0671x over previous
#include <cuda_runtime.h>
#include <cuda_fp16.h>
#include <math.h>

#define BATCH 64
#define SEQ   512
#define DIN   128
#define HID   512
#define OUTN  24
#define K0    640
#define K1    1024
#define COLS  2048

#define NCTA   128
#define NBG    4
#define NCTABG 32
#define NT     256

// fp16 weight words (u32 = half2) per old-style column-group of 8 units
#define WPW_L0 10240               // 40 k16-blocks * 4 n8-blocks * 64 words
#define WPW_L1 16384               // 64 * 4 * 64
#define WPW    (WPW_L0 + WPW_L1)   // 26624 u32 per cg

#define AS_STRIDE 260              // 256 words (512 fp16) + 4 pad
#define AS_WORDS (16 * AS_STRIDE)  // 4160

// red: 2 layers x 4 kq x [16][68] floats
#define RED_PER   1088
#define RED_FLOATS (8 * RED_PER)

#define SMEM_U32  (2 * AS_WORDS + RED_FLOATS + 64 + 16)
#define SMEM_BYTES (SMEM_U32 * 4)

#define XG_SMEM_U32 (128 * 68 + 16384)
#define XG_SMEM_BYTES (XG_SMEM_U32 * 4)

// fc1: w tile [32][516] floats + h tile [16][256] half2 words
#define FC1_SMEM_U32 (32 * 516 + 4096)
#define FC1_SMEM_BYTES (FC1_SMEM_U32 * 4)

// ---------------- persistent device state ----------------------------------
__device__ __align__(16) unsigned d_Wp[64 * WPW];
__device__ __align__(16) unsigned d_x16[BATCH * SEQ * (DIN / 2)];
__device__ __align__(16) unsigned d_xz[BATCH * SEQ * (COLS / 2)];
__device__ float d_b0r[COLS];
__device__ float d_b1r[COLS];
__device__ __align__(16) unsigned d_h0[2][BATCH * (HID / 2)];
__device__ __align__(16) unsigned d_h1[2][BATCH * (HID / 2)];
__device__ float d_y1[BATCH * HID];
// Fused barrier word per bg (padded to 128B): low16 = arrivals, high16 = round.
// Monotonic: arrive = +1; last arriver also += (0x10000 - NCTABG)  (same-address
// atomics from one thread are ordered -> no fence between them needed).
__device__ unsigned g_bar[NBG * 32];

__device__ __forceinline__ float sigf(float v) { return 1.0f / (1.0f + __expf(-v)); }
__device__ __forceinline__ float tanha(float v) {
    float r; asm("tanh.approx.f32 %0, %1;" : "=f"(r) : "f"(v)); return r;
}

__device__ __forceinline__ void mma16(float c[4], unsigned a0, unsigned a1,
                                      unsigned a2, unsigned a3,
                                      unsigned b0, unsigned b1)
{
    asm volatile(
        "mma.sync.aligned.m16n8k16.row.col.f32.f16.f16.f32 "
        "{%0,%1,%2,%3},{%4,%5,%6,%7},{%8,%9},{%0,%1,%2,%3};"
        : "+f"(c[0]), "+f"(c[1]), "+f"(c[2]), "+f"(c[3])
        : "r"(a0), "r"(a1), "r"(a2), "r"(a3), "r"(b0), "r"(b1));
}

__device__ __forceinline__ void ldsm4(unsigned& a0, unsigned& a1,
                                      unsigned& a2, unsigned& a3, unsigned addr)
{
    asm volatile(
        "ldmatrix.sync.aligned.m8n8.x4.shared.b16 {%0,%1,%2,%3}, [%4];"
        : "=r"(a0), "=r"(a1), "=r"(a2), "=r"(a3) : "r"(addr));
}

__device__ __forceinline__ void cpa16(void* dst, const void* src)
{
    unsigned d = (unsigned)__cvta_generic_to_shared(dst);
    asm volatile("cp.async.cg.shared.global [%0], [%1], 16;" :: "r"(d), "l"(src));
}
__device__ __forceinline__ void cpa_commit()
{
    asm volatile("cp.async.commit_group;");
}
template<int N>
__device__ __forceinline__ void cpa_wait()
{
    asm volatile("cp.async.wait_group %0;" :: "n"(N));
}

// ---------------- prep: weight packing (fp16), x conversion, biases ---------
__global__ void prep_kernel(
    const float* __restrict__ x,
    const float* __restrict__ wf0, const float* __restrict__ wi0,
    const float* __restrict__ wo0, const float* __restrict__ wg0,
    const float* __restrict__ bf0, const float* __restrict__ bi0,
    const float* __restrict__ bo0, const float* __restrict__ bg0,
    const float* __restrict__ wf1, const float* __restrict__ wi1,
    const float* __restrict__ wo1, const float* __restrict__ wg1,
    const float* __restrict__ bf1, const float* __restrict__ bi1,
    const float* __restrict__ bo1, const float* __restrict__ bg1)
{
    const int nW = 64 * WPW;
    const int nX = BATCH * SEQ * (DIN / 2);
    const int ntot = nW + nX + 2 * COLS;
    for (int idx = blockIdx.x * blockDim.x + threadIdx.x; idx < ntot;
         idx += gridDim.x * blockDim.x) {
        if (idx < nW) {
            int cg = idx / WPW;
            int r  = idx % WPW;
            int layer = (r < WPW_L0) ? 0 : 1;
            int rr    = layer ? (r - WPW_L0) : r;
            int kb   = rr >> 8;
            int rem  = rr & 255;
            int nb   = rem >> 6;
            int t    = rem & 63;
            int lane = t >> 1;
            int reg  = t & 1;
            int colloc = nb * 8 + (lane >> 2);
            int unit = cg * 8 + (colloc >> 2);
            int gate = colloc & 3;
            int k    = kb * 16 + (lane & 3) * 2 + reg * 8;
            const float* w;
            int K;
            if (layer == 0) {
                w = (gate == 0) ? wf0 : (gate == 1) ? wi0 : (gate == 2) ? wo0 : wg0;
                K = K0;
            } else {
                w = (gate == 0) ? wf1 : (gate == 1) ? wi1 : (gate == 2) ? wo1 : wg1;
                K = K1;
            }
            __half2 h2 = __floats2half2_rn(w[unit * K + k], w[unit * K + k + 1]);
            d_Wp[idx] = *(unsigned*)&h2;
        } else if (idx < nW + nX) {
            int i = idx - nW;
            __half2 h2 = __floats2half2_rn(x[2 * i], x[2 * i + 1]);
            d_x16[i] = *(unsigned*)&h2;
        } else {
            int col = idx - nW - nX;
            if (col < COLS) {
                int u = col >> 2, g = col & 3;
                const float* bb = (g == 0) ? bf0 : (g == 1) ? bi0 : (g == 2) ? bo0 : bg0;
                d_b0r[col] = bb[u];
            } else {
                col -= COLS;
                int u = col >> 2, g = col & 3;
                const float* bb = (g == 0) ? bf1 : (g == 1) ? bi1 : (g == 2) ? bo1 : bg1;
                d_b1r[col] = bb[u];
            }
        }
    }
}

// ---------------- xz GEMM: xz[b,t,:] = x_t @ Wx0^T + b0 (fp16 out) ----------
__global__ void __launch_bounds__(NT) xz_gemm_kernel()
{
    extern __shared__ unsigned smem_u[];
    unsigned* As = smem_u;                 // [128][68]
    unsigned* Ws = smem_u + 128 * 68;      // 8 cgs * 2048 words

    const int tid  = threadIdx.x;
    const int w    = tid >> 5, lane = tid & 31;
    const int r4   = lane >> 2, kq4 = lane & 3;
    const int row0 = blockIdx.x * 128;
    const int cg0  = blockIdx.y * 8;

    #pragma unroll
    for (int i = tid; i < 2048; i += NT) {
        int row = i >> 4, w4 = (i & 15) * 4;
        cpa16(As + row * 68 + w4, d_x16 + (size_t)(row0 + row) * 64 + w4);
    }
    #pragma unroll
    for (int i = tid; i < 4096; i += NT) {
        int cgL = i >> 9, r = (i & 511) * 4;
        cpa16(Ws + cgL * 2048 + r, d_Wp + (size_t)(cg0 + cgL) * WPW + r);
    }
    cpa_commit();
    cpa_wait<0>();
    __syncthreads();

    float acc[32][4];
    #pragma unroll
    for (int i = 0; i < 32; ++i)
        { acc[i][0] = 0.f; acc[i][1] = 0.f; acc[i][2] = 0.f; acc[i][3] = 0.f; }

    #pragma unroll
    for (int kb = 0; kb < 8; ++kb) {
        const unsigned* ab = As + (w * 16 + r4) * 68 + kb * 8 + kq4;
        unsigned a0 = ab[0];
        unsigned a1 = ab[8 * 68];
        unsigned a2 = ab[4];
        unsigned a3 = ab[8 * 68 + 4];
        #pragma unroll
        for (int j = 0; j < 32; ++j) {
            const unsigned* bp = Ws + (j >> 2) * 2048 + kb * 256 + (j & 3) * 64 + lane * 2;
            uint2 b = *(const uint2*)bp;
            mma16(acc[j], a0, a1, a2, a3, b.x, b.y);
        }
    }

    #pragma unroll
    for (int j = 0; j < 32; ++j) {
        int col = (cg0 + (j >> 2)) * 32 + (j & 3) * 8 + 2 * (lane & 3);
        float bs0 = d_b0r[col], bs1 = d_b0r[col + 1];
        int mrow = row0 + w * 16 + r4;
        __half2 p0 = __floats2half2_rn(acc[j][0] + bs0, acc[j][1] + bs1);
        __half2 p1 = __floats2half2_rn(acc[j][2] + bs0, acc[j][3] + bs1);
        d_xz[(size_t)mrow * 1024 + (col >> 1)]        = *(unsigned*)&p0;
        d_xz[(size_t)(mrow + 8) * 1024 + (col >> 1)]  = *(unsigned*)&p1;
    }
}

// ---------------- fused single-word barrier ----------------------------------
__device__ __forceinline__ void bar_arrive(int bg)
{
    __syncthreads();
    if (threadIdx.x == 0) {
        __threadfence();                       // release my h stores
        unsigned prev = atomicAdd(&g_bar[bg * 32], 1u);
        if ((prev & 0xFFFFu) == NCTABG - 1)
            atomicAdd(&g_bar[bg * 32], 0x10000u - NCTABG);  // reset low + flip round
    }
}
__device__ __forceinline__ void bar_wait(int bg, unsigned base, unsigned mygen)
{
    if (threadIdx.x == 0) {
        volatile unsigned* p = &g_bar[bg * 32];
        while ((((*p >> 16) - base) & 0xFFFFu) < mygen) {}
        __threadfence();                       // acquire others' h stores
    }
    __syncthreads();
}

// ---------------- persistent scan kernel --------------------------------------
// 128 CTAs = 4 batch-groups (16 batches) x 32 unit-groups (16 units = 64 cols)
// warps: 4 K-quarters (kq) x 2 col-halves (wn, 32 cols = 4 n8 blocks)
__global__ void __launch_bounds__(NT, 1) scan_kernel()
{
    extern __shared__ unsigned smem_u[];
    unsigned* As0   = smem_u;                    // [16][260]  h0[t]
    unsigned* As1   = As0 + AS_WORDS;            // [16][260]  h1[t-1]
    float*    red   = (float*)(As1 + AS_WORDS);  // [2 layers][4 kq][16][68]
    float*    bias1 = red + RED_FLOATS;          // [64]

    const int tid  = threadIdx.x;
    const int cg   = blockIdx.x & 31;
    const int bg   = blockIdx.x >> 5;
    const int w    = tid >> 5, lane = tid & 31;
    const int wn   = w & 1;                      // col half (32 cols)
    const int kq   = w >> 1;                     // K quarter
    const int r4   = lane >> 2;

    const int fb = tid >> 4, fu = tid & 15;

    // Snapshot round BEFORE first arrive (replay-safe: rounds only advance
    // after ALL CTAs arrive, and every CTA snapshots before arriving).
    unsigned bar_base = 0;
    if (tid == 0) bar_base = (*(volatile unsigned*)&g_bar[bg * 32]) >> 16;

    // ---- one-time: B fragments -> registers ----
    const int cgA = cg * 2 + wn;
    uint2 B0[8][4];      // L0 recurrent: 8 k16 blocks x 4 n8
    uint2 B1[16][4];     // L1: 16 k16 blocks x 4 n8
    {
        const unsigned* w0 = d_Wp + (size_t)cgA * WPW + 2048
                           + (kq * 8) * 256 + lane * 2;
        #pragma unroll
        for (int j = 0; j < 8; ++j)
            #pragma unroll
            for (int n = 0; n < 4; ++n)
                B0[j][n] = *(const uint2*)(w0 + j * 256 + n * 64);
        const unsigned* w1 = d_Wp + (size_t)cgA * WPW + WPW_L0
                           + (kq * 16) * 256 + lane * 2;
        #pragma unroll
        for (int j = 0; j < 16; ++j)
            #pragma unroll
            for (int n = 0; n < 4; ++n)
                B1[j][n] = *(const uint2*)(w1 + j * 256 + n * 64);
    }
    if (tid < 64) bias1[tid] = d_b1r[cg * 64 + tid];

    // zero this bg's t=-1 hidden rows
    {
        int idx = cg * NT + tid;
        if (idx < 4096) d_h0[1][bg * 4096 + idx] = 0u;
        else            d_h1[1][bg * 4096 + (idx - 4096)] = 0u;
    }
    float c0 = 0.0f, c1 = 0.0f;
    bar_arrive(bg);
    unsigned mygen = 1;

    // ldmatrix per-lane addresses
    unsigned smem_base = (unsigned)__cvta_generic_to_shared(smem_u);
    const int lrow = lane & 15;
    const int lcol = (lane >> 4) * 4;
    const unsigned la0 = smem_base + (unsigned)(lrow * AS_STRIDE + lcol) * 4;
    // L1: quarters 0,1 -> As0 blocks [16kq,16kq+16); quarters 2,3 -> As1
    const unsigned la1 = (kq < 2 ? la0 : la0 + AS_WORDS * 4)
                       + (unsigned)((kq & 1) * 16) * 32;

    float* red0 = red + kq * RED_PER;
    float* red1 = red + 4 * RED_PER + kq * RED_PER;

    for (int k = 0; k <= SEQ; ++k) {
        const int doL0 = (k < SEQ);
        const int doL1 = (k >= 1);

        // xz prefetch (no dependency on h) — overlap with barrier propagation
        uint2 zraw;
        if (doL0)
            zraw = *(const uint2*)(d_xz +
                    (size_t)((bg * 16 + fb) * SEQ + k) * 1024 + cg * 32 + fu * 2);

        bar_wait(bg, bar_base, mygen); ++mygen;

        // ===== stage h0[t=k-1] (group 1), then h1[t=k-2] (group 0) ============
        {
            const unsigned* __restrict__ h0prev = d_h0[(k + 1) & 1];
            #pragma unroll
            for (int i = tid; i < 1024; i += NT) {
                int row = i >> 6, wd = (i & 63) * 4;
                cpa16(As0 + row * AS_STRIDE + wd,
                      h0prev + (bg * 16 + row) * 256 + wd);
            }
        }
        cpa_commit();
        if (doL1) {
            const unsigned* __restrict__ h1prev = d_h1[k & 1];
            #pragma unroll
            for (int i = tid; i < 1024; i += NT) {
                int row = i >> 6, wd = (i & 63) * 4;
                cpa16(As1 + row * AS_STRIDE + wd,
                      h1prev + (bg * 16 + row) * 256 + wd);
            }
        }
        cpa_commit();

        cpa_wait<1>();         // h0 tile ready
        __syncthreads();

        const int cbb = 2 * (lane & 3);

        // ===== layer 0 MMAs (overlaps in-flight h1 staging) =====
        if (doL0) {
            float acc[4][4] = {};
            #pragma unroll
            for (int j = 0; j < 8; ++j) {
                unsigned a0, a1, a2, a3;
                ldsm4(a0, a1, a2, a3, la0 + (unsigned)(kq * 8 + j) * 32);
                #pragma unroll
                for (int n = 0; n < 4; ++n)
                    mma16(acc[n], a0, a1, a2, a3, B0[j][n].x, B0[j][n].y);
            }
            #pragma unroll
            for (int n = 0; n < 4; ++n) {
                int cb = wn * 32 + n * 8 + cbb;
                *(float2*)&red0[r4 * 68 + cb]       = make_float2(acc[n][0], acc[n][1]);
                *(float2*)&red0[(r4 + 8) * 68 + cb] = make_float2(acc[n][2], acc[n][3]);
            }
        }

        cpa_wait<0>();         // h1 tile ready
        __syncthreads();

        // ===== layer 1 MMAs =====
        if (doL1) {
            float acc[4][4] = {};
            #pragma unroll
            for (int j = 0; j < 16; ++j) {
                unsigned a0, a1, a2, a3;
                ldsm4(a0, a1, a2, a3, la1 + (unsigned)j * 32);
                #pragma unroll
                for (int n = 0; n < 4; ++n)
                    mma16(acc[n], a0, a1, a2, a3, B1[j][n].x, B1[j][n].y);
            }
            #pragma unroll
            for (int n = 0; n < 4; ++n) {
                int cb = wn * 32 + n * 8 + cbb;
                *(float2*)&red1[r4 * 68 + cb]       = make_float2(acc[n][0], acc[n][1]);
                *(float2*)&red1[(r4 + 8) * 68 + cb] = make_float2(acc[n][2], acc[n][3]);
            }
        }

        __syncthreads();

        // ===== pointwise finishes =====
        const int o = fb * 68 + fu * 4;
        if (doL0) {
            float4 q0 = *(const float4*)&red[0 * RED_PER + o];
            float4 q1 = *(const float4*)&red[1 * RED_PER + o];
            float4 q2 = *(const float4*)&red[2 * RED_PER + o];
            float4 q3 = *(const float4*)&red[3 * RED_PER + o];
            __half2 zl = *(__half2*)&zraw.x;
            __half2 zh = *(__half2*)&zraw.y;
            float zf = q0.x + q1.x + q2.x + q3.x + __low2float(zl);
            float zi = q0.y + q1.y + q2.y + q3.y + __high2float(zl);
            float zo = q0.z + q1.z + q2.z + q3.z + __low2float(zh);
            float zg = q0.w + q1.w + q2.w + q3.w + __high2float(zh);
            float f  = sigf(zf);
            float ii = sigf(zi);
            float oo = sigf(zo);
            float g  = tanha(zg);
            float c  = f * c0 + ii * g;
            c0 = c;
            float hv = oo * tanha(c);
            ((__half*)d_h0[k & 1])[(bg * 16 + fb) * HID + cg * 16 + fu] =
                __float2half_rn(hv);
        }
        if (doL1) {
            float4 q0 = *(const float4*)&red[4 * RED_PER + o];
            float4 q1 = *(const float4*)&red[5 * RED_PER + o];
            float4 q2 = *(const float4*)&red[6 * RED_PER + o];
            float4 q3 = *(const float4*)&red[7 * RED_PER + o];
            float zf = q0.x + q1.x + q2.x + q3.x + bias1[fu * 4 + 0];
            float zi = q0.y + q1.y + q2.y + q3.y + bias1[fu * 4 + 1];
            float zo = q0.z + q1.z + q2.z + q3.z + bias1[fu * 4 + 2];
            float zg = q0.w + q1.w + q2.w + q3.w + bias1[fu * 4 + 3];
            float f  = sigf(zf);
            float ii = sigf(zi);
            float oo = sigf(zo);
            float g  = tanha(zg);
            float c  = f * c1 + ii * g;
            c1 = c;
            float hv = oo * tanha(c);
            ((__half*)d_h1[(k - 1) & 1])[(bg * 16 + fb) * HID + cg * 16 + fu] =
                __float2half_rn(hv);
        }

        bar_arrive(bg);
    }
}

// ---------------- fc1: smem-staged weight tile, coalesced --------------------
// grid (16 colblocks, 4 batchgroups), block 256. CTA: 32 cols x 16 batches.
__global__ void __launch_bounds__(256) fc1_kernel(
    const float* __restrict__ fc1w, const float* __restrict__ fc1b)
{
    extern __shared__ unsigned fsm[];
    float*    wsm = (float*)fsm;            // [32][516] padded
    unsigned* hsm = fsm + 32 * 516;         // [16][256] h as half2 words

    const int tid  = threadIdx.x;
    const int bgrp = blockIdx.y;
    const int jbase = blockIdx.x * 32;

    #pragma unroll
    for (int i = tid; i < 4096; i += 256)
        hsm[i] = d_h1[1][bgrp * 4096 + i];
    // stage fc1w tile coalesced (float4)
    #pragma unroll
    for (int i = tid; i < 32 * 128; i += 256) {
        int row = i >> 7, k4 = i & 127;
        *(float4*)&wsm[row * 516 + k4 * 4] =
            *(const float4*)&fc1w[(size_t)(jbase + row) * HID + k4 * 4];
    }
    __syncthreads();

    const int j   = tid & 31;
    const int wid = tid >> 5;            // 0..7 -> 2 batches each
    float acc0 = 0.f, acc1 = 0.f;
    const float* wr = wsm + j * 516;
    const unsigned* h0p = hsm + (wid * 2) * 256;
    const unsigned* h1p = hsm + (wid * 2 + 1) * 256;
    #pragma unroll 4
    for (int k4 = 0; k4 < 128; ++k4) {
        float4 wv = *(const float4*)&wr[k4 * 4];
        uint2 hpa = *(const uint2*)(h0p + k4 * 2);
        uint2 hpb = *(const uint2*)(h1p + k4 * 2);
        float2 a0 = __half22float2(*(__half2*)&hpa.x);
        float2 a1 = __half22float2(*(__half2*)&hpa.y);
        float2 b0 = __half22float2(*(__half2*)&hpb.x);
        float2 b1 = __half22float2(*(__half2*)&hpb.y);
        acc0 = fmaf(wv.x, a0.x, acc0); acc0 = fmaf(wv.y, a0.y, acc0);
        acc0 = fmaf(wv.z, a1.x, acc0); acc0 = fmaf(wv.w, a1.y, acc0);
        acc1 = fmaf(wv.x, b0.x, acc1); acc1 = fmaf(wv.y, b0.y, acc1);
        acc1 = fmaf(wv.z, b1.x, acc1); acc1 = fmaf(wv.w, b1.y, acc1);
    }
    float bj = fc1b[jbase + j];
    d_y1[(size_t)(bgrp * 16 + wid * 2)     * HID + jbase + j] = acc0 + bj;
    d_y1[(size_t)(bgrp * 16 + wid * 2 + 1) * HID + jbase + j] = acc1 + bj;
}

// ---------------- fc2 + relu: out[64,24] -----------------------------------------
__global__ void __launch_bounds__(192) fc2_kernel(
    const float* __restrict__ fc2w, const float* __restrict__ fc2b,
    float* __restrict__ out)
{
    __shared__ float ys[HID];
    const int b = blockIdx.x;
    const int tid = threadIdx.x;
    for (int i = tid; i < HID; i += 192) ys[i] = d_y1[(size_t)b * HID + i];
    __syncthreads();
    int j = tid >> 3, part = tid & 7;
    const float4* wr = (const float4*)(fc2w + (size_t)j * HID + part * 64);
    const float4* yv = (const float4*)(ys + part * 64);
    float a = 0.0f;
    #pragma unroll
    for (int kk = 0; kk < 16; ++kk) {
        float4 wv = wr[kk];
        float4 xv = yv[kk];
        a = fmaf(wv.x, xv.x, a);
        a = fmaf(wv.y, xv.y, a);
        a = fmaf(wv.z, xv.z, a);
        a = fmaf(wv.w, xv.w, a);
    }
    a += __shfl_down_sync(0xffffffffu, a, 4, 8);
    a += __shfl_down_sync(0xffffffffu, a, 2, 8);
    a += __shfl_down_sync(0xffffffffu, a, 1, 8);
    if (part == 0)
        out[b * OUTN + j] = fmaxf(a + fc2b[j], 0.0f);
}

// ---------------- launch ---------------------------------------------------------
extern "C" void kernel_launch(void* const* d_in, const int* in_sizes, int n_in,
                              void* d_out, int out_size)
{
    const float* x    = (const float*)d_in[0];
    const float* wf0  = (const float*)d_in[1];
    const float* bf0  = (const float*)d_in[2];
    const float* wi0  = (const float*)d_in[3];
    const float* bi0  = (const float*)d_in[4];
    const float* wo0  = (const float*)d_in[5];
    const float* bo0  = (const float*)d_in[6];
    const float* wg0  = (const float*)d_in[7];
    const float* bg0  = (const float*)d_in[8];
    const float* wf1  = (const float*)d_in[9];
    const float* bf1  = (const float*)d_in[10];
    const float* wi1  = (const float*)d_in[11];
    const float* bi1  = (const float*)d_in[12];
    const float* wo1  = (const float*)d_in[13];
    const float* bo1  = (const float*)d_in[14];
    const float* wg1  = (const float*)d_in[15];
    const float* bg1  = (const float*)d_in[16];
    const float* fc1w = (const float*)d_in[17];
    const float* fc1b = (const float*)d_in[18];
    const float* fc2w = (const float*)d_in[19];
    const float* fc2b = (const float*)d_in[20];
    float* out = (float*)d_out;

    cudaFuncSetAttribute(scan_kernel,
                         cudaFuncAttributeMaxDynamicSharedMemorySize, SMEM_BYTES);
    cudaFuncSetAttribute(xz_gemm_kernel,
                         cudaFuncAttributeMaxDynamicSharedMemorySize, XG_SMEM_BYTES);
    cudaFuncSetAttribute(fc1_kernel,
                         cudaFuncAttributeMaxDynamicSharedMemorySize, FC1_SMEM_BYTES);

    prep_kernel<<<4096, 256>>>(x, wf0, wi0, wo0, wg0, bf0, bi0, bo0, bg0,
                               wf1, wi1, wo1, wg1, bf1, bi1, bo1, bg1);
    dim3 xzgrid(256, 8);
    xz_gemm_kernel<<<xzgrid, NT, XG_SMEM_BYTES>>>();
    scan_kernel<<<NCTA, NT, SMEM_BYTES>>>();
    dim3 fc1grid(16, 4);
    fc1_kernel<<<fc1grid, 256, FC1_SMEM_BYTES>>>(fc1w, fc1b);
    fc2_kernel<<<BATCH, 192>>>(fc2w, fc2b, out);
}

// round 12
// speedup vs baseline: 11.2710x; 1.0383x over previous
#include <cuda_runtime.h>
#include <cuda_fp16.h>
#include <math.h>

#define BATCH 64
#define SEQ   512
#define DIN   128
#define HID   512
#define OUTN  24
#define K0    640
#define K1    1024
#define COLS  2048

#define NCTA   128
#define NBG    4
#define NCTABG 32
#define NT     256

// fp16 weight words (u32 = half2) per old-style column-group of 8 units
#define WPW_L0 10240               // 40 k16-blocks * 4 n8-blocks * 64 words
#define WPW_L1 16384               // 64 * 4 * 64
#define WPW    (WPW_L0 + WPW_L1)   // 26624 u32 per cg

#define AS_STRIDE 260              // 256 words (512 fp16) + 4 pad
#define AS_WORDS (16 * AS_STRIDE)  // 4160

// red: 2 layers x 4 kq x [16][68] floats
#define RED_PER   1088
#define RED_FLOATS (8 * RED_PER)

#define SMEM_U32  (2 * AS_WORDS + RED_FLOATS + 64 + 16)
#define SMEM_BYTES (SMEM_U32 * 4)

#define XG_SMEM_U32 (128 * 68 + 16384)
#define XG_SMEM_BYTES (XG_SMEM_U32 * 4)

// fc1: w tile [32][516] floats + h tile [16][256] half2 words
#define FC1_SMEM_U32 (32 * 516 + 4096)
#define FC1_SMEM_BYTES (FC1_SMEM_U32 * 4)

// ---------------- persistent device state ----------------------------------
__device__ __align__(16) unsigned d_Wp[64 * WPW];
__device__ __align__(16) unsigned d_x16[BATCH * SEQ * (DIN / 2)];
__device__ __align__(16) unsigned d_xz[BATCH * SEQ * (COLS / 2)];
__device__ float d_b0r[COLS];
__device__ float d_b1r[COLS];
__device__ __align__(16) unsigned d_h0[2][BATCH * (HID / 2)];
__device__ __align__(16) unsigned d_h1[2][BATCH * (HID / 2)];
__device__ float d_y1[BATCH * HID];
// Fused barrier word per bg: low16 = arrivals, high16 = round (monotonic).
__device__ unsigned g_bar[NBG * 32];

__device__ __forceinline__ float sigf(float v) { return 1.0f / (1.0f + __expf(-v)); }
__device__ __forceinline__ float tanha(float v) {
    float r; asm("tanh.approx.f32 %0, %1;" : "=f"(r) : "f"(v)); return r;
}

__device__ __forceinline__ void mma16(float c[4], unsigned a0, unsigned a1,
                                      unsigned a2, unsigned a3,
                                      unsigned b0, unsigned b1)
{
    asm volatile(
        "mma.sync.aligned.m16n8k16.row.col.f32.f16.f16.f32 "
        "{%0,%1,%2,%3},{%4,%5,%6,%7},{%8,%9},{%0,%1,%2,%3};"
        : "+f"(c[0]), "+f"(c[1]), "+f"(c[2]), "+f"(c[3])
        : "r"(a0), "r"(a1), "r"(a2), "r"(a3), "r"(b0), "r"(b1));
}

__device__ __forceinline__ void ldsm4(unsigned& a0, unsigned& a1,
                                      unsigned& a2, unsigned& a3, unsigned addr)
{
    asm volatile(
        "ldmatrix.sync.aligned.m8n8.x4.shared.b16 {%0,%1,%2,%3}, [%4];"
        : "=r"(a0), "=r"(a1), "=r"(a2), "=r"(a3) : "r"(addr));
}

__device__ __forceinline__ void cpa16(void* dst, const void* src)
{
    unsigned d = (unsigned)__cvta_generic_to_shared(dst);
    asm volatile("cp.async.cg.shared.global [%0], [%1], 16;" :: "r"(d), "l"(src));
}
__device__ __forceinline__ void cpa_commit()
{
    asm volatile("cp.async.commit_group;");
}
template<int N>
__device__ __forceinline__ void cpa_wait()
{
    asm volatile("cp.async.wait_group %0;" :: "n"(N));
}
__device__ __forceinline__ void pair_bar(int id)
{
    asm volatile("bar.sync %0, 64;" :: "r"(id) : "memory");
}

// ---------------- prep: weight packing (fp16), x conversion, biases ---------
__global__ void prep_kernel(
    const float* __restrict__ x,
    const float* __restrict__ wf0, const float* __restrict__ wi0,
    const float* __restrict__ wo0, const float* __restrict__ wg0,
    const float* __restrict__ bf0, const float* __restrict__ bi0,
    const float* __restrict__ bo0, const float* __restrict__ bg0,
    const float* __restrict__ wf1, const float* __restrict__ wi1,
    const float* __restrict__ wo1, const float* __restrict__ wg1,
    const float* __restrict__ bf1, const float* __restrict__ bi1,
    const float* __restrict__ bo1, const float* __restrict__ bg1)
{
    const int nW = 64 * WPW;
    const int nX = BATCH * SEQ * (DIN / 2);
    const int ntot = nW + nX + 2 * COLS;
    for (int idx = blockIdx.x * blockDim.x + threadIdx.x; idx < ntot;
         idx += gridDim.x * blockDim.x) {
        if (idx < nW) {
            int cg = idx / WPW;
            int r  = idx % WPW;
            int layer = (r < WPW_L0) ? 0 : 1;
            int rr    = layer ? (r - WPW_L0) : r;
            int kb   = rr >> 8;
            int rem  = rr & 255;
            int nb   = rem >> 6;
            int t    = rem & 63;
            int lane = t >> 1;
            int reg  = t & 1;
            int colloc = nb * 8 + (lane >> 2);
            int unit = cg * 8 + (colloc >> 2);
            int gate = colloc & 3;
            int k    = kb * 16 + (lane & 3) * 2 + reg * 8;
            const float* w;
            int K;
            if (layer == 0) {
                w = (gate == 0) ? wf0 : (gate == 1) ? wi0 : (gate == 2) ? wo0 : wg0;
                K = K0;
            } else {
                w = (gate == 0) ? wf1 : (gate == 1) ? wi1 : (gate == 2) ? wo1 : wg1;
                K = K1;
            }
            __half2 h2 = __floats2half2_rn(w[unit * K + k], w[unit * K + k + 1]);
            d_Wp[idx] = *(unsigned*)&h2;
        } else if (idx < nW + nX) {
            int i = idx - nW;
            __half2 h2 = __floats2half2_rn(x[2 * i], x[2 * i + 1]);
            d_x16[i] = *(unsigned*)&h2;
        } else {
            int col = idx - nW - nX;
            if (col < COLS) {
                int u = col >> 2, g = col & 3;
                const float* bb = (g == 0) ? bf0 : (g == 1) ? bi0 : (g == 2) ? bo0 : bg0;
                d_b0r[col] = bb[u];
            } else {
                col -= COLS;
                int u = col >> 2, g = col & 3;
                const float* bb = (g == 0) ? bf1 : (g == 1) ? bi1 : (g == 2) ? bo1 : bg1;
                d_b1r[col] = bb[u];
            }
        }
    }
}

// ---------------- xz GEMM: xz[b,t,:] = x_t @ Wx0^T + b0 (fp16 out) ----------
__global__ void __launch_bounds__(NT) xz_gemm_kernel()
{
    extern __shared__ unsigned smem_u[];
    unsigned* As = smem_u;                 // [128][68]
    unsigned* Ws = smem_u + 128 * 68;      // 8 cgs * 2048 words

    const int tid  = threadIdx.x;
    const int w    = tid >> 5, lane = tid & 31;
    const int r4   = lane >> 2, kq4 = lane & 3;
    const int row0 = blockIdx.x * 128;
    const int cg0  = blockIdx.y * 8;

    #pragma unroll
    for (int i = tid; i < 2048; i += NT) {
        int row = i >> 4, w4 = (i & 15) * 4;
        cpa16(As + row * 68 + w4, d_x16 + (size_t)(row0 + row) * 64 + w4);
    }
    #pragma unroll
    for (int i = tid; i < 4096; i += NT) {
        int cgL = i >> 9, r = (i & 511) * 4;
        cpa16(Ws + cgL * 2048 + r, d_Wp + (size_t)(cg0 + cgL) * WPW + r);
    }
    cpa_commit();
    cpa_wait<0>();
    __syncthreads();

    float acc[32][4];
    #pragma unroll
    for (int i = 0; i < 32; ++i)
        { acc[i][0] = 0.f; acc[i][1] = 0.f; acc[i][2] = 0.f; acc[i][3] = 0.f; }

    #pragma unroll
    for (int kb = 0; kb < 8; ++kb) {
        const unsigned* ab = As + (w * 16 + r4) * 68 + kb * 8 + kq4;
        unsigned a0 = ab[0];
        unsigned a1 = ab[8 * 68];
        unsigned a2 = ab[4];
        unsigned a3 = ab[8 * 68 + 4];
        #pragma unroll
        for (int j = 0; j < 32; ++j) {
            const unsigned* bp = Ws + (j >> 2) * 2048 + kb * 256 + (j & 3) * 64 + lane * 2;
            uint2 b = *(const uint2*)bp;
            mma16(acc[j], a0, a1, a2, a3, b.x, b.y);
        }
    }

    #pragma unroll
    for (int j = 0; j < 32; ++j) {
        int col = (cg0 + (j >> 2)) * 32 + (j & 3) * 8 + 2 * (lane & 3);
        float bs0 = d_b0r[col], bs1 = d_b0r[col + 1];
        int mrow = row0 + w * 16 + r4;
        __half2 p0 = __floats2half2_rn(acc[j][0] + bs0, acc[j][1] + bs1);
        __half2 p1 = __floats2half2_rn(acc[j][2] + bs0, acc[j][3] + bs1);
        d_xz[(size_t)mrow * 1024 + (col >> 1)]        = *(unsigned*)&p0;
        d_xz[(size_t)(mrow + 8) * 1024 + (col >> 1)]  = *(unsigned*)&p1;
    }
}

// ---------------- fused single-word barrier ----------------------------------
__device__ __forceinline__ void bar_arrive(int bg)
{
    __syncthreads();
    if (threadIdx.x == 0) {
        __threadfence();
        unsigned prev = atomicAdd(&g_bar[bg * 32], 1u);
        if ((prev & 0xFFFFu) == NCTABG - 1)
            atomicAdd(&g_bar[bg * 32], 0x10000u - NCTABG);
    }
}
__device__ __forceinline__ void bar_wait(int bg, unsigned base, unsigned mygen)
{
    if (threadIdx.x == 0) {
        volatile unsigned* p = &g_bar[bg * 32];
        while ((((*p >> 16) - base) & 0xFFFFu) < mygen) {}
        __threadfence();
    }
    __syncthreads();
}

// ---------------- persistent scan kernel --------------------------------------
// 128 CTAs = 4 batch-groups (16 batches) x 32 unit-groups (16 units = 64 cols)
// warps: 4 K-quarters (kq) x 2 col-halves (wn). L1 K-split is kq-interleaved:
// warp kq handles h0 cols [128kq,128kq+128) and h1 cols [128kq,128kq+128).
__global__ void __launch_bounds__(NT, 1) scan_kernel()
{
    extern __shared__ unsigned smem_u[];
    unsigned* As0   = smem_u;                    // [16][260]  h0[t]
    unsigned* As1   = As0 + AS_WORDS;            // [16][260]  h1[t-1]
    float*    red   = (float*)(As1 + AS_WORDS);  // [2 layers][4 kq][16][68]
    float*    bias1 = red + RED_FLOATS;          // [64]

    const int tid  = threadIdx.x;
    const int cg   = blockIdx.x & 31;
    const int bg   = blockIdx.x >> 5;
    const int w    = tid >> 5, lane = tid & 31;
    const int wn   = w & 1;                      // col half (32 cols)
    const int kq   = w >> 1;                     // K quarter
    const int r4   = lane >> 2;

    const int fb = tid >> 4, fu = tid & 15;

    unsigned bar_base = 0;
    if (tid == 0) bar_base = (*(volatile unsigned*)&g_bar[bg * 32]) >> 16;

    // ---- one-time: B fragments -> registers ----
    const int cgA = cg * 2 + wn;
    uint2 B0[8][4];       // L0 recurrent: blocks kq*8+j
    uint2 B1a[8][4];      // L1 h0-part:   blocks kq*8+j
    uint2 B1b[8][4];      // L1 h1-part:   blocks 32+kq*8+j
    {
        const unsigned* w0 = d_Wp + (size_t)cgA * WPW + 2048
                           + (kq * 8) * 256 + lane * 2;
        #pragma unroll
        for (int j = 0; j < 8; ++j)
            #pragma unroll
            for (int n = 0; n < 4; ++n)
                B0[j][n] = *(const uint2*)(w0 + j * 256 + n * 64);
        const unsigned* w1 = d_Wp + (size_t)cgA * WPW + WPW_L0
                           + (kq * 8) * 256 + lane * 2;
        #pragma unroll
        for (int j = 0; j < 8; ++j)
            #pragma unroll
            for (int n = 0; n < 4; ++n)
                B1a[j][n] = *(const uint2*)(w1 + j * 256 + n * 64);
        const unsigned* w1b = w1 + 32 * 256;
        #pragma unroll
        for (int j = 0; j < 8; ++j)
            #pragma unroll
            for (int n = 0; n < 4; ++n)
                B1b[j][n] = *(const uint2*)(w1b + j * 256 + n * 64);
    }
    if (tid < 64) bias1[tid] = d_b1r[cg * 64 + tid];

    // zero this bg's t=-1 hidden rows
    {
        int idx = cg * NT + tid;
        if (idx < 4096) d_h0[1][bg * 4096 + idx] = 0u;
        else            d_h1[1][bg * 4096 + (idx - 4096)] = 0u;
    }
    float c0 = 0.0f, c1 = 0.0f;
    bar_arrive(bg);
    unsigned mygen = 1;

    // ldmatrix per-lane addresses (blocks kq*8+j live in quarter kq)
    unsigned smem_base = (unsigned)__cvta_generic_to_shared(smem_u);
    const int lrow = lane & 15;
    const int lcol = (lane >> 4) * 4;
    const unsigned la0  = smem_base + (unsigned)(lrow * AS_STRIDE + lcol) * 4;
    const unsigned la1h = la0 + AS_WORDS * 4;    // same pattern in As1

    float* red0 = red + kq * RED_PER;
    float* red1 = red + 4 * RED_PER + kq * RED_PER;
    const int barid = 1 + kq;

    for (int k = 0; k <= SEQ; ++k) {
        const int doL0 = (k < SEQ);
        const int doL1 = (k >= 1);

        // xz prefetch (no dependency on h) — overlap with barrier propagation
        uint2 zraw;
        if (doL0)
            zraw = *(const uint2*)(d_xz +
                    (size_t)((bg * 16 + fb) * SEQ + k) * 1024 + cg * 32 + fu * 2);

        bar_wait(bg, bar_base, mygen); ++mygen;

        // ===== self-staging: warp (kq,wn) stages its own 8 rows x quarter kq ===
        {
            const unsigned* __restrict__ h0prev = d_h0[(k + 1) & 1];
            #pragma unroll
            for (int it = 0; it < 4; ++it) {
                int idx = it * 32 + lane;            // 0..127
                int row = wn * 8 + (idx >> 4);
                int wd  = kq * 64 + (idx & 15) * 4;
                cpa16(As0 + row * AS_STRIDE + wd,
                      h0prev + (bg * 16 + row) * 256 + wd);
            }
        }
        cpa_commit();
        if (doL1) {
            const unsigned* __restrict__ h1prev = d_h1[k & 1];
            #pragma unroll
            for (int it = 0; it < 4; ++it) {
                int idx = it * 32 + lane;
                int row = wn * 8 + (idx >> 4);
                int wd  = kq * 64 + (idx & 15) * 4;
                cpa16(As1 + row * AS_STRIDE + wd,
                      h1prev + (bg * 16 + row) * 256 + wd);
            }
        }
        cpa_commit();                    // always commit (possibly empty group)

        cpa_wait<1>();                   // own As0 quarter done
        pair_bar(barid);                 // partner's half of the quarter done

        const int cbb = 2 * (lane & 3);

        // ===== fused pass over As0: L0 MMA + L1 h0-part MMA share fragments ===
        float acc0[4][4] = {};
        float acc1[4][4] = {};
        #pragma unroll
        for (int j = 0; j < 8; ++j) {
            unsigned a0, a1, a2, a3;
            ldsm4(a0, a1, a2, a3, la0 + (unsigned)(kq * 8 + j) * 32);
            if (doL0) {
                #pragma unroll
                for (int n = 0; n < 4; ++n)
                    mma16(acc0[n], a0, a1, a2, a3, B0[j][n].x, B0[j][n].y);
            }
            if (doL1) {
                #pragma unroll
                for (int n = 0; n < 4; ++n)
                    mma16(acc1[n], a0, a1, a2, a3, B1a[j][n].x, B1a[j][n].y);
            }
        }
        if (doL0) {
            #pragma unroll
            for (int n = 0; n < 4; ++n) {
                int cb = wn * 32 + n * 8 + cbb;
                *(float2*)&red0[r4 * 68 + cb]       = make_float2(acc0[n][0], acc0[n][1]);
                *(float2*)&red0[(r4 + 8) * 68 + cb] = make_float2(acc0[n][2], acc0[n][3]);
            }
        }

        cpa_wait<0>();                   // own As1 quarter done
        pair_bar(barid);

        // ===== L1 h1-part MMAs =====
        if (doL1) {
            #pragma unroll
            for (int j = 0; j < 8; ++j) {
                unsigned a0, a1, a2, a3;
                ldsm4(a0, a1, a2, a3, la1h + (unsigned)(kq * 8 + j) * 32);
                #pragma unroll
                for (int n = 0; n < 4; ++n)
                    mma16(acc1[n], a0, a1, a2, a3, B1b[j][n].x, B1b[j][n].y);
            }
            #pragma unroll
            for (int n = 0; n < 4; ++n) {
                int cb = wn * 32 + n * 8 + cbb;
                *(float2*)&red1[r4 * 68 + cb]       = make_float2(acc1[n][0], acc1[n][1]);
                *(float2*)&red1[(r4 + 8) * 68 + cb] = make_float2(acc1[n][2], acc1[n][3]);
            }
        }

        __syncthreads();

        // ===== pointwise finishes =====
        const int o = fb * 68 + fu * 4;
        if (doL0) {
            float4 q0 = *(const float4*)&red[0 * RED_PER + o];
            float4 q1 = *(const float4*)&red[1 * RED_PER + o];
            float4 q2 = *(const float4*)&red[2 * RED_PER + o];
            float4 q3 = *(const float4*)&red[3 * RED_PER + o];
            __half2 zl = *(__half2*)&zraw.x;
            __half2 zh = *(__half2*)&zraw.y;
            float zf = q0.x + q1.x + q2.x + q3.x + __low2float(zl);
            float zi = q0.y + q1.y + q2.y + q3.y + __high2float(zl);
            float zo = q0.z + q1.z + q2.z + q3.z + __low2float(zh);
            float zg = q0.w + q1.w + q2.w + q3.w + __high2float(zh);
            float f  = sigf(zf);
            float ii = sigf(zi);
            float oo = sigf(zo);
            float g  = tanha(zg);
            float c  = f * c0 + ii * g;
            c0 = c;
            float hv = oo * tanha(c);
            ((__half*)d_h0[k & 1])[(bg * 16 + fb) * HID + cg * 16 + fu] =
                __float2half_rn(hv);
        }
        if (doL1) {
            float4 q0 = *(const float4*)&red[4 * RED_PER + o];
            float4 q1 = *(const float4*)&red[5 * RED_PER + o];
            float4 q2 = *(const float4*)&red[6 * RED_PER + o];
            float4 q3 = *(const float4*)&red[7 * RED_PER + o];
            float zf = q0.x + q1.x + q2.x + q3.x + bias1[fu * 4 + 0];
            float zi = q0.y + q1.y + q2.y + q3.y + bias1[fu * 4 + 1];
            float zo = q0.z + q1.z + q2.z + q3.z + bias1[fu * 4 + 2];
            float zg = q0.w + q1.w + q2.w + q3.w + bias1[fu * 4 + 3];
            float f  = sigf(zf);
            float ii = sigf(zi);
            float oo = sigf(zo);
            float g  = tanha(zg);
            float c  = f * c1 + ii * g;
            c1 = c;
            float hv = oo * tanha(c);
            ((__half*)d_h1[(k - 1) & 1])[(bg * 16 + fb) * HID + cg * 16 + fu] =
                __float2half_rn(hv);
        }

        bar_arrive(bg);
    }
}

// ---------------- fc1: smem-staged weight tile, coalesced --------------------
__global__ void __launch_bounds__(256) fc1_kernel(
    const float* __restrict__ fc1w, const float* __restrict__ fc1b)
{
    extern __shared__ unsigned fsm[];
    float*    wsm = (float*)fsm;            // [32][516] padded
    unsigned* hsm = fsm + 32 * 516;         // [16][256] h as half2 words

    const int tid  = threadIdx.x;
    const int bgrp = blockIdx.y;
    const int jbase = blockIdx.x * 32;

    #pragma unroll
    for (int i = tid; i < 4096; i += 256)
        hsm[i] = d_h1[1][bgrp * 4096 + i];
    #pragma unroll
    for (int i = tid; i < 32 * 128; i += 256) {
        int row = i >> 7, k4 = i & 127;
        *(float4*)&wsm[row * 516 + k4 * 4] =
            *(const float4*)&fc1w[(size_t)(jbase + row) * HID + k4 * 4];
    }
    __syncthreads();

    const int j   = tid & 31;
    const int wid = tid >> 5;
    float acc0 = 0.f, acc1 = 0.f;
    const float* wr = wsm + j * 516;
    const unsigned* h0p = hsm + (wid * 2) * 256;
    const unsigned* h1p = hsm + (wid * 2 + 1) * 256;
    #pragma unroll 4
    for (int k4 = 0; k4 < 128; ++k4) {
        float4 wv = *(const float4*)&wr[k4 * 4];
        uint2 hpa = *(const uint2*)(h0p + k4 * 2);
        uint2 hpb = *(const uint2*)(h1p + k4 * 2);
        float2 a0 = __half22float2(*(__half2*)&hpa.x);
        float2 a1 = __half22float2(*(__half2*)&hpa.y);
        float2 b0 = __half22float2(*(__half2*)&hpb.x);
        float2 b1 = __half22float2(*(__half2*)&hpb.y);
        acc0 = fmaf(wv.x, a0.x, acc0); acc0 = fmaf(wv.y, a0.y, acc0);
        acc0 = fmaf(wv.z, a1.x, acc0); acc0 = fmaf(wv.w, a1.y, acc0);
        acc1 = fmaf(wv.x, b0.x, acc1); acc1 = fmaf(wv.y, b0.y, acc1);
        acc1 = fmaf(wv.z, b1.x, acc1); acc1 = fmaf(wv.w, b1.y, acc1);
    }
    float bj = fc1b[jbase + j];
    d_y1[(size_t)(bgrp * 16 + wid * 2)     * HID + jbase + j] = acc0 + bj;
    d_y1[(size_t)(bgrp * 16 + wid * 2 + 1) * HID + jbase + j] = acc1 + bj;
}

// ---------------- fc2 + relu: out[64,24] -----------------------------------------
__global__ void __launch_bounds__(192) fc2_kernel(
    const float* __restrict__ fc2w, const float* __restrict__ fc2b,
    float* __restrict__ out)
{
    __shared__ float ys[HID];
    const int b = blockIdx.x;
    const int tid = threadIdx.x;
    for (int i = tid; i < HID; i += 192) ys[i] = d_y1[(size_t)b * HID + i];
    __syncthreads();
    int j = tid >> 3, part = tid & 7;
    const float4* wr = (const float4*)(fc2w + (size_t)j * HID + part * 64);
    const float4* yv = (const float4*)(ys + part * 64);
    float a = 0.0f;
    #pragma unroll
    for (int kk = 0; kk < 16; ++kk) {
        float4 wv = wr[kk];
        float4 xv = yv[kk];
        a = fmaf(wv.x, xv.x, a);
        a = fmaf(wv.y, xv.y, a);
        a = fmaf(wv.z, xv.z, a);
        a = fmaf(wv.w, xv.w, a);
    }
    a += __shfl_down_sync(0xffffffffu, a, 4, 8);
    a += __shfl_down_sync(0xffffffffu, a, 2, 8);
    a += __shfl_down_sync(0xffffffffu, a, 1, 8);
    if (part == 0)
        out[b * OUTN + j] = fmaxf(a + fc2b[j], 0.0f);
}

// ---------------- launch ---------------------------------------------------------
extern "C" void kernel_launch(void* const* d_in, const int* in_sizes, int n_in,
                              void* d_out, int out_size)
{
    const float* x    = (const float*)d_in[0];
    const float* wf0  = (const float*)d_in[1];
    const float* bf0  = (const float*)d_in[2];
    const float* wi0  = (const float*)d_in[3];
    const float* bi0  = (const float*)d_in[4];
    const float* wo0  = (const float*)d_in[5];
    const float* bo0  = (const float*)d_in[6];
    const float* wg0  = (const float*)d_in[7];
    const float* bg0  = (const float*)d_in[8];
    const float* wf1  = (const float*)d_in[9];
    const float* bf1  = (const float*)d_in[10];
    const float* wi1  = (const float*)d_in[11];
    const float* bi1  = (const float*)d_in[12];
    const float* wo1  = (const float*)d_in[13];
    const float* bo1  = (const float*)d_in[14];
    const float* wg1  = (const float*)d_in[15];
    const float* bg1  = (const float*)d_in[16];
    const float* fc1w = (const float*)d_in[17];
    const float* fc1b = (const float*)d_in[18];
    const float* fc2w = (const float*)d_in[19];
    const float* fc2b = (const float*)d_in[20];
    float* out = (float*)d_out;

    cudaFuncSetAttribute(scan_kernel,
                         cudaFuncAttributeMaxDynamicSharedMemorySize, SMEM_BYTES);
    cudaFuncSetAttribute(xz_gemm_kernel,
                         cudaFuncAttributeMaxDynamicSharedMemorySize, XG_SMEM_BYTES);
    cudaFuncSetAttribute(fc1_kernel,
                         cudaFuncAttributeMaxDynamicSharedMemorySize, FC1_SMEM_BYTES);

    prep_kernel<<<4096, 256>>>(x, wf0, wi0, wo0, wg0, bf0, bi0, bo0, bg0,
                               wf1, wi1, wo1, wg1, bf1, bi1, bo1, bg1);
    dim3 xzgrid(256, 8);
    xz_gemm_kernel<<<xzgrid, NT, XG_SMEM_BYTES>>>();
    scan_kernel<<<NCTA, NT, SMEM_BYTES>>>();
    dim3 fc1grid(16, 4);
    fc1_kernel<<<fc1grid, 256, FC1_SMEM_BYTES>>>(fc1w, fc1b);
    fc2_kernel<<<BATCH, 192>>>(fc2w, fc2b, out);
}

// round 13
// speedup vs baseline: 11.7215x; 1.0400x over previous
#include <cuda_runtime.h>
#include <cuda_fp16.h>
#include <math.h>

#define BATCH 64
#define SEQ   512
#define DIN   128
#define HID   512
#define OUTN  24
#define K0    640
#define K1    1024
#define COLS  2048

#define NCTA   128
#define NBG    4
#define NCTABG 32
#define NT     256

// fp16 weight words (u32 = half2) per old-style column-group of 8 units
#define WPW_L0 10240               // 40 k16-blocks * 4 n8-blocks * 64 words
#define WPW_L1 16384               // 64 * 4 * 64
#define WPW    (WPW_L0 + WPW_L1)   // 26624 u32 per cg

#define AS_STRIDE 260              // 256 words (512 fp16) + 4 pad
#define AS_WORDS (16 * AS_STRIDE)  // 4160

// red: 2 layers x 4 kq x [16][68] floats
#define RED_PER   1088
#define RED_FLOATS (8 * RED_PER)

#define SMEM_U32  (2 * AS_WORDS + RED_FLOATS + 64 + 16)
#define SMEM_BYTES (SMEM_U32 * 4)

#define XG_SMEM_U32 (128 * 68 + 16384)
#define XG_SMEM_BYTES (XG_SMEM_U32 * 4)

// fc1: w tile [32][516] floats + h tile [16][256] half2 words
#define FC1_SMEM_U32 (32 * 516 + 4096)
#define FC1_SMEM_BYTES (FC1_SMEM_U32 * 4)

// ---------------- persistent device state ----------------------------------
__device__ __align__(16) unsigned d_Wp[64 * WPW];
__device__ __align__(16) unsigned d_x16[BATCH * SEQ * (DIN / 2)];
__device__ __align__(16) unsigned d_xz[BATCH * SEQ * (COLS / 2)];
__device__ float d_b0r[COLS];
__device__ float d_b1r[COLS];
__device__ __align__(16) unsigned d_h0[2][BATCH * (HID / 2)];
__device__ __align__(16) unsigned d_h1[2][BATCH * (HID / 2)];
__device__ float d_y1[BATCH * HID];
// Fused barrier word per bg: low16 = arrivals, high16 = round (monotonic).
__device__ unsigned g_bar[NBG * 32];

__device__ __forceinline__ float sigf(float v) { return 1.0f / (1.0f + __expf(-v)); }
__device__ __forceinline__ float tanha(float v) {
    float r; asm("tanh.approx.f32 %0, %1;" : "=f"(r) : "f"(v)); return r;
}

__device__ __forceinline__ void mma16(float c[4], unsigned a0, unsigned a1,
                                      unsigned a2, unsigned a3,
                                      unsigned b0, unsigned b1)
{
    asm volatile(
        "mma.sync.aligned.m16n8k16.row.col.f32.f16.f16.f32 "
        "{%0,%1,%2,%3},{%4,%5,%6,%7},{%8,%9},{%0,%1,%2,%3};"
        : "+f"(c[0]), "+f"(c[1]), "+f"(c[2]), "+f"(c[3])
        : "r"(a0), "r"(a1), "r"(a2), "r"(a3), "r"(b0), "r"(b1));
}

__device__ __forceinline__ void ldsm4(unsigned& a0, unsigned& a1,
                                      unsigned& a2, unsigned& a3, unsigned addr)
{
    asm volatile(
        "ldmatrix.sync.aligned.m8n8.x4.shared.b16 {%0,%1,%2,%3}, [%4];"
        : "=r"(a0), "=r"(a1), "=r"(a2), "=r"(a3) : "r"(addr));
}

__device__ __forceinline__ void cpa16(void* dst, const void* src)
{
    unsigned d = (unsigned)__cvta_generic_to_shared(dst);
    asm volatile("cp.async.cg.shared.global [%0], [%1], 16;" :: "r"(d), "l"(src));
}
__device__ __forceinline__ void cpa_commit()
{
    asm volatile("cp.async.commit_group;");
}
template<int N>
__device__ __forceinline__ void cpa_wait()
{
    asm volatile("cp.async.wait_group %0;" :: "n"(N));
}
__device__ __forceinline__ void pair_bar(int id)
{
    asm volatile("bar.sync %0, 64;" :: "r"(id) : "memory");
}

// ---------------- prep: weight packing (fp16), x conversion, biases ---------
__global__ void prep_kernel(
    const float* __restrict__ x,
    const float* __restrict__ wf0, const float* __restrict__ wi0,
    const float* __restrict__ wo0, const float* __restrict__ wg0,
    const float* __restrict__ bf0, const float* __restrict__ bi0,
    const float* __restrict__ bo0, const float* __restrict__ bg0,
    const float* __restrict__ wf1, const float* __restrict__ wi1,
    const float* __restrict__ wo1, const float* __restrict__ wg1,
    const float* __restrict__ bf1, const float* __restrict__ bi1,
    const float* __restrict__ bo1, const float* __restrict__ bg1)
{
    const int nW = 64 * WPW;
    const int nX = BATCH * SEQ * (DIN / 2);
    const int ntot = nW + nX + 2 * COLS;
    for (int idx = blockIdx.x * blockDim.x + threadIdx.x; idx < ntot;
         idx += gridDim.x * blockDim.x) {
        if (idx < nW) {
            int cg = idx / WPW;
            int r  = idx % WPW;
            int layer = (r < WPW_L0) ? 0 : 1;
            int rr    = layer ? (r - WPW_L0) : r;
            int kb   = rr >> 8;
            int rem  = rr & 255;
            int nb   = rem >> 6;
            int t    = rem & 63;
            int lane = t >> 1;
            int reg  = t & 1;
            int colloc = nb * 8 + (lane >> 2);
            int unit = cg * 8 + (colloc >> 2);
            int gate = colloc & 3;
            int k    = kb * 16 + (lane & 3) * 2 + reg * 8;
            const float* w;
            int K;
            if (layer == 0) {
                w = (gate == 0) ? wf0 : (gate == 1) ? wi0 : (gate == 2) ? wo0 : wg0;
                K = K0;
            } else {
                w = (gate == 0) ? wf1 : (gate == 1) ? wi1 : (gate == 2) ? wo1 : wg1;
                K = K1;
            }
            __half2 h2 = __floats2half2_rn(w[unit * K + k], w[unit * K + k + 1]);
            d_Wp[idx] = *(unsigned*)&h2;
        } else if (idx < nW + nX) {
            int i = idx - nW;
            __half2 h2 = __floats2half2_rn(x[2 * i], x[2 * i + 1]);
            d_x16[i] = *(unsigned*)&h2;
        } else {
            int col = idx - nW - nX;
            if (col < COLS) {
                int u = col >> 2, g = col & 3;
                const float* bb = (g == 0) ? bf0 : (g == 1) ? bi0 : (g == 2) ? bo0 : bg0;
                d_b0r[col] = bb[u];
            } else {
                col -= COLS;
                int u = col >> 2, g = col & 3;
                const float* bb = (g == 0) ? bf1 : (g == 1) ? bi1 : (g == 2) ? bo1 : bg1;
                d_b1r[col] = bb[u];
            }
        }
    }
}

// ---------------- xz GEMM: xz[b,t,:] = x_t @ Wx0^T + b0 (fp16 out) ----------
__global__ void __launch_bounds__(NT) xz_gemm_kernel()
{
    extern __shared__ unsigned smem_u[];
    unsigned* As = smem_u;                 // [128][68]
    unsigned* Ws = smem_u + 128 * 68;      // 8 cgs * 2048 words

    const int tid  = threadIdx.x;
    const int w    = tid >> 5, lane = tid & 31;
    const int r4   = lane >> 2, kq4 = lane & 3;
    const int row0 = blockIdx.x * 128;
    const int cg0  = blockIdx.y * 8;

    #pragma unroll
    for (int i = tid; i < 2048; i += NT) {
        int row = i >> 4, w4 = (i & 15) * 4;
        cpa16(As + row * 68 + w4, d_x16 + (size_t)(row0 + row) * 64 + w4);
    }
    #pragma unroll
    for (int i = tid; i < 4096; i += NT) {
        int cgL = i >> 9, r = (i & 511) * 4;
        cpa16(Ws + cgL * 2048 + r, d_Wp + (size_t)(cg0 + cgL) * WPW + r);
    }
    cpa_commit();
    cpa_wait<0>();
    __syncthreads();

    float acc[32][4];
    #pragma unroll
    for (int i = 0; i < 32; ++i)
        { acc[i][0] = 0.f; acc[i][1] = 0.f; acc[i][2] = 0.f; acc[i][3] = 0.f; }

    #pragma unroll
    for (int kb = 0; kb < 8; ++kb) {
        const unsigned* ab = As + (w * 16 + r4) * 68 + kb * 8 + kq4;
        unsigned a0 = ab[0];
        unsigned a1 = ab[8 * 68];
        unsigned a2 = ab[4];
        unsigned a3 = ab[8 * 68 + 4];
        #pragma unroll
        for (int j = 0; j < 32; ++j) {
            const unsigned* bp = Ws + (j >> 2) * 2048 + kb * 256 + (j & 3) * 64 + lane * 2;
            uint2 b = *(const uint2*)bp;
            mma16(acc[j], a0, a1, a2, a3, b.x, b.y);
        }
    }

    #pragma unroll
    for (int j = 0; j < 32; ++j) {
        int col = (cg0 + (j >> 2)) * 32 + (j & 3) * 8 + 2 * (lane & 3);
        float bs0 = d_b0r[col], bs1 = d_b0r[col + 1];
        int mrow = row0 + w * 16 + r4;
        __half2 p0 = __floats2half2_rn(acc[j][0] + bs0, acc[j][1] + bs1);
        __half2 p1 = __floats2half2_rn(acc[j][2] + bs0, acc[j][3] + bs1);
        d_xz[(size_t)mrow * 1024 + (col >> 1)]        = *(unsigned*)&p0;
        d_xz[(size_t)(mrow + 8) * 1024 + (col >> 1)]  = *(unsigned*)&p1;
    }
}

// ---------------- fused single-word barrier (release/acquire) -----------------
__device__ __forceinline__ void bar_arrive(int bg)
{
    __syncthreads();                       // all threads' h stores + red reads done
    if (threadIdx.x == 0) {
        unsigned prev;
        asm volatile("atom.release.gpu.global.add.u32 %0, [%1], %2;"
                     : "=r"(prev) : "l"(&g_bar[bg * 32]), "r"(1u) : "memory");
        if ((prev & 0xFFFFu) == NCTABG - 1) {
            unsigned d;
            asm volatile("atom.release.gpu.global.add.u32 %0, [%1], %2;"
                         : "=r"(d) : "l"(&g_bar[bg * 32]),
                           "r"(0x10000u - NCTABG) : "memory");
        }
    }
}
// ALL threads poll with acquire loads and resume independently (no syncthreads).
__device__ __forceinline__ void bar_wait(int bg, unsigned base, unsigned mygen)
{
    const unsigned* p = &g_bar[bg * 32];
    unsigned v;
    do {
        asm volatile("ld.acquire.gpu.global.u32 %0, [%1];"
                     : "=r"(v) : "l"(p) : "memory");
    } while ((((v >> 16) - base) & 0xFFFFu) < mygen);
}

// ---------------- persistent scan kernel --------------------------------------
// 128 CTAs = 4 batch-groups (16 batches) x 32 unit-groups (16 units = 64 cols)
// warps: 4 K-quarters (kq) x 2 col-halves (wn). L1 K-split is kq-interleaved.
__global__ void __launch_bounds__(NT, 1) scan_kernel()
{
    extern __shared__ unsigned smem_u[];
    unsigned* As0   = smem_u;                    // [16][260]  h0[t]
    unsigned* As1   = As0 + AS_WORDS;            // [16][260]  h1[t-1]
    float*    red   = (float*)(As1 + AS_WORDS);  // [2 layers][4 kq][16][68]
    float*    bias1 = red + RED_FLOATS;          // [64]

    const int tid  = threadIdx.x;
    const int cg   = blockIdx.x & 31;
    const int bg   = blockIdx.x >> 5;
    const int w    = tid >> 5, lane = tid & 31;
    const int wn   = w & 1;                      // col half (32 cols)
    const int kq   = w >> 1;                     // K quarter
    const int r4   = lane >> 2;

    const int fb = tid >> 4, fu = tid & 15;

    // All threads snapshot the round BEFORE this CTA's first arrive (replay-safe:
    // the round can't advance until every CTA has arrived, and each CTA reads
    // its base before arriving).
    unsigned bar_base = (*(volatile unsigned*)&g_bar[bg * 32]) >> 16;

    // ---- one-time: B fragments -> registers ----
    const int cgA = cg * 2 + wn;
    uint2 B0[8][4];       // L0 recurrent: blocks kq*8+j
    uint2 B1a[8][4];      // L1 h0-part:   blocks kq*8+j
    uint2 B1b[8][4];      // L1 h1-part:   blocks 32+kq*8+j
    {
        const unsigned* w0 = d_Wp + (size_t)cgA * WPW + 2048
                           + (kq * 8) * 256 + lane * 2;
        #pragma unroll
        for (int j = 0; j < 8; ++j)
            #pragma unroll
            for (int n = 0; n < 4; ++n)
                B0[j][n] = *(const uint2*)(w0 + j * 256 + n * 64);
        const unsigned* w1 = d_Wp + (size_t)cgA * WPW + WPW_L0
                           + (kq * 8) * 256 + lane * 2;
        #pragma unroll
        for (int j = 0; j < 8; ++j)
            #pragma unroll
            for (int n = 0; n < 4; ++n)
                B1a[j][n] = *(const uint2*)(w1 + j * 256 + n * 64);
        const unsigned* w1b = w1 + 32 * 256;
        #pragma unroll
        for (int j = 0; j < 8; ++j)
            #pragma unroll
            for (int n = 0; n < 4; ++n)
                B1b[j][n] = *(const uint2*)(w1b + j * 256 + n * 64);
    }
    if (tid < 64) bias1[tid] = d_b1r[cg * 64 + tid];

    // zero this bg's t=-1 hidden rows
    {
        int idx = cg * NT + tid;
        if (idx < 4096) d_h0[1][bg * 4096 + idx] = 0u;
        else            d_h1[1][bg * 4096 + (idx - 4096)] = 0u;
    }
    float c0 = 0.0f, c1 = 0.0f;
    bar_arrive(bg);
    unsigned mygen = 1;

    // ldmatrix per-lane addresses (blocks kq*8+j live in quarter kq)
    unsigned smem_base = (unsigned)__cvta_generic_to_shared(smem_u);
    const int lrow = lane & 15;
    const int lcol = (lane >> 4) * 4;
    const unsigned la0  = smem_base + (unsigned)(lrow * AS_STRIDE + lcol) * 4;
    const unsigned la1h = la0 + AS_WORDS * 4;    // same pattern in As1

    float* red0 = red + kq * RED_PER;
    float* red1 = red + 4 * RED_PER + kq * RED_PER;
    const int barid = 1 + kq;

    for (int k = 0; k <= SEQ; ++k) {
        const int doL0 = (k < SEQ);
        const int doL1 = (k >= 1);

        // xz prefetch (no dependency on h) — overlap with barrier propagation
        uint2 zraw;
        if (doL0)
            zraw = *(const uint2*)(d_xz +
                    (size_t)((bg * 16 + fb) * SEQ + k) * 1024 + cg * 32 + fu * 2);

        bar_wait(bg, bar_base, mygen); ++mygen;

        // ===== self-staging: warp (kq,wn) stages its own 8 rows x quarter kq ===
        {
            const unsigned* __restrict__ h0prev = d_h0[(k + 1) & 1];
            #pragma unroll
            for (int it = 0; it < 4; ++it) {
                int idx = it * 32 + lane;            // 0..127
                int row = wn * 8 + (idx >> 4);
                int wd  = kq * 64 + (idx & 15) * 4;
                cpa16(As0 + row * AS_STRIDE + wd,
                      h0prev + (bg * 16 + row) * 256 + wd);
            }
        }
        cpa_commit();
        if (doL1) {
            const unsigned* __restrict__ h1prev = d_h1[k & 1];
            #pragma unroll
            for (int it = 0; it < 4; ++it) {
                int idx = it * 32 + lane;
                int row = wn * 8 + (idx >> 4);
                int wd  = kq * 64 + (idx & 15) * 4;
                cpa16(As1 + row * AS_STRIDE + wd,
                      h1prev + (bg * 16 + row) * 256 + wd);
            }
        }
        cpa_commit();                    // always commit (possibly empty group)

        cpa_wait<1>();                   // own As0 quarter done
        pair_bar(barid);                 // partner's half of the quarter done

        const int cbb = 2 * (lane & 3);

        // ===== fused pass over As0: L0 MMA + L1 h0-part MMA share fragments ===
        float acc0[4][4] = {};
        float acc1[4][4] = {};
        #pragma unroll
        for (int j = 0; j < 8; ++j) {
            unsigned a0, a1, a2, a3;
            ldsm4(a0, a1, a2, a3, la0 + (unsigned)(kq * 8 + j) * 32);
            if (doL0) {
                #pragma unroll
                for (int n = 0; n < 4; ++n)
                    mma16(acc0[n], a0, a1, a2, a3, B0[j][n].x, B0[j][n].y);
            }
            if (doL1) {
                #pragma unroll
                for (int n = 0; n < 4; ++n)
                    mma16(acc1[n], a0, a1, a2, a3, B1a[j][n].x, B1a[j][n].y);
            }
        }
        if (doL0) {
            #pragma unroll
            for (int n = 0; n < 4; ++n) {
                int cb = wn * 32 + n * 8 + cbb;
                *(float2*)&red0[r4 * 68 + cb]       = make_float2(acc0[n][0], acc0[n][1]);
                *(float2*)&red0[(r4 + 8) * 68 + cb] = make_float2(acc0[n][2], acc0[n][3]);
            }
        }

        cpa_wait<0>();                   // own As1 quarter done
        pair_bar(barid);

        // ===== L1 h1-part MMAs =====
        if (doL1) {
            #pragma unroll
            for (int j = 0; j < 8; ++j) {
                unsigned a0, a1, a2, a3;
                ldsm4(a0, a1, a2, a3, la1h + (unsigned)(kq * 8 + j) * 32);
                #pragma unroll
                for (int n = 0; n < 4; ++n)
                    mma16(acc1[n], a0, a1, a2, a3, B1b[j][n].x, B1b[j][n].y);
            }
            #pragma unroll
            for (int n = 0; n < 4; ++n) {
                int cb = wn * 32 + n * 8 + cbb;
                *(float2*)&red1[r4 * 68 + cb]       = make_float2(acc1[n][0], acc1[n][1]);
                *(float2*)&red1[(r4 + 8) * 68 + cb] = make_float2(acc1[n][2], acc1[n][3]);
            }
        }

        __syncthreads();

        // ===== pointwise finishes =====
        const int o = fb * 68 + fu * 4;
        if (doL0) {
            float4 q0 = *(const float4*)&red[0 * RED_PER + o];
            float4 q1 = *(const float4*)&red[1 * RED_PER + o];
            float4 q2 = *(const float4*)&red[2 * RED_PER + o];
            float4 q3 = *(const float4*)&red[3 * RED_PER + o];
            __half2 zl = *(__half2*)&zraw.x;
            __half2 zh = *(__half2*)&zraw.y;
            float zf = q0.x + q1.x + q2.x + q3.x + __low2float(zl);
            float zi = q0.y + q1.y + q2.y + q3.y + __high2float(zl);
            float zo = q0.z + q1.z + q2.z + q3.z + __low2float(zh);
            float zg = q0.w + q1.w + q2.w + q3.w + __high2float(zh);
            float f  = sigf(zf);
            float ii = sigf(zi);
            float oo = sigf(zo);
            float g  = tanha(zg);
            float c  = f * c0 + ii * g;
            c0 = c;
            float hv = oo * tanha(c);
            ((__half*)d_h0[k & 1])[(bg * 16 + fb) * HID + cg * 16 + fu] =
                __float2half_rn(hv);
        }
        if (doL1) {
            float4 q0 = *(const float4*)&red[4 * RED_PER + o];
            float4 q1 = *(const float4*)&red[5 * RED_PER + o];
            float4 q2 = *(const float4*)&red[6 * RED_PER + o];
            float4 q3 = *(const float4*)&red[7 * RED_PER + o];
            float zf = q0.x + q1.x + q2.x + q3.x + bias1[fu * 4 + 0];
            float zi = q0.y + q1.y + q2.y + q3.y + bias1[fu * 4 + 1];
            float zo = q0.z + q1.z + q2.z + q3.z + bias1[fu * 4 + 2];
            float zg = q0.w + q1.w + q2.w + q3.w + bias1[fu * 4 + 3];
            float f  = sigf(zf);
            float ii = sigf(zi);
            float oo = sigf(zo);
            float g  = tanha(zg);
            float c  = f * c1 + ii * g;
            c1 = c;
            float hv = oo * tanha(c);
            ((__half*)d_h1[(k - 1) & 1])[(bg * 16 + fb) * HID + cg * 16 + fu] =
                __float2half_rn(hv);
        }

        bar_arrive(bg);
    }
}

// ---------------- fc1: smem-staged weight tile, coalesced --------------------
__global__ void __launch_bounds__(256) fc1_kernel(
    const float* __restrict__ fc1w, const float* __restrict__ fc1b)
{
    extern __shared__ unsigned fsm[];
    float*    wsm = (float*)fsm;            // [32][516] padded
    unsigned* hsm = fsm + 32 * 516;         // [16][256] h as half2 words

    const int tid  = threadIdx.x;
    const int bgrp = blockIdx.y;
    const int jbase = blockIdx.x * 32;

    #pragma unroll
    for (int i = tid; i < 4096; i += 256)
        hsm[i] = d_h1[1][bgrp * 4096 + i];
    #pragma unroll
    for (int i = tid; i < 32 * 128; i += 256) {
        int row = i >> 7, k4 = i & 127;
        *(float4*)&wsm[row * 516 + k4 * 4] =
            *(const float4*)&fc1w[(size_t)(jbase + row) * HID + k4 * 4];
    }
    __syncthreads();

    const int j   = tid & 31;
    const int wid = tid >> 5;
    float acc0 = 0.f, acc1 = 0.f;
    const float* wr = wsm + j * 516;
    const unsigned* h0p = hsm + (wid * 2) * 256;
    const unsigned* h1p = hsm + (wid * 2 + 1) * 256;
    #pragma unroll 4
    for (int k4 = 0; k4 < 128; ++k4) {
        float4 wv = *(const float4*)&wr[k4 * 4];
        uint2 hpa = *(const uint2*)(h0p + k4 * 2);
        uint2 hpb = *(const uint2*)(h1p + k4 * 2);
        float2 a0 = __half22float2(*(__half2*)&hpa.x);
        float2 a1 = __half22float2(*(__half2*)&hpa.y);
        float2 b0 = __half22float2(*(__half2*)&hpb.x);
        float2 b1 = __half22float2(*(__half2*)&hpb.y);
        acc0 = fmaf(wv.x, a0.x, acc0); acc0 = fmaf(wv.y, a0.y, acc0);
        acc0 = fmaf(wv.z, a1.x, acc0); acc0 = fmaf(wv.w, a1.y, acc0);
        acc1 = fmaf(wv.x, b0.x, acc1); acc1 = fmaf(wv.y, b0.y, acc1);
        acc1 = fmaf(wv.z, b1.x, acc1); acc1 = fmaf(wv.w, b1.y, acc1);
    }
    float bj = fc1b[jbase + j];
    d_y1[(size_t)(bgrp * 16 + wid * 2)     * HID + jbase + j] = acc0 + bj;
    d_y1[(size_t)(bgrp * 16 + wid * 2 + 1) * HID + jbase + j] = acc1 + bj;
}

// ---------------- fc2 + relu: out[64,24] -----------------------------------------
__global__ void __launch_bounds__(192) fc2_kernel(
    const float* __restrict__ fc2w, const float* __restrict__ fc2b,
    float* __restrict__ out)
{
    __shared__ float ys[HID];
    const int b = blockIdx.x;
    const int tid = threadIdx.x;
    for (int i = tid; i < HID; i += 192) ys[i] = d_y1[(size_t)b * HID + i];
    __syncthreads();
    int j = tid >> 3, part = tid & 7;
    const float4* wr = (const float4*)(fc2w + (size_t)j * HID + part * 64);
    const float4* yv = (const float4*)(ys + part * 64);
    float a = 0.0f;
    #pragma unroll
    for (int kk = 0; kk < 16; ++kk) {
        float4 wv = wr[kk];
        float4 xv = yv[kk];
        a = fmaf(wv.x, xv.x, a);
        a = fmaf(wv.y, xv.y, a);
        a = fmaf(wv.z, xv.z, a);
        a = fmaf(wv.w, xv.w, a);
    }
    a += __shfl_down_sync(0xffffffffu, a, 4, 8);
    a += __shfl_down_sync(0xffffffffu, a, 2, 8);
    a += __shfl_down_sync(0xffffffffu, a, 1, 8);
    if (part == 0)
        out[b * OUTN + j] = fmaxf(a + fc2b[j], 0.0f);
}

// ---------------- launch ---------------------------------------------------------
extern "C" void kernel_launch(void* const* d_in, const int* in_sizes, int n_in,
                              void* d_out, int out_size)
{
    const float* x    = (const float*)d_in[0];
    const float* wf0  = (const float*)d_in[1];
    const float* bf0  = (const float*)d_in[2];
    const float* wi0  = (const float*)d_in[3];
    const float* bi0  = (const float*)d_in[4];
    const float* wo0  = (const float*)d_in[5];
    const float* bo0  = (const float*)d_in[6];
    const float* wg0  = (const float*)d_in[7];
    const float* bg0  = (const float*)d_in[8];
    const float* wf1  = (const float*)d_in[9];
    const float* bf1  = (const float*)d_in[10];
    const float* wi1  = (const float*)d_in[11];
    const float* bi1  = (const float*)d_in[12];
    const float* wo1  = (const float*)d_in[13];
    const float* bo1  = (const float*)d_in[14];
    const float* wg1  = (const float*)d_in[15];
    const float* bg1  = (const float*)d_in[16];
    const float* fc1w = (const float*)d_in[17];
    const float* fc1b = (const float*)d_in[18];
    const float* fc2w = (const float*)d_in[19];
    const float* fc2b = (const float*)d_in[20];
    float* out = (float*)d_out;

    cudaFuncSetAttribute(scan_kernel,
                         cudaFuncAttributeMaxDynamicSharedMemorySize, SMEM_BYTES);
    cudaFuncSetAttribute(xz_gemm_kernel,
                         cudaFuncAttributeMaxDynamicSharedMemorySize, XG_SMEM_BYTES);
    cudaFuncSetAttribute(fc1_kernel,
                         cudaFuncAttributeMaxDynamicSharedMemorySize, FC1_SMEM_BYTES);

    prep_kernel<<<4096, 256>>>(x, wf0, wi0, wo0, wg0, bf0, bi0, bo0, bg0,
                               wf1, wi1, wo1, wg1, bf1, bi1, bo1, bg1);
    dim3 xzgrid(256, 8);
    xz_gemm_kernel<<<xzgrid, NT, XG_SMEM_BYTES>>>();
    scan_kernel<<<NCTA, NT, SMEM_BYTES>>>();
    dim3 fc1grid(16, 4);
    fc1_kernel<<<fc1grid, 256, FC1_SMEM_BYTES>>>(fc1w, fc1b);
    fc2_kernel<<<BATCH, 192>>>(fc2w, fc2b, out);
}